// round 11
// baseline (speedup 1.0000x reference)
#include <cuda_runtime.h>
#include <math.h>
#include <stdint.h>

#define T_    2048
#define DIM_  2048
#define QL_   1536
#define H_    16
#define DH_   256
#define NOPE_ 192
#define HI_   32
#define DI_   128
#define INOPE_ 64
#define SC_   512
#define TOPK_ 256
#define II_   8192
#define G_    4
#define OLORA_ 512
#define FG_   1024
#define EPSF  1e-6f
#define NEGF  (-1e30f)
#define SCALE_   0.0625f
#define ISCALE_  0.08838834764831845f
#define LOG_THETA 11.98292909421596506

// ---------------- scratch ----------------
__device__ float g_x   [T_ * DIM_];
__device__ float g_qr  [T_ * QL_];
__device__ float g_q   [T_ * H_ * DH_];
__device__ float g_qi  [T_ * HI_ * DI_];
__device__ float g_wkv2[2 * DIM_ * 2 * DH_];   // packed {comp_wkv, comp_wgate}
__device__ float g_wik2[2 * DIM_ * 2 * DI_];   // packed {icomp_wkv, icomp_wgate}
__device__ float g_kv2 [2 * T_ * 2 * DH_];     // raw z-batched outputs
__device__ float g_ik2 [2 * T_ * 2 * DI_];
__device__ float g_kvF [T_ * 2 * DH_];
__device__ float g_kvc [SC_ * DH_];
__device__ float g_ikF [T_ * 2 * DI_];
__device__ float g_ki  [SC_ * DI_];
__device__ float g_kiT [DI_ * SC_];
__device__ float g_woaT[G_ * FG_ * OLORA_];
__device__ float g_iw  [T_ * HI_];
__device__ float g_isc [T_ * SC_];
__device__ int   g_selidx[T_ * TOPK_];
__device__ int   g_selcnt[T_];
__device__ float g_o   [T_ * H_ * DH_];
__device__ float g_oa  [T_ * G_ * OLORA_];
__device__ float g_h   [T_ * DIM_];
__device__ float g_x2  [T_ * DIM_];
__device__ float g_act [(size_t)T_ * II_];
__device__ float g_ropeC[T_ * 32];
__device__ float g_ropeS[T_ * 32];

// ---------------- reductions ----------------
__device__ __forceinline__ float blockReduceSum(float v) {
    __shared__ float sh[32];
    int lane = threadIdx.x & 31, wid = threadIdx.x >> 5;
    #pragma unroll
    for (int o = 16; o > 0; o >>= 1) v += __shfl_xor_sync(0xffffffffu, v, o);
    if (lane == 0) sh[wid] = v;
    __syncthreads();
    int nw = (blockDim.x + 31) >> 5;
    if (wid == 0) {
        float r = (lane < nw) ? sh[lane] : 0.0f;
        #pragma unroll
        for (int o = 16; o > 0; o >>= 1) r += __shfl_xor_sync(0xffffffffu, r, o);
        if (lane == 0) sh[0] = r;
    }
    __syncthreads();
    float res = sh[0];
    __syncthreads();
    return res;
}

// ---------------- tf32 / cp.async helpers ----------------
__device__ __forceinline__ uint32_t f2tf32(float x) {
    uint32_t r;
    asm("cvt.rna.tf32.f32 %0, %1;" : "=r"(r) : "f"(x));
    return r;
}

__device__ __forceinline__ void mma_tf32(float* d, const uint32_t* a, const uint32_t* b) {
    asm volatile(
        "mma.sync.aligned.m16n8k8.row.col.f32.tf32.tf32.f32 "
        "{%0,%1,%2,%3}, {%4,%5,%6,%7}, {%8,%9}, {%0,%1,%2,%3};"
        : "+f"(d[0]), "+f"(d[1]), "+f"(d[2]), "+f"(d[3])
        : "r"(a[0]), "r"(a[1]), "r"(a[2]), "r"(a[3]), "r"(b[0]), "r"(b[1]));
}

__device__ __forceinline__ void cp16(float* smem_dst, const float* gsrc, bool pred) {
    uint32_t s = (uint32_t)__cvta_generic_to_shared(smem_dst);
    int sz = pred ? 16 : 0;
    asm volatile("cp.async.cg.shared.global [%0], [%1], 16, %2;\n"
                 :: "r"(s), "l"(gsrc), "r"(sz));
}
#define CP_COMMIT() asm volatile("cp.async.commit_group;" ::: "memory")
#define CP_WAIT1()  asm volatile("cp.async.wait_group 1;" ::: "memory")
#define CP_WAIT0()  asm volatile("cp.async.wait_group 0;" ::: "memory")

// ---------------- epilogue modes ----------------
#define EP_NONE  0
#define EP_ADD   1
#define EP_SILU  3
#define EP_RFUSE 4

// ---------------- tensor-core TF32 GEMM, 128x128x32, 3-stage cp.async +
// register double-buffered fragments ----------------
#define BM 128
#define BN 128
#define BK 32
#define AS_S 36
#define BS_S 136
#define A_TILE (BM * AS_S)
#define B_TILE (BK * BS_S)
#define STAGE_F (A_TILE + B_TILE)
#define SMEM_PIPE_BYTES (STAGE_F * 3 * 4)   // 107520

template<int EP>
__global__ void __launch_bounds__(256, 2) tgemm_kernel(
    int M, int N, int K,
    const float* __restrict__ A, int lda, int aZ,
    const float* __restrict__ B, int ldb, int bZ,
    const float* __restrict__ Cadd,
    float* __restrict__ C, int ldc, int cZ)
{
    extern __shared__ float smem[];
    const int bm = blockIdx.y * BM;
    const int bn = blockIdx.x * BN;
    A += (size_t)blockIdx.z * aZ;
    B += (size_t)blockIdx.z * bZ;
    C += (size_t)blockIdx.z * cZ;
    const int tid = threadIdx.x;
    const int lane = tid & 31;
    const int wid = tid >> 5;
    const int wm = wid & 3;
    const int wn = wid >> 2;
    const int gid = lane >> 2;
    const int tig = lane & 3;

    float acc[2][8][4];
    #pragma unroll
    for (int mi = 0; mi < 2; mi++)
        #pragma unroll
        for (int ni = 0; ni < 8; ni++)
            #pragma unroll
            for (int r = 0; r < 4; r++) acc[mi][ni][r] = 0.0f;

    const int nIter = K / BK;

    auto issue = [&](int st, int k0) {
        float* sA = smem + st * STAGE_F;
        float* sB = sA + A_TILE;
        #pragma unroll
        for (int i = 0; i < 4; i++) {
            int f = tid + i * 256;
            int r = f >> 3, q = f & 7;
            int gr = bm + r;
            cp16(&sA[r * AS_S + 4 * q], A + (size_t)gr * lda + k0 + 4 * q, gr < M);
        }
        #pragma unroll
        for (int i = 0; i < 4; i++) {
            int f = tid + i * 256;
            int k = f >> 5, q = f & 31;
            int gc = bn + 4 * q;
            cp16(&sB[k * BS_S + 4 * q], B + (size_t)(k0 + k) * ldb + gc, gc < N);
        }
    };

    auto load_frags = [&](const float* sA, const float* sB, int kb,
                          uint32_t af[2][4], uint32_t bf[8][2]) {
        #pragma unroll
        for (int mi = 0; mi < 2; mi++) {
            int r = wm * 32 + mi * 16 + gid;
            af[mi][0] = f2tf32(sA[r * AS_S + kb + tig]);
            af[mi][1] = f2tf32(sA[(r + 8) * AS_S + kb + tig]);
            af[mi][2] = f2tf32(sA[r * AS_S + kb + tig + 4]);
            af[mi][3] = f2tf32(sA[(r + 8) * AS_S + kb + tig + 4]);
        }
        #pragma unroll
        for (int ni = 0; ni < 8; ni++) {
            int c = wn * 64 + ni * 8 + gid;
            bf[ni][0] = f2tf32(sB[(kb + tig) * BS_S + c]);
            bf[ni][1] = f2tf32(sB[(kb + tig + 4) * BS_S + c]);
        }
    };

    auto frag_compute = [&](int st) {
        const float* sA = smem + st * STAGE_F;
        const float* sB = sA + A_TILE;
        uint32_t af[2][2][4];
        uint32_t bf[2][8][2];
        load_frags(sA, sB, 0, af[0], bf[0]);
        #pragma unroll
        for (int kk = 0; kk < 4; kk++) {
            if (kk < 3)
                load_frags(sA, sB, (kk + 1) * 8, af[(kk + 1) & 1], bf[(kk + 1) & 1]);
            #pragma unroll
            for (int mi = 0; mi < 2; mi++)
                #pragma unroll
                for (int ni = 0; ni < 8; ni++)
                    mma_tf32(acc[mi][ni], af[kk & 1][mi], bf[kk & 1][ni]);
        }
    };

    issue(0, 0);
    CP_COMMIT();
    if (nIter > 1) { issue(1, BK); CP_COMMIT(); }

    int st = 0;
    for (int it = 0; it < nIter; ++it) {
        if (it + 1 < nIter) CP_WAIT1(); else CP_WAIT0();
        __syncthreads();
        if (it + 2 < nIter) {
            int st2 = st + 2; if (st2 >= 3) st2 -= 3;
            issue(st2, (it + 2) * BK);
            CP_COMMIT();
        }
        frag_compute(st);
        if (++st == 3) st = 0;
    }

    // ---------------- epilogues ----------------
    if (EP == EP_RFUSE) {
        int t = bm / HI_ + wm;
        float wA = Cadd[t * HI_ + gid];
        float wB = Cadd[t * HI_ + gid + 8];
        float wC = Cadd[t * HI_ + gid + 16];
        float wD = Cadd[t * HI_ + gid + 24];
        #pragma unroll
        for (int ni = 0; ni < 8; ni++) {
            float p0 = wA * fmaxf(acc[0][ni][0], 0.f) + wB * fmaxf(acc[0][ni][2], 0.f)
                     + wC * fmaxf(acc[1][ni][0], 0.f) + wD * fmaxf(acc[1][ni][2], 0.f);
            float p1 = wA * fmaxf(acc[0][ni][1], 0.f) + wB * fmaxf(acc[0][ni][3], 0.f)
                     + wC * fmaxf(acc[1][ni][1], 0.f) + wD * fmaxf(acc[1][ni][3], 0.f);
            #pragma unroll
            for (int off = 4; off < 32; off <<= 1) {
                p0 += __shfl_xor_sync(0xffffffffu, p0, off);
                p1 += __shfl_xor_sync(0xffffffffu, p1, off);
            }
            if (gid == 0) {
                int c = bn + wn * 64 + ni * 8 + tig * 2;
                C[(size_t)t * ldc + c]     = p0 * ISCALE_;
                C[(size_t)t * ldc + c + 1] = p1 * ISCALE_;
            }
        }
        return;
    }

    #pragma unroll
    for (int mi = 0; mi < 2; mi++) {
        int r0 = bm + wm * 32 + mi * 16 + gid;
        int r1 = r0 + 8;
        #pragma unroll
        for (int ni = 0; ni < 8; ni++) {
            int c = bn + wn * 64 + ni * 8 + tig * 2;
            float* ap = acc[mi][ni];
            if (c < N) {
                #pragma unroll
                for (int half = 0; half < 2; half++) {
                    int r = half ? r1 : r0;
                    if (r >= M) continue;
                    float a0 = ap[half * 2], a1 = ap[half * 2 + 1];
                    float v0, v1;
                    if (EP == EP_NONE) {
                        v0 = a0; v1 = a1;
                    } else if (EP == EP_ADD) {
                        float2 cc = *(const float2*)(Cadd + (size_t)r * ldc + c);
                        v0 = a0 + cc.x; v1 = a1 + cc.y;
                    } else { // EP_SILU
                        float2 gg = *(const float2*)(Cadd + (size_t)r * ldc + c);
                        v0 = gg.x / (1.0f + expf(-gg.x)) * a0;
                        v1 = gg.y / (1.0f + expf(-gg.y)) * a1;
                    }
                    *(float2*)(C + (size_t)r * ldc + c) = make_float2(v0, v1);
                }
            }
        }
    }
}

// ---------------- pack two weight matrices contiguously ----------------
__global__ void pack2_kernel(const float* __restrict__ a, const float* __restrict__ b,
                             float* __restrict__ out, int n)
{
    int i = blockIdx.x * blockDim.x + threadIdx.x;
    if (i < n) { out[i] = a[i]; out[n + i] = b[i]; }
}

// ---------------- apply sigmoid-gate + ape on z-batched GEMM output ----------------
__global__ void gate2_kernel(const float* __restrict__ raw, const float* __restrict__ ape,
                             float* __restrict__ outF, int W)
{
    int i = blockIdx.x * blockDim.x + threadIdx.x;
    if (i >= T_ * W) return;
    int t = i / W, e = i - t * W;
    float kv = raw[i];
    float gt = raw[(size_t)T_ * W + i];
    outF[i] = kv / (1.0f + expf(-gt)) + ape[(t & 3) * W + e];
}

// ---------------- tiled transpose ----------------
__global__ void transpose_kernel(const float* __restrict__ in, float* __restrict__ out,
                                 int R, int C)
{
    __shared__ float tile[32][33];
    const float* inz = in + (size_t)blockIdx.z * R * C;
    float* outz = out + (size_t)blockIdx.z * R * C;
    int bx = blockIdx.x * 32, by = blockIdx.y * 32;
    int x = bx + threadIdx.x;
    #pragma unroll
    for (int i = 0; i < 4; i++) {
        int y = by + threadIdx.y + 8 * i;
        if (y < R && x < C) tile[threadIdx.y + 8 * i][threadIdx.x] = inz[(size_t)y * C + x];
    }
    __syncthreads();
    int x2 = by + threadIdx.x;
    #pragma unroll
    for (int i = 0; i < 4; i++) {
        int y2 = bx + threadIdx.y + 8 * i;
        if (y2 < C && x2 < R) outz[(size_t)y2 * R + x2] = tile[threadIdx.x][threadIdx.y + 8 * i];
    }
}

// ---------------- rmsnorm ----------------
__global__ void rms_kernel(const float* __restrict__ in, const float* __restrict__ w,
                           float* __restrict__ out, int D)
{
    int t = blockIdx.x;
    const float* row = in + (size_t)t * D;
    float s = 0.0f;
    for (int d = threadIdx.x; d < D; d += blockDim.x) { float v = row[d]; s += v * v; }
    s = blockReduceSum(s);
    float inv = rsqrtf(s / (float)D + EPSF);
    for (int d = threadIdx.x; d < D; d += blockDim.x)
        out[(size_t)t * D + d] = row[d] * inv * w[d];
}

// ---------------- compress ----------------
__global__ void compress_kernel(const float* __restrict__ kvf, const float* __restrict__ w,
                                float* __restrict__ out, int d)
{
    int b = blockIdx.x;
    int e = threadIdx.x;
    int W = 2 * d;
    float m = 0.0f;
    if (b > 0) {
        #pragma unroll
        for (int r = 0; r < 4; r++) m += kvf[(size_t)((b - 1) * 4 + r) * W + e];
    }
    #pragma unroll
    for (int r = 0; r < 4; r++) m += kvf[(size_t)(b * 4 + r) * W + d + e];
    m *= 0.125f;
    float ssq = blockReduceSum(m * m);
    float inv = rsqrtf(ssq / (float)d + EPSF);
    out[(size_t)b * d + e] = m * inv * w[e];
}

// ---------------- RoPE table + apply ----------------
__global__ void rope_table_kernel(float* __restrict__ tc, float* __restrict__ ts)
{
    int i = blockIdx.x * blockDim.x + threadIdx.x;
    if (i >= T_ * 32) return;
    int pos = i >> 5, f = i & 31;
    double freq = exp(-((double)(2 * f) / 64.0) * LOG_THETA);
    double ang = (double)pos * freq;
    tc[i] = (float)cos(ang);
    ts[i] = (float)sin(ang);
}

__global__ void rope_apply_kernel(float* __restrict__ x, const int* __restrict__ positions,
                                  const float* __restrict__ tc, const float* __restrict__ ts,
                                  int Hh, int Dd, int ropeOff, int compPos, int nRows)
{
    int row = blockIdx.x * 8 + (threadIdx.x >> 5);
    if (row >= nRows) return;
    int lane = threadIdx.x & 31;
    int t = row / Hh;
    int pos = compPos ? (4 * (t + 1) - 1) : positions[t];
    float c = tc[pos * 32 + lane], s = ts[pos * 32 + lane];
    float* p = x + (size_t)row * Dd + ropeOff;
    float x0 = p[2 * lane], x1 = p[2 * lane + 1];
    p[2 * lane]     = x0 * c - x1 * s;
    p[2 * lane + 1] = x0 * s + x1 * c;
}

// ---------------- exact top-256 ----------------
__global__ void topk_kernel(const float* __restrict__ isc, int* __restrict__ selidx,
                            int* __restrict__ selcnt)
{
    int t = blockIdx.x;
    __shared__ float sv[SC_];
    __shared__ int   si[SC_];
    int tid = threadIdx.x;
    int visCount = (t >= 3) ? ((t - 3) / 4 + 1) : 0;
    for (int i = tid; i < SC_; i += 256) {
        sv[i] = (i < visCount) ? isc[t * SC_ + i] : NEGF;
        si[i] = i;
    }
    __syncthreads();
    for (int k = 2; k <= SC_; k <<= 1) {
        for (int j = k >> 1; j > 0; j >>= 1) {
            for (int base = tid; base < SC_; base += 256) {
                int partner = base ^ j;
                if (partner > base) {
                    bool up = ((base & k) == 0);
                    float va = sv[base], vb = sv[partner];
                    int ia = si[base], ib = si[partner];
                    bool aFirst = (va > vb) || (va == vb && ia < ib);
                    if (up ? !aFirst : aFirst) {
                        sv[base] = vb; sv[partner] = va;
                        si[base] = ib; si[partner] = ia;
                    }
                }
            }
            __syncthreads();
        }
    }
    int cnt = min(visCount, TOPK_);
    if (tid == 0) selcnt[t] = cnt;
    for (int r = tid; r < cnt; r += 256) selidx[t * TOPK_ + r] = si[r];
}

// ---------------- head-shared flash attention ----------------
__global__ void __launch_bounds__(512) attn2_kernel(
    const float* __restrict__ q, const float* __restrict__ kvc,
    const int* __restrict__ selidx, const int* __restrict__ selcnt,
    const float* __restrict__ sink, float* __restrict__ o)
{
    __shared__ float kt[32][DH_];
    __shared__ int   ss[TOPK_];
    int t = blockIdx.x;
    int tid = threadIdx.x, lane = tid & 31, w = tid >> 5;
    int cnt = selcnt[t];
    for (int i = tid; i < cnt; i += 512) ss[i] = selidx[t * TOPK_ + i];
    __syncthreads();

    float q8[8];
    const float* qp = q + ((size_t)t * H_ + w) * DH_;
    #pragma unroll
    for (int i = 0; i < 8; i++) q8[i] = qp[lane + 32 * i];

    float m = NEGF, se = 0.0f;
    float acc[8] = {};

    for (int j0 = 0; j0 < cnt; j0 += 32) {
        int rem = min(32, cnt - j0);
        __syncthreads();
        for (int f = tid; f < 32 * 64; f += 512) {
            int r = f >> 6, c4 = f & 63;
            float4 v = make_float4(0.f, 0.f, 0.f, 0.f);
            if (r < rem) v = *(const float4*)(kvc + (size_t)ss[j0 + r] * DH_ + 4 * c4);
            *(float4*)&kt[r][4 * c4] = v;
        }
        __syncthreads();
        for (int j = 0; j < rem; j++) {
            float dot = 0.0f;
            #pragma unroll
            for (int i = 0; i < 8; i++) dot += q8[i] * kt[j][lane + 32 * i];
            #pragma unroll
            for (int off = 16; off > 0; off >>= 1)
                dot += __shfl_xor_sync(0xffffffffu, dot, off);
            float lg = dot * SCALE_;
            float mn = fmaxf(m, lg);
            float sc = expf(m - mn);
            float p  = expf(lg - mn);
            se = se * sc + p;
            #pragma unroll
            for (int i = 0; i < 8; i++)
                acc[i] = acc[i] * sc + p * kt[j][lane + 32 * i];
            m = mn;
        }
    }

    float snk = sink[w];
    float mn = fmaxf(m, snk);
    float sc = expf(m - mn);
    se = se * sc + expf(snk - mn);
    float inv = 1.0f / se;
    float* op = o + ((size_t)t * H_ + w) * DH_;
    #pragma unroll
    for (int i = 0; i < 8; i++) op[lane + 32 * i] = acc[i] * sc * inv;
}

// ---------------- host ----------------
static inline dim3 ggrid(int M, int N) { return dim3((N + BN - 1) / BN, (M + BM - 1) / BM); }

extern "C" void kernel_launch(void* const* d_in, const int* in_sizes, int n_in,
                              void* d_out, int out_size)
{
    const float* hidden      = (const float*)d_in[0];
    const int*   positions   = (const int*)  d_in[1];
    const float* ln1_w       = (const float*)d_in[2];
    const float* ln2_w       = (const float*)d_in[3];
    const float* wq_a        = (const float*)d_in[4];
    const float* q_norm_w    = (const float*)d_in[5];
    const float* wq_b        = (const float*)d_in[6];
    const float* comp_wkv    = (const float*)d_in[7];
    const float* comp_wgate  = (const float*)d_in[8];
    const float* comp_ape    = (const float*)d_in[9];
    const float* comp_norm_w = (const float*)d_in[10];
    const float* idx_wq_b    = (const float*)d_in[11];
    const float* idx_wproj   = (const float*)d_in[12];
    const float* icomp_wkv   = (const float*)d_in[13];
    const float* icomp_wgate = (const float*)d_in[14];
    const float* icomp_ape   = (const float*)d_in[15];
    const float* icomp_norm_w= (const float*)d_in[16];
    const float* attn_sink   = (const float*)d_in[17];
    const float* wo_a        = (const float*)d_in[18];
    const float* wo_b        = (const float*)d_in[19];
    const float* gate_up_w   = (const float*)d_in[20];
    const float* down_w      = (const float*)d_in[21];
    float* out = (float*)d_out;

    float *px,*pqr,*pq,*pqi,*pwkv2,*pwik2,*pkv2,*pik2,*pkvF,*pkvc,*pikF,*pki,*pkiT,*pwoaT,*piw,*pisc;
    float *po,*poa,*ph,*px2,*pact,*pRC,*pRS;
    int *pselidx,*pselcnt;
    cudaGetSymbolAddress((void**)&px, g_x);       cudaGetSymbolAddress((void**)&pqr, g_qr);
    cudaGetSymbolAddress((void**)&pq, g_q);       cudaGetSymbolAddress((void**)&pqi, g_qi);
    cudaGetSymbolAddress((void**)&pwkv2, g_wkv2); cudaGetSymbolAddress((void**)&pwik2, g_wik2);
    cudaGetSymbolAddress((void**)&pkv2, g_kv2);   cudaGetSymbolAddress((void**)&pik2, g_ik2);
    cudaGetSymbolAddress((void**)&pkvF, g_kvF);   cudaGetSymbolAddress((void**)&pkvc, g_kvc);
    cudaGetSymbolAddress((void**)&pikF, g_ikF);   cudaGetSymbolAddress((void**)&pki, g_ki);
    cudaGetSymbolAddress((void**)&pkiT, g_kiT);   cudaGetSymbolAddress((void**)&pwoaT, g_woaT);
    cudaGetSymbolAddress((void**)&piw, g_iw);     cudaGetSymbolAddress((void**)&pisc, g_isc);
    cudaGetSymbolAddress((void**)&pselidx, g_selidx); cudaGetSymbolAddress((void**)&pselcnt, g_selcnt);
    cudaGetSymbolAddress((void**)&po, g_o);       cudaGetSymbolAddress((void**)&poa, g_oa);
    cudaGetSymbolAddress((void**)&ph, g_h);       cudaGetSymbolAddress((void**)&px2, g_x2);
    cudaGetSymbolAddress((void**)&pact, g_act);   cudaGetSymbolAddress((void**)&pRC, g_ropeC);
    cudaGetSymbolAddress((void**)&pRS, g_ropeS);

    cudaFuncSetAttribute(tgemm_kernel<EP_NONE>,  cudaFuncAttributeMaxDynamicSharedMemorySize, SMEM_PIPE_BYTES);
    cudaFuncSetAttribute(tgemm_kernel<EP_ADD>,   cudaFuncAttributeMaxDynamicSharedMemorySize, SMEM_PIPE_BYTES);
    cudaFuncSetAttribute(tgemm_kernel<EP_SILU>,  cudaFuncAttributeMaxDynamicSharedMemorySize, SMEM_PIPE_BYTES);
    cudaFuncSetAttribute(tgemm_kernel<EP_RFUSE>, cudaFuncAttributeMaxDynamicSharedMemorySize, SMEM_PIPE_BYTES);

    // 0) rope table + weight packs
    rope_table_kernel<<<(T_ * 32 + 255) / 256, 256>>>(pRC, pRS);
    pack2_kernel<<<(DIM_ * 2 * DH_ + 255) / 256, 256>>>(comp_wkv, comp_wgate, pwkv2, DIM_ * 2 * DH_);
    pack2_kernel<<<(DIM_ * 2 * DI_ + 255) / 256, 256>>>(icomp_wkv, icomp_wgate, pwik2, DIM_ * 2 * DI_);

    // 1) x = rms(hidden, ln1)
    rms_kernel<<<T_, 256>>>(hidden, ln1_w, px, DIM_);

    // 2) qr = rms(x @ wq_a, q_norm)
    tgemm_kernel<EP_NONE><<<ggrid(T_, QL_), 256, SMEM_PIPE_BYTES>>>(T_, QL_, DIM_, px, DIM_, 0, wq_a, QL_, 0, nullptr, pqr, QL_, 0);
    rms_kernel<<<T_, 256>>>(pqr, q_norm_w, pqr, QL_);

    // 3) q / qi projections + rope
    tgemm_kernel<EP_NONE><<<ggrid(T_, H_*DH_), 256, SMEM_PIPE_BYTES>>>(T_, H_*DH_, QL_, pqr, QL_, 0, wq_b, H_*DH_, 0, nullptr, pq, H_*DH_, 0);
    tgemm_kernel<EP_NONE><<<ggrid(T_, HI_*DI_), 256, SMEM_PIPE_BYTES>>>(T_, HI_*DI_, QL_, pqr, QL_, 0, idx_wq_b, HI_*DI_, 0, nullptr, pqi, HI_*DI_, 0);
    rope_apply_kernel<<<T_ * H_ / 8,  256>>>(pq,  positions, pRC, pRS, H_,  DH_, NOPE_,  0, T_ * H_);
    rope_apply_kernel<<<T_ * HI_ / 8, 256>>>(pqi, positions, pRC, pRS, HI_, DI_, INOPE_, 0, T_ * HI_);

    // 4) kvc: z=2 batched {wkv, wgate} GEMM, then elementwise gate+ape
    {
        dim3 g = ggrid(T_, 2*DH_); g.z = 2;
        tgemm_kernel<EP_NONE><<<g, 256, SMEM_PIPE_BYTES>>>(
            T_, 2*DH_, DIM_, px, DIM_, 0, pwkv2, 2*DH_, DIM_ * 2*DH_,
            nullptr, pkv2, 2*DH_, T_ * 2*DH_);
    }
    gate2_kernel<<<(T_ * 2*DH_ + 255) / 256, 256>>>(pkv2, comp_ape, pkvF, 2*DH_);
    compress_kernel<<<SC_, DH_>>>(pkvF, comp_norm_w, pkvc, DH_);
    rope_apply_kernel<<<SC_ / 8, 256>>>(pkvc, positions, pRC, pRS, 1, DH_, NOPE_, 1, SC_);

    // 5) ki: z=2 batched {iwkv, iwgate} GEMM + gate + compress + rope + transpose
    {
        dim3 g = ggrid(T_, 2*DI_); g.z = 2;
        tgemm_kernel<EP_NONE><<<g, 256, SMEM_PIPE_BYTES>>>(
            T_, 2*DI_, DIM_, px, DIM_, 0, pwik2, 2*DI_, DIM_ * 2*DI_,
            nullptr, pik2, 2*DI_, T_ * 2*DI_);
    }
    gate2_kernel<<<(T_ * 2*DI_ + 255) / 256, 256>>>(pik2, icomp_ape, pikF, 2*DI_);
    compress_kernel<<<SC_, DI_>>>(pikF, icomp_norm_w, pki, DI_);
    rope_apply_kernel<<<SC_ / 8, 256>>>(pki, positions, pRC, pRS, 1, DI_, INOPE_, 1, SC_);
    transpose_kernel<<<dim3(DI_/32, SC_/32, 1), dim3(32, 8)>>>(pki, pkiT, SC_, DI_);

    // 6) iw
    tgemm_kernel<EP_NONE><<<ggrid(T_, HI_), 256, SMEM_PIPE_BYTES>>>(T_, HI_, DIM_, px, DIM_, 0, idx_wproj, HI_, 0, nullptr, piw, HI_, 0);

    // 7) R GEMM with fused weighted-relu head reduction -> isc
    tgemm_kernel<EP_RFUSE><<<ggrid(T_*HI_, SC_), 256, SMEM_PIPE_BYTES>>>(T_*HI_, SC_, DI_, pqi, DI_, 0, pkiT, SC_, 0, piw, pisc, SC_, 0);

    // 8) top-256 + attention
    topk_kernel<<<T_, 256>>>(pisc, pselidx, pselcnt);
    attn2_kernel<<<T_, 512>>>(pq, pkvc, pselidx, pselcnt, attn_sink, po);

    // 9) output proj: transpose wo_a, z-batched GEMM, then wo_b (+residual)
    transpose_kernel<<<dim3(FG_/32, OLORA_/32, G_), dim3(32, 8)>>>(wo_a, pwoaT, OLORA_, FG_);
    {
        dim3 g = ggrid(T_, OLORA_); g.z = G_;
        tgemm_kernel<EP_NONE><<<g, 256, SMEM_PIPE_BYTES>>>(
            T_, OLORA_, FG_, po, H_*DH_, FG_, pwoaT, OLORA_, FG_*OLORA_,
            nullptr, poa, G_*OLORA_, OLORA_);
    }
    tgemm_kernel<EP_ADD><<<ggrid(T_, DIM_), 256, SMEM_PIPE_BYTES>>>(T_, DIM_, G_*OLORA_, poa, G_*OLORA_, 0, wo_b, DIM_, 0, hidden, ph, DIM_, 0);

    // 10) MLP: gate GEMM -> act; up GEMM fused silu-mul; down GEMM + residual
    rms_kernel<<<T_, 256>>>(ph, ln2_w, px2, DIM_);
    tgemm_kernel<EP_NONE><<<ggrid(T_, II_), 256, SMEM_PIPE_BYTES>>>(T_, II_, DIM_, px2, DIM_, 0, gate_up_w, 2*II_, 0, nullptr, pact, II_, 0);
    tgemm_kernel<EP_SILU><<<ggrid(T_, II_), 256, SMEM_PIPE_BYTES>>>(T_, II_, DIM_, px2, DIM_, 0, gate_up_w + II_, 2*II_, 0, pact, pact, II_, 0);
    tgemm_kernel<EP_ADD><<<ggrid(T_, DIM_), 256, SMEM_PIPE_BYTES>>>(T_, DIM_, II_, pact, II_, 0, down_w, DIM_, 0, ph, out, DIM_, 0);
}

// round 12
// speedup vs baseline: 1.4944x; 1.4944x over previous
#include <cuda_runtime.h>
#include <math.h>
#include <stdint.h>

#define T_    2048
#define DIM_  2048
#define QL_   1536
#define H_    16
#define DH_   256
#define NOPE_ 192
#define HI_   32
#define DI_   128
#define INOPE_ 64
#define SC_   512
#define TOPK_ 256
#define II_   8192
#define G_    4
#define OLORA_ 512
#define FG_   1024
#define EPSF  1e-6f
#define NEGF  (-1e30f)
#define SCALE_   0.0625f
#define ISCALE_  0.08838834764831845f
#define LOG_THETA 11.98292909421596506

// ---------------- scratch ----------------
__device__ float g_x   [T_ * DIM_];
__device__ float g_qr  [T_ * QL_];
__device__ float g_q   [T_ * H_ * DH_];
__device__ float g_qi  [T_ * HI_ * DI_];
__device__ float g_kvA [T_ * 2 * DH_];
__device__ float g_kvF [T_ * 2 * DH_];
__device__ float g_kvc [SC_ * DH_];
__device__ float g_ikA [T_ * 2 * DI_];
__device__ float g_ikF [T_ * 2 * DI_];
__device__ float g_ki  [SC_ * DI_];
__device__ float g_kiT [DI_ * SC_];
__device__ float g_woaT[G_ * FG_ * OLORA_];
__device__ float g_iw  [T_ * HI_];
__device__ float g_isc [T_ * SC_];
__device__ int   g_selidx[T_ * TOPK_];
__device__ int   g_selcnt[T_];
__device__ float g_o   [T_ * H_ * DH_];
__device__ float g_oa  [T_ * G_ * OLORA_];
__device__ float g_h   [T_ * DIM_];
__device__ float g_x2  [T_ * DIM_];
__device__ float g_act [(size_t)T_ * II_];
__device__ float g_ropeC[T_ * 32];
__device__ float g_ropeS[T_ * 32];

// ---------------- reductions ----------------
__device__ __forceinline__ float blockReduceSum(float v) {
    __shared__ float sh[32];
    int lane = threadIdx.x & 31, wid = threadIdx.x >> 5;
    #pragma unroll
    for (int o = 16; o > 0; o >>= 1) v += __shfl_xor_sync(0xffffffffu, v, o);
    if (lane == 0) sh[wid] = v;
    __syncthreads();
    int nw = (blockDim.x + 31) >> 5;
    if (wid == 0) {
        float r = (lane < nw) ? sh[lane] : 0.0f;
        #pragma unroll
        for (int o = 16; o > 0; o >>= 1) r += __shfl_xor_sync(0xffffffffu, r, o);
        if (lane == 0) sh[0] = r;
    }
    __syncthreads();
    float res = sh[0];
    __syncthreads();
    return res;
}

// ---------------- tf32 / cp.async helpers ----------------
__device__ __forceinline__ uint32_t f2tf32(float x) {
    uint32_t r;
    asm("cvt.rna.tf32.f32 %0, %1;" : "=r"(r) : "f"(x));
    return r;
}

__device__ __forceinline__ void mma_tf32(float* d, const uint32_t* a, const uint32_t* b) {
    asm volatile(
        "mma.sync.aligned.m16n8k8.row.col.f32.tf32.tf32.f32 "
        "{%0,%1,%2,%3}, {%4,%5,%6,%7}, {%8,%9}, {%0,%1,%2,%3};"
        : "+f"(d[0]), "+f"(d[1]), "+f"(d[2]), "+f"(d[3])
        : "r"(a[0]), "r"(a[1]), "r"(a[2]), "r"(a[3]), "r"(b[0]), "r"(b[1]));
}

__device__ __forceinline__ void cp16(float* smem_dst, const float* gsrc, bool pred) {
    uint32_t s = (uint32_t)__cvta_generic_to_shared(smem_dst);
    int sz = pred ? 16 : 0;
    asm volatile("cp.async.cg.shared.global [%0], [%1], 16, %2;\n"
                 :: "r"(s), "l"(gsrc), "r"(sz));
}
#define CP_COMMIT() asm volatile("cp.async.commit_group;" ::: "memory")
#define CP_WAIT1()  asm volatile("cp.async.wait_group 1;" ::: "memory")
#define CP_WAIT0()  asm volatile("cp.async.wait_group 0;" ::: "memory")

// ---------------- epilogue modes ----------------
#define EP_NONE  0
#define EP_ADD   1
#define EP_GATE  2
#define EP_SILU  3
#define EP_RFUSE 4

// ---------------- tensor-core TF32 GEMM, 128x128x32, 3-stage cp.async +
// register double-buffered fragments ----------------
#define BM 128
#define BN 128
#define BK 32
#define AS_S 36
#define BS_S 136
#define A_TILE (BM * AS_S)
#define B_TILE (BK * BS_S)
#define STAGE_F (A_TILE + B_TILE)
#define SMEM_PIPE_BYTES (STAGE_F * 3 * 4)   // 107520

template<int EP>
__global__ void __launch_bounds__(256, 2) tgemm_kernel(
    int M, int N, int K,
    const float* __restrict__ A, int lda, int aZ,
    const float* __restrict__ B, int ldb, int bZ,
    const float* __restrict__ Cadd,
    const float* __restrict__ aux,
    float* __restrict__ C, int ldc, int cZ)
{
    extern __shared__ float smem[];
    const int bm = blockIdx.y * BM;
    const int bn = blockIdx.x * BN;
    A += (size_t)blockIdx.z * aZ;
    B += (size_t)blockIdx.z * bZ;
    C += (size_t)blockIdx.z * cZ;
    const int tid = threadIdx.x;
    const int lane = tid & 31;
    const int wid = tid >> 5;
    const int wm = wid & 3;
    const int wn = wid >> 2;
    const int gid = lane >> 2;
    const int tig = lane & 3;

    float acc[2][8][4];
    #pragma unroll
    for (int mi = 0; mi < 2; mi++)
        #pragma unroll
        for (int ni = 0; ni < 8; ni++)
            #pragma unroll
            for (int r = 0; r < 4; r++) acc[mi][ni][r] = 0.0f;

    const int nIter = K / BK;

    auto issue = [&](int st, int k0) {
        float* sA = smem + st * STAGE_F;
        float* sB = sA + A_TILE;
        #pragma unroll
        for (int i = 0; i < 4; i++) {
            int f = tid + i * 256;
            int r = f >> 3, q = f & 7;
            int gr = bm + r;
            cp16(&sA[r * AS_S + 4 * q], A + (size_t)gr * lda + k0 + 4 * q, gr < M);
        }
        #pragma unroll
        for (int i = 0; i < 4; i++) {
            int f = tid + i * 256;
            int k = f >> 5, q = f & 31;
            int gc = bn + 4 * q;
            cp16(&sB[k * BS_S + 4 * q], B + (size_t)(k0 + k) * ldb + gc, gc < N);
        }
    };

    // fragment loaders for one kk-step (kb = kk*8)
    auto load_frags = [&](const float* sA, const float* sB, int kb,
                          uint32_t af[2][4], uint32_t bf[8][2]) {
        #pragma unroll
        for (int mi = 0; mi < 2; mi++) {
            int r = wm * 32 + mi * 16 + gid;
            af[mi][0] = f2tf32(sA[r * AS_S + kb + tig]);
            af[mi][1] = f2tf32(sA[(r + 8) * AS_S + kb + tig]);
            af[mi][2] = f2tf32(sA[r * AS_S + kb + tig + 4]);
            af[mi][3] = f2tf32(sA[(r + 8) * AS_S + kb + tig + 4]);
        }
        #pragma unroll
        for (int ni = 0; ni < 8; ni++) {
            int c = wn * 64 + ni * 8 + gid;
            bf[ni][0] = f2tf32(sB[(kb + tig) * BS_S + c]);
            bf[ni][1] = f2tf32(sB[(kb + tig + 4) * BS_S + c]);
        }
    };

    auto frag_compute = [&](int st) {
        const float* sA = smem + st * STAGE_F;
        const float* sB = sA + A_TILE;
        uint32_t af[2][2][4];
        uint32_t bf[2][8][2];
        load_frags(sA, sB, 0, af[0], bf[0]);
        #pragma unroll
        for (int kk = 0; kk < 4; kk++) {
            if (kk < 3)
                load_frags(sA, sB, (kk + 1) * 8, af[(kk + 1) & 1], bf[(kk + 1) & 1]);
            #pragma unroll
            for (int mi = 0; mi < 2; mi++)
                #pragma unroll
                for (int ni = 0; ni < 8; ni++)
                    mma_tf32(acc[mi][ni], af[kk & 1][mi], bf[kk & 1][ni]);
        }
    };

    issue(0, 0);
    CP_COMMIT();
    if (nIter > 1) { issue(1, BK); CP_COMMIT(); }

    int st = 0;
    for (int it = 0; it < nIter; ++it) {
        if (it + 1 < nIter) CP_WAIT1(); else CP_WAIT0();
        __syncthreads();
        if (it + 2 < nIter) {
            int st2 = st + 2; if (st2 >= 3) st2 -= 3;
            issue(st2, (it + 2) * BK);
            CP_COMMIT();
        }
        frag_compute(st);
        if (++st == 3) st = 0;
    }

    // ---------------- epilogues ----------------
    if (EP == EP_RFUSE) {
        int t = bm / HI_ + wm;
        float wA = Cadd[t * HI_ + gid];
        float wB = Cadd[t * HI_ + gid + 8];
        float wC = Cadd[t * HI_ + gid + 16];
        float wD = Cadd[t * HI_ + gid + 24];
        #pragma unroll
        for (int ni = 0; ni < 8; ni++) {
            float p0 = wA * fmaxf(acc[0][ni][0], 0.f) + wB * fmaxf(acc[0][ni][2], 0.f)
                     + wC * fmaxf(acc[1][ni][0], 0.f) + wD * fmaxf(acc[1][ni][2], 0.f);
            float p1 = wA * fmaxf(acc[0][ni][1], 0.f) + wB * fmaxf(acc[0][ni][3], 0.f)
                     + wC * fmaxf(acc[1][ni][1], 0.f) + wD * fmaxf(acc[1][ni][3], 0.f);
            #pragma unroll
            for (int off = 4; off < 32; off <<= 1) {
                p0 += __shfl_xor_sync(0xffffffffu, p0, off);
                p1 += __shfl_xor_sync(0xffffffffu, p1, off);
            }
            if (gid == 0) {
                int c = bn + wn * 64 + ni * 8 + tig * 2;
                C[(size_t)t * ldc + c]     = p0 * ISCALE_;
                C[(size_t)t * ldc + c + 1] = p1 * ISCALE_;
            }
        }
        return;
    }

    #pragma unroll
    for (int mi = 0; mi < 2; mi++) {
        int r0 = bm + wm * 32 + mi * 16 + gid;
        int r1 = r0 + 8;
        #pragma unroll
        for (int ni = 0; ni < 8; ni++) {
            int c = bn + wn * 64 + ni * 8 + tig * 2;
            float* ap = acc[mi][ni];
            if (c < N) {
                #pragma unroll
                for (int half = 0; half < 2; half++) {
                    int r = half ? r1 : r0;
                    if (r >= M) continue;
                    float a0 = ap[half * 2], a1 = ap[half * 2 + 1];
                    float v0, v1;
                    if (EP == EP_NONE) {
                        v0 = a0; v1 = a1;
                    } else if (EP == EP_ADD) {
                        float2 cc = *(const float2*)(Cadd + (size_t)r * ldc + c);
                        v0 = a0 + cc.x; v1 = a1 + cc.y;
                    } else if (EP == EP_GATE) {
                        float2 kv = *(const float2*)(Cadd + (size_t)r * ldc + c);
                        float2 ap2 = *(const float2*)(aux + (size_t)(r & 3) * N + c);
                        v0 = kv.x / (1.0f + expf(-a0)) + ap2.x;
                        v1 = kv.y / (1.0f + expf(-a1)) + ap2.y;
                    } else { // EP_SILU
                        float2 gg = *(const float2*)(Cadd + (size_t)r * ldc + c);
                        v0 = gg.x / (1.0f + expf(-gg.x)) * a0;
                        v1 = gg.y / (1.0f + expf(-gg.y)) * a1;
                    }
                    *(float2*)(C + (size_t)r * ldc + c) = make_float2(v0, v1);
                }
            }
        }
    }
}

// ---------------- tiled transpose ----------------
__global__ void transpose_kernel(const float* __restrict__ in, float* __restrict__ out,
                                 int R, int C)
{
    __shared__ float tile[32][33];
    const float* inz = in + (size_t)blockIdx.z * R * C;
    float* outz = out + (size_t)blockIdx.z * R * C;
    int bx = blockIdx.x * 32, by = blockIdx.y * 32;
    int x = bx + threadIdx.x;
    #pragma unroll
    for (int i = 0; i < 4; i++) {
        int y = by + threadIdx.y + 8 * i;
        if (y < R && x < C) tile[threadIdx.y + 8 * i][threadIdx.x] = inz[(size_t)y * C + x];
    }
    __syncthreads();
    int x2 = by + threadIdx.x;
    #pragma unroll
    for (int i = 0; i < 4; i++) {
        int y2 = bx + threadIdx.y + 8 * i;
        if (y2 < C && x2 < R) outz[(size_t)y2 * R + x2] = tile[threadIdx.x][threadIdx.y + 8 * i];
    }
}

// ---------------- rmsnorm ----------------
__global__ void rms_kernel(const float* __restrict__ in, const float* __restrict__ w,
                           float* __restrict__ out, int D)
{
    int t = blockIdx.x;
    const float* row = in + (size_t)t * D;
    float s = 0.0f;
    for (int d = threadIdx.x; d < D; d += blockDim.x) { float v = row[d]; s += v * v; }
    s = blockReduceSum(s);
    float inv = rsqrtf(s / (float)D + EPSF);
    for (int d = threadIdx.x; d < D; d += blockDim.x)
        out[(size_t)t * D + d] = row[d] * inv * w[d];
}

// ---------------- compress ----------------
__global__ void compress_kernel(const float* __restrict__ kvf, const float* __restrict__ w,
                                float* __restrict__ out, int d)
{
    int b = blockIdx.x;
    int e = threadIdx.x;
    int W = 2 * d;
    float m = 0.0f;
    if (b > 0) {
        #pragma unroll
        for (int r = 0; r < 4; r++) m += kvf[(size_t)((b - 1) * 4 + r) * W + e];
    }
    #pragma unroll
    for (int r = 0; r < 4; r++) m += kvf[(size_t)(b * 4 + r) * W + d + e];
    m *= 0.125f;
    float ssq = blockReduceSum(m * m);
    float inv = rsqrtf(ssq / (float)d + EPSF);
    out[(size_t)b * d + e] = m * inv * w[e];
}

// ---------------- RoPE table + apply ----------------
__global__ void rope_table_kernel(float* __restrict__ tc, float* __restrict__ ts)
{
    int i = blockIdx.x * blockDim.x + threadIdx.x;
    if (i >= T_ * 32) return;
    int pos = i >> 5, f = i & 31;
    double freq = exp(-((double)(2 * f) / 64.0) * LOG_THETA);
    double ang = (double)pos * freq;
    tc[i] = (float)cos(ang);
    ts[i] = (float)sin(ang);
}

__global__ void rope_apply_kernel(float* __restrict__ x, const int* __restrict__ positions,
                                  const float* __restrict__ tc, const float* __restrict__ ts,
                                  int Hh, int Dd, int ropeOff, int compPos, int nRows)
{
    int row = blockIdx.x * 8 + (threadIdx.x >> 5);
    if (row >= nRows) return;
    int lane = threadIdx.x & 31;
    int t = row / Hh;
    int pos = compPos ? (4 * (t + 1) - 1) : positions[t];
    float c = tc[pos * 32 + lane], s = ts[pos * 32 + lane];
    float* p = x + (size_t)row * Dd + ropeOff;
    float x0 = p[2 * lane], x1 = p[2 * lane + 1];
    p[2 * lane]     = x0 * c - x1 * s;
    p[2 * lane + 1] = x0 * s + x1 * c;
}

// ---------------- exact top-256 ----------------
__global__ void topk_kernel(const float* __restrict__ isc, int* __restrict__ selidx,
                            int* __restrict__ selcnt)
{
    int t = blockIdx.x;
    __shared__ float sv[SC_];
    __shared__ int   si[SC_];
    int tid = threadIdx.x;
    int visCount = (t >= 3) ? ((t - 3) / 4 + 1) : 0;
    for (int i = tid; i < SC_; i += 256) {
        sv[i] = (i < visCount) ? isc[t * SC_ + i] : NEGF;
        si[i] = i;
    }
    __syncthreads();
    for (int k = 2; k <= SC_; k <<= 1) {
        for (int j = k >> 1; j > 0; j >>= 1) {
            for (int base = tid; base < SC_; base += 256) {
                int partner = base ^ j;
                if (partner > base) {
                    bool up = ((base & k) == 0);
                    float va = sv[base], vb = sv[partner];
                    int ia = si[base], ib = si[partner];
                    bool aFirst = (va > vb) || (va == vb && ia < ib);
                    if (up ? !aFirst : aFirst) {
                        sv[base] = vb; sv[partner] = va;
                        si[base] = ib; si[partner] = ia;
                    }
                }
            }
            __syncthreads();
        }
    }
    int cnt = min(visCount, TOPK_);
    if (tid == 0) selcnt[t] = cnt;
    for (int r = tid; r < cnt; r += 256) selidx[t * TOPK_ + r] = si[r];
}

// ---------------- head-shared flash attention ----------------
__global__ void __launch_bounds__(512) attn2_kernel(
    const float* __restrict__ q, const float* __restrict__ kvc,
    const int* __restrict__ selidx, const int* __restrict__ selcnt,
    const float* __restrict__ sink, float* __restrict__ o)
{
    __shared__ float kt[32][DH_];
    __shared__ int   ss[TOPK_];
    int t = blockIdx.x;
    int tid = threadIdx.x, lane = tid & 31, w = tid >> 5;
    int cnt = selcnt[t];
    for (int i = tid; i < cnt; i += 512) ss[i] = selidx[t * TOPK_ + i];
    __syncthreads();

    float q8[8];
    const float* qp = q + ((size_t)t * H_ + w) * DH_;
    #pragma unroll
    for (int i = 0; i < 8; i++) q8[i] = qp[lane + 32 * i];

    float m = NEGF, se = 0.0f;
    float acc[8] = {};

    for (int j0 = 0; j0 < cnt; j0 += 32) {
        int rem = min(32, cnt - j0);
        __syncthreads();
        for (int f = tid; f < 32 * 64; f += 512) {
            int r = f >> 6, c4 = f & 63;
            float4 v = make_float4(0.f, 0.f, 0.f, 0.f);
            if (r < rem) v = *(const float4*)(kvc + (size_t)ss[j0 + r] * DH_ + 4 * c4);
            *(float4*)&kt[r][4 * c4] = v;
        }
        __syncthreads();
        for (int j = 0; j < rem; j++) {
            float dot = 0.0f;
            #pragma unroll
            for (int i = 0; i < 8; i++) dot += q8[i] * kt[j][lane + 32 * i];
            #pragma unroll
            for (int off = 16; off > 0; off >>= 1)
                dot += __shfl_xor_sync(0xffffffffu, dot, off);
            float lg = dot * SCALE_;
            float mn = fmaxf(m, lg);
            float sc = expf(m - mn);
            float p  = expf(lg - mn);
            se = se * sc + p;
            #pragma unroll
            for (int i = 0; i < 8; i++)
                acc[i] = acc[i] * sc + p * kt[j][lane + 32 * i];
            m = mn;
        }
    }

    float snk = sink[w];
    float mn = fmaxf(m, snk);
    float sc = expf(m - mn);
    se = se * sc + expf(snk - mn);
    float inv = 1.0f / se;
    float* op = o + ((size_t)t * H_ + w) * DH_;
    #pragma unroll
    for (int i = 0; i < 8; i++) op[lane + 32 * i] = acc[i] * sc * inv;
}

// ---------------- host ----------------
static inline dim3 ggrid(int M, int N) { return dim3((N + BN - 1) / BN, (M + BM - 1) / BM); }

extern "C" void kernel_launch(void* const* d_in, const int* in_sizes, int n_in,
                              void* d_out, int out_size)
{
    const float* hidden      = (const float*)d_in[0];
    const int*   positions   = (const int*)  d_in[1];
    const float* ln1_w       = (const float*)d_in[2];
    const float* ln2_w       = (const float*)d_in[3];
    const float* wq_a        = (const float*)d_in[4];
    const float* q_norm_w    = (const float*)d_in[5];
    const float* wq_b        = (const float*)d_in[6];
    const float* comp_wkv    = (const float*)d_in[7];
    const float* comp_wgate  = (const float*)d_in[8];
    const float* comp_ape    = (const float*)d_in[9];
    const float* comp_norm_w = (const float*)d_in[10];
    const float* idx_wq_b    = (const float*)d_in[11];
    const float* idx_wproj   = (const float*)d_in[12];
    const float* icomp_wkv   = (const float*)d_in[13];
    const float* icomp_wgate = (const float*)d_in[14];
    const float* icomp_ape   = (const float*)d_in[15];
    const float* icomp_norm_w= (const float*)d_in[16];
    const float* attn_sink   = (const float*)d_in[17];
    const float* wo_a        = (const float*)d_in[18];
    const float* wo_b        = (const float*)d_in[19];
    const float* gate_up_w   = (const float*)d_in[20];
    const float* down_w      = (const float*)d_in[21];
    float* out = (float*)d_out;

    float *px,*pqr,*pq,*pqi,*pkvA,*pkvF,*pkvc,*pikA,*pikF,*pki,*pkiT,*pwoaT,*piw,*pisc;
    float *po,*poa,*ph,*px2,*pact,*pRC,*pRS;
    int *pselidx,*pselcnt;
    cudaGetSymbolAddress((void**)&px, g_x);       cudaGetSymbolAddress((void**)&pqr, g_qr);
    cudaGetSymbolAddress((void**)&pq, g_q);       cudaGetSymbolAddress((void**)&pqi, g_qi);
    cudaGetSymbolAddress((void**)&pkvA, g_kvA);   cudaGetSymbolAddress((void**)&pkvF, g_kvF);
    cudaGetSymbolAddress((void**)&pkvc, g_kvc);   cudaGetSymbolAddress((void**)&pikA, g_ikA);
    cudaGetSymbolAddress((void**)&pikF, g_ikF);   cudaGetSymbolAddress((void**)&pki, g_ki);
    cudaGetSymbolAddress((void**)&pkiT, g_kiT);   cudaGetSymbolAddress((void**)&pwoaT, g_woaT);
    cudaGetSymbolAddress((void**)&piw, g_iw);     cudaGetSymbolAddress((void**)&pisc, g_isc);
    cudaGetSymbolAddress((void**)&pselidx, g_selidx); cudaGetSymbolAddress((void**)&pselcnt, g_selcnt);
    cudaGetSymbolAddress((void**)&po, g_o);       cudaGetSymbolAddress((void**)&poa, g_oa);
    cudaGetSymbolAddress((void**)&ph, g_h);       cudaGetSymbolAddress((void**)&px2, g_x2);
    cudaGetSymbolAddress((void**)&pact, g_act);   cudaGetSymbolAddress((void**)&pRC, g_ropeC);
    cudaGetSymbolAddress((void**)&pRS, g_ropeS);

    cudaFuncSetAttribute(tgemm_kernel<EP_NONE>,  cudaFuncAttributeMaxDynamicSharedMemorySize, SMEM_PIPE_BYTES);
    cudaFuncSetAttribute(tgemm_kernel<EP_ADD>,   cudaFuncAttributeMaxDynamicSharedMemorySize, SMEM_PIPE_BYTES);
    cudaFuncSetAttribute(tgemm_kernel<EP_GATE>,  cudaFuncAttributeMaxDynamicSharedMemorySize, SMEM_PIPE_BYTES);
    cudaFuncSetAttribute(tgemm_kernel<EP_SILU>,  cudaFuncAttributeMaxDynamicSharedMemorySize, SMEM_PIPE_BYTES);
    cudaFuncSetAttribute(tgemm_kernel<EP_RFUSE>, cudaFuncAttributeMaxDynamicSharedMemorySize, SMEM_PIPE_BYTES);

    // 0) rope table
    rope_table_kernel<<<(T_ * 32 + 255) / 256, 256>>>(pRC, pRS);

    // 1) x = rms(hidden, ln1)
    rms_kernel<<<T_, 256>>>(hidden, ln1_w, px, DIM_);

    // 2) qr = rms(x @ wq_a, q_norm)
    tgemm_kernel<EP_NONE><<<ggrid(T_, QL_), 256, SMEM_PIPE_BYTES>>>(T_, QL_, DIM_, px, DIM_, 0, wq_a, QL_, 0, nullptr, nullptr, pqr, QL_, 0);
    rms_kernel<<<T_, 256>>>(pqr, q_norm_w, pqr, QL_);

    // 3) q / qi projections + rope
    tgemm_kernel<EP_NONE><<<ggrid(T_, H_*DH_), 256, SMEM_PIPE_BYTES>>>(T_, H_*DH_, QL_, pqr, QL_, 0, wq_b, H_*DH_, 0, nullptr, nullptr, pq, H_*DH_, 0);
    tgemm_kernel<EP_NONE><<<ggrid(T_, HI_*DI_), 256, SMEM_PIPE_BYTES>>>(T_, HI_*DI_, QL_, pqr, QL_, 0, idx_wq_b, HI_*DI_, 0, nullptr, nullptr, pqi, HI_*DI_, 0);
    rope_apply_kernel<<<T_ * H_ / 8,  256>>>(pq,  positions, pRC, pRS, H_,  DH_, NOPE_,  0, T_ * H_);
    rope_apply_kernel<<<T_ * HI_ / 8, 256>>>(pqi, positions, pRC, pRS, HI_, DI_, INOPE_, 0, T_ * HI_);

    // 4) kvc: wkv GEMM, then wgate GEMM with fused sigmoid-gate + ape
    tgemm_kernel<EP_NONE><<<ggrid(T_, 2*DH_), 256, SMEM_PIPE_BYTES>>>(T_, 2*DH_, DIM_, px, DIM_, 0, comp_wkv, 2*DH_, 0, nullptr, nullptr, pkvA, 2*DH_, 0);
    tgemm_kernel<EP_GATE><<<ggrid(T_, 2*DH_), 256, SMEM_PIPE_BYTES>>>(T_, 2*DH_, DIM_, px, DIM_, 0, comp_wgate, 2*DH_, 0, pkvA, comp_ape, pkvF, 2*DH_, 0);
    compress_kernel<<<SC_, DH_>>>(pkvF, comp_norm_w, pkvc, DH_);
    rope_apply_kernel<<<SC_ / 8, 256>>>(pkvc, positions, pRC, pRS, 1, DH_, NOPE_, 1, SC_);

    // 5) ki: same fused pattern + rope + transpose
    tgemm_kernel<EP_NONE><<<ggrid(T_, 2*DI_), 256, SMEM_PIPE_BYTES>>>(T_, 2*DI_, DIM_, px, DIM_, 0, icomp_wkv, 2*DI_, 0, nullptr, nullptr, pikA, 2*DI_, 0);
    tgemm_kernel<EP_GATE><<<ggrid(T_, 2*DI_), 256, SMEM_PIPE_BYTES>>>(T_, 2*DI_, DIM_, px, DIM_, 0, icomp_wgate, 2*DI_, 0, pikA, icomp_ape, pikF, 2*DI_, 0);
    compress_kernel<<<SC_, DI_>>>(pikF, icomp_norm_w, pki, DI_);
    rope_apply_kernel<<<SC_ / 8, 256>>>(pki, positions, pRC, pRS, 1, DI_, INOPE_, 1, SC_);
    transpose_kernel<<<dim3(DI_/32, SC_/32, 1), dim3(32, 8)>>>(pki, pkiT, SC_, DI_);

    // 6) iw
    tgemm_kernel<EP_NONE><<<ggrid(T_, HI_), 256, SMEM_PIPE_BYTES>>>(T_, HI_, DIM_, px, DIM_, 0, idx_wproj, HI_, 0, nullptr, nullptr, piw, HI_, 0);

    // 7) R GEMM with fused weighted-relu head reduction -> isc
    tgemm_kernel<EP_RFUSE><<<ggrid(T_*HI_, SC_), 256, SMEM_PIPE_BYTES>>>(T_*HI_, SC_, DI_, pqi, DI_, 0, pkiT, SC_, 0, piw, nullptr, pisc, SC_, 0);

    // 8) top-256 + attention
    topk_kernel<<<T_, 256>>>(pisc, pselidx, pselcnt);
    attn2_kernel<<<T_, 512>>>(pq, pkvc, pselidx, pselcnt, attn_sink, po);

    // 9) output proj: transpose wo_a, ONE z-batched GEMM, then wo_b (+residual)
    transpose_kernel<<<dim3(FG_/32, OLORA_/32, G_), dim3(32, 8)>>>(wo_a, pwoaT, OLORA_, FG_);
    {
        dim3 g = ggrid(T_, OLORA_); g.z = G_;
        tgemm_kernel<EP_NONE><<<g, 256, SMEM_PIPE_BYTES>>>(
            T_, OLORA_, FG_, po, H_*DH_, FG_, pwoaT, OLORA_, FG_*OLORA_,
            nullptr, nullptr, poa, G_*OLORA_, OLORA_);
    }
    tgemm_kernel<EP_ADD><<<ggrid(T_, DIM_), 256, SMEM_PIPE_BYTES>>>(T_, DIM_, G_*OLORA_, poa, G_*OLORA_, 0, wo_b, DIM_, 0, hidden, nullptr, ph, DIM_, 0);

    // 10) MLP: gate GEMM -> act; up GEMM fused silu-mul; down GEMM + residual
    rms_kernel<<<T_, 256>>>(ph, ln2_w, px2, DIM_);
    tgemm_kernel<EP_NONE><<<ggrid(T_, II_), 256, SMEM_PIPE_BYTES>>>(T_, II_, DIM_, px2, DIM_, 0, gate_up_w, 2*II_, 0, nullptr, nullptr, pact, II_, 0);
    tgemm_kernel<EP_SILU><<<ggrid(T_, II_), 256, SMEM_PIPE_BYTES>>>(T_, II_, DIM_, px2, DIM_, 0, gate_up_w + II_, 2*II_, 0, pact, nullptr, pact, II_, 0);
    tgemm_kernel<EP_ADD><<<ggrid(T_, DIM_), 256, SMEM_PIPE_BYTES>>>(T_, DIM_, II_, pact, II_, 0, down_w, DIM_, 0, ph, nullptr, out, DIM_, 0);
}

// round 13
// speedup vs baseline: 1.5670x; 1.0486x over previous
#include <cuda_runtime.h>
#include <math.h>
#include <stdint.h>

#define T_    2048
#define DIM_  2048
#define QL_   1536
#define H_    16
#define DH_   256
#define NOPE_ 192
#define HI_   32
#define DI_   128
#define INOPE_ 64
#define SC_   512
#define TOPK_ 256
#define II_   8192
#define G_    4
#define OLORA_ 512
#define FG_   1024
#define EPSF  1e-6f
#define NEGF  (-1e30f)
#define SCALE_   0.0625f
#define ISCALE_  0.08838834764831845f
#define LOG_THETA 11.98292909421596506

// ---------------- scratch ----------------
__device__ float g_x   [T_ * DIM_];
__device__ float g_qr  [T_ * QL_];
__device__ float g_q   [T_ * H_ * DH_];
__device__ float g_qi  [T_ * HI_ * DI_];
__device__ float g_wkv2[2 * DIM_ * 2 * DH_];   // packed {comp_wkv, comp_wgate}
__device__ float g_wik2[2 * DIM_ * 2 * DI_];   // packed {icomp_wkv, icomp_wgate}
__device__ float g_kv2 [2 * T_ * 2 * DH_];     // raw z-batched outputs
__device__ float g_ik2 [2 * T_ * 2 * DI_];
__device__ float g_kvF [T_ * 2 * DH_];
__device__ float g_kvc [SC_ * DH_];
__device__ float g_ikF [T_ * 2 * DI_];
__device__ float g_ki  [SC_ * DI_];
__device__ float g_kiT [DI_ * SC_];
__device__ float g_woaT[G_ * FG_ * OLORA_];
__device__ float g_iw  [T_ * HI_];
__device__ float g_isc [T_ * SC_];
__device__ int   g_selidx[T_ * TOPK_];
__device__ int   g_selcnt[T_];
__device__ float g_o   [T_ * H_ * DH_];
__device__ float g_oa  [T_ * G_ * OLORA_];
__device__ float g_h   [T_ * DIM_];
__device__ float g_x2  [T_ * DIM_];
__device__ float g_act [(size_t)T_ * II_];
__device__ float g_ropeC[T_ * 32];
__device__ float g_ropeS[T_ * 32];

// ---------------- reductions ----------------
__device__ __forceinline__ float blockReduceSum(float v) {
    __shared__ float sh[32];
    int lane = threadIdx.x & 31, wid = threadIdx.x >> 5;
    #pragma unroll
    for (int o = 16; o > 0; o >>= 1) v += __shfl_xor_sync(0xffffffffu, v, o);
    if (lane == 0) sh[wid] = v;
    __syncthreads();
    int nw = (blockDim.x + 31) >> 5;
    if (wid == 0) {
        float r = (lane < nw) ? sh[lane] : 0.0f;
        #pragma unroll
        for (int o = 16; o > 0; o >>= 1) r += __shfl_xor_sync(0xffffffffu, r, o);
        if (lane == 0) sh[0] = r;
    }
    __syncthreads();
    float res = sh[0];
    __syncthreads();
    return res;
}

// ---------------- tf32 / cp.async helpers ----------------
__device__ __forceinline__ uint32_t f2tf32(float x) {
    uint32_t r;
    asm("cvt.rna.tf32.f32 %0, %1;" : "=r"(r) : "f"(x));
    return r;
}

__device__ __forceinline__ void mma_tf32(float* d, const uint32_t* a, const uint32_t* b) {
    asm volatile(
        "mma.sync.aligned.m16n8k8.row.col.f32.tf32.tf32.f32 "
        "{%0,%1,%2,%3}, {%4,%5,%6,%7}, {%8,%9}, {%0,%1,%2,%3};"
        : "+f"(d[0]), "+f"(d[1]), "+f"(d[2]), "+f"(d[3])
        : "r"(a[0]), "r"(a[1]), "r"(a[2]), "r"(a[3]), "r"(b[0]), "r"(b[1]));
}

__device__ __forceinline__ void cp16(float* smem_dst, const float* gsrc, bool pred) {
    uint32_t s = (uint32_t)__cvta_generic_to_shared(smem_dst);
    int sz = pred ? 16 : 0;
    asm volatile("cp.async.cg.shared.global [%0], [%1], 16, %2;\n"
                 :: "r"(s), "l"(gsrc), "r"(sz));
}
#define CP_COMMIT() asm volatile("cp.async.commit_group;" ::: "memory")
#define CP_WAIT1()  asm volatile("cp.async.wait_group 1;" ::: "memory")
#define CP_WAIT0()  asm volatile("cp.async.wait_group 0;" ::: "memory")

// ---------------- epilogue modes ----------------
#define EP_NONE  0
#define EP_ADD   1
#define EP_SILU  3
#define EP_RFUSE 4

// ---------------- tensor-core TF32 GEMM, 128x128x32, 3-stage cp.async +
// register double-buffered fragments ----------------
#define BM 128
#define BN 128
#define BK 32
#define AS_S 36
#define BS_S 136
#define A_TILE (BM * AS_S)
#define B_TILE (BK * BS_S)
#define STAGE_F (A_TILE + B_TILE)
#define SMEM_PIPE_BYTES (STAGE_F * 3 * 4)   // 107520

template<int EP>
__global__ void __launch_bounds__(256, 2) tgemm_kernel(
    int M, int N, int K,
    const float* __restrict__ A, int lda, int aZ,
    const float* __restrict__ B, int ldb, int bZ,
    const float* __restrict__ Cadd,
    float* __restrict__ C, int ldc, int cZ)
{
    extern __shared__ float smem[];
    const int bm = blockIdx.y * BM;
    const int bn = blockIdx.x * BN;
    A += (size_t)blockIdx.z * aZ;
    B += (size_t)blockIdx.z * bZ;
    C += (size_t)blockIdx.z * cZ;
    const int tid = threadIdx.x;
    const int lane = tid & 31;
    const int wid = tid >> 5;
    const int wm = wid & 3;
    const int wn = wid >> 2;
    const int gid = lane >> 2;
    const int tig = lane & 3;

    float acc[2][8][4];
    #pragma unroll
    for (int mi = 0; mi < 2; mi++)
        #pragma unroll
        for (int ni = 0; ni < 8; ni++)
            #pragma unroll
            for (int r = 0; r < 4; r++) acc[mi][ni][r] = 0.0f;

    const int nIter = K / BK;

    auto issue = [&](int st, int k0) {
        float* sA = smem + st * STAGE_F;
        float* sB = sA + A_TILE;
        #pragma unroll
        for (int i = 0; i < 4; i++) {
            int f = tid + i * 256;
            int r = f >> 3, q = f & 7;
            int gr = bm + r;
            cp16(&sA[r * AS_S + 4 * q], A + (size_t)gr * lda + k0 + 4 * q, gr < M);
        }
        #pragma unroll
        for (int i = 0; i < 4; i++) {
            int f = tid + i * 256;
            int k = f >> 5, q = f & 31;
            int gc = bn + 4 * q;
            cp16(&sB[k * BS_S + 4 * q], B + (size_t)(k0 + k) * ldb + gc, gc < N);
        }
    };

    auto load_frags = [&](const float* sA, const float* sB, int kb,
                          uint32_t af[2][4], uint32_t bf[8][2]) {
        #pragma unroll
        for (int mi = 0; mi < 2; mi++) {
            int r = wm * 32 + mi * 16 + gid;
            af[mi][0] = f2tf32(sA[r * AS_S + kb + tig]);
            af[mi][1] = f2tf32(sA[(r + 8) * AS_S + kb + tig]);
            af[mi][2] = f2tf32(sA[r * AS_S + kb + tig + 4]);
            af[mi][3] = f2tf32(sA[(r + 8) * AS_S + kb + tig + 4]);
        }
        #pragma unroll
        for (int ni = 0; ni < 8; ni++) {
            int c = wn * 64 + ni * 8 + gid;
            bf[ni][0] = f2tf32(sB[(kb + tig) * BS_S + c]);
            bf[ni][1] = f2tf32(sB[(kb + tig + 4) * BS_S + c]);
        }
    };

    auto frag_compute = [&](int st) {
        const float* sA = smem + st * STAGE_F;
        const float* sB = sA + A_TILE;
        uint32_t af[2][2][4];
        uint32_t bf[2][8][2];
        load_frags(sA, sB, 0, af[0], bf[0]);
        #pragma unroll
        for (int kk = 0; kk < 4; kk++) {
            if (kk < 3)
                load_frags(sA, sB, (kk + 1) * 8, af[(kk + 1) & 1], bf[(kk + 1) & 1]);
            #pragma unroll
            for (int mi = 0; mi < 2; mi++)
                #pragma unroll
                for (int ni = 0; ni < 8; ni++)
                    mma_tf32(acc[mi][ni], af[kk & 1][mi], bf[kk & 1][ni]);
        }
    };

    issue(0, 0);
    CP_COMMIT();
    if (nIter > 1) { issue(1, BK); CP_COMMIT(); }

    int st = 0;
    for (int it = 0; it < nIter; ++it) {
        if (it + 1 < nIter) CP_WAIT1(); else CP_WAIT0();
        __syncthreads();
        if (it + 2 < nIter) {
            int st2 = st + 2; if (st2 >= 3) st2 -= 3;
            issue(st2, (it + 2) * BK);
            CP_COMMIT();
        }
        frag_compute(st);
        if (++st == 3) st = 0;
    }

    // ---------------- epilogues ----------------
    if (EP == EP_RFUSE) {
        int t = bm / HI_ + wm;
        float wA = Cadd[t * HI_ + gid];
        float wB = Cadd[t * HI_ + gid + 8];
        float wC = Cadd[t * HI_ + gid + 16];
        float wD = Cadd[t * HI_ + gid + 24];
        #pragma unroll
        for (int ni = 0; ni < 8; ni++) {
            float p0 = wA * fmaxf(acc[0][ni][0], 0.f) + wB * fmaxf(acc[0][ni][2], 0.f)
                     + wC * fmaxf(acc[1][ni][0], 0.f) + wD * fmaxf(acc[1][ni][2], 0.f);
            float p1 = wA * fmaxf(acc[0][ni][1], 0.f) + wB * fmaxf(acc[0][ni][3], 0.f)
                     + wC * fmaxf(acc[1][ni][1], 0.f) + wD * fmaxf(acc[1][ni][3], 0.f);
            #pragma unroll
            for (int off = 4; off < 32; off <<= 1) {
                p0 += __shfl_xor_sync(0xffffffffu, p0, off);
                p1 += __shfl_xor_sync(0xffffffffu, p1, off);
            }
            if (gid == 0) {
                int c = bn + wn * 64 + ni * 8 + tig * 2;
                C[(size_t)t * ldc + c]     = p0 * ISCALE_;
                C[(size_t)t * ldc + c + 1] = p1 * ISCALE_;
            }
        }
        return;
    }

    #pragma unroll
    for (int mi = 0; mi < 2; mi++) {
        int r0 = bm + wm * 32 + mi * 16 + gid;
        int r1 = r0 + 8;
        #pragma unroll
        for (int ni = 0; ni < 8; ni++) {
            int c = bn + wn * 64 + ni * 8 + tig * 2;
            float* ap = acc[mi][ni];
            if (c < N) {
                #pragma unroll
                for (int half = 0; half < 2; half++) {
                    int r = half ? r1 : r0;
                    if (r >= M) continue;
                    float a0 = ap[half * 2], a1 = ap[half * 2 + 1];
                    float v0, v1;
                    if (EP == EP_NONE) {
                        v0 = a0; v1 = a1;
                    } else if (EP == EP_ADD) {
                        float2 cc = *(const float2*)(Cadd + (size_t)r * ldc + c);
                        v0 = a0 + cc.x; v1 = a1 + cc.y;
                    } else { // EP_SILU
                        float2 gg = *(const float2*)(Cadd + (size_t)r * ldc + c);
                        v0 = gg.x / (1.0f + expf(-gg.x)) * a0;
                        v1 = gg.y / (1.0f + expf(-gg.y)) * a1;
                    }
                    *(float2*)(C + (size_t)r * ldc + c) = make_float2(v0, v1);
                }
            }
        }
    }
}

// ---------------- pack two weight matrices contiguously ----------------
__global__ void pack2_kernel(const float* __restrict__ a, const float* __restrict__ b,
                             float* __restrict__ out, int n)
{
    int i = blockIdx.x * blockDim.x + threadIdx.x;
    if (i < n) { out[i] = a[i]; out[n + i] = b[i]; }
}

// ---------------- apply sigmoid-gate + ape on z-batched GEMM output ----------------
__global__ void gate2_kernel(const float* __restrict__ raw, const float* __restrict__ ape,
                             float* __restrict__ outF, int W)
{
    int i = blockIdx.x * blockDim.x + threadIdx.x;
    if (i >= T_ * W) return;
    int t = i / W, e = i - t * W;
    float kv = raw[i];
    float gt = raw[(size_t)T_ * W + i];
    outF[i] = kv / (1.0f + expf(-gt)) + ape[(t & 3) * W + e];
}

// ---------------- tiled transpose ----------------
__global__ void transpose_kernel(const float* __restrict__ in, float* __restrict__ out,
                                 int R, int C)
{
    __shared__ float tile[32][33];
    const float* inz = in + (size_t)blockIdx.z * R * C;
    float* outz = out + (size_t)blockIdx.z * R * C;
    int bx = blockIdx.x * 32, by = blockIdx.y * 32;
    int x = bx + threadIdx.x;
    #pragma unroll
    for (int i = 0; i < 4; i++) {
        int y = by + threadIdx.y + 8 * i;
        if (y < R && x < C) tile[threadIdx.y + 8 * i][threadIdx.x] = inz[(size_t)y * C + x];
    }
    __syncthreads();
    int x2 = by + threadIdx.x;
    #pragma unroll
    for (int i = 0; i < 4; i++) {
        int y2 = bx + threadIdx.y + 8 * i;
        if (y2 < C && x2 < R) outz[(size_t)y2 * R + x2] = tile[threadIdx.x][threadIdx.y + 8 * i];
    }
}

// ---------------- rmsnorm ----------------
__global__ void rms_kernel(const float* __restrict__ in, const float* __restrict__ w,
                           float* __restrict__ out, int D)
{
    int t = blockIdx.x;
    const float* row = in + (size_t)t * D;
    float s = 0.0f;
    for (int d = threadIdx.x; d < D; d += blockDim.x) { float v = row[d]; s += v * v; }
    s = blockReduceSum(s);
    float inv = rsqrtf(s / (float)D + EPSF);
    for (int d = threadIdx.x; d < D; d += blockDim.x)
        out[(size_t)t * D + d] = row[d] * inv * w[d];
}

// ---------------- compress ----------------
__global__ void compress_kernel(const float* __restrict__ kvf, const float* __restrict__ w,
                                float* __restrict__ out, int d)
{
    int b = blockIdx.x;
    int e = threadIdx.x;
    int W = 2 * d;
    float m = 0.0f;
    if (b > 0) {
        #pragma unroll
        for (int r = 0; r < 4; r++) m += kvf[(size_t)((b - 1) * 4 + r) * W + e];
    }
    #pragma unroll
    for (int r = 0; r < 4; r++) m += kvf[(size_t)(b * 4 + r) * W + d + e];
    m *= 0.125f;
    float ssq = blockReduceSum(m * m);
    float inv = rsqrtf(ssq / (float)d + EPSF);
    out[(size_t)b * d + e] = m * inv * w[e];
}

// ---------------- RoPE table + apply ----------------
__global__ void rope_table_kernel(float* __restrict__ tc, float* __restrict__ ts)
{
    int i = blockIdx.x * blockDim.x + threadIdx.x;
    if (i >= T_ * 32) return;
    int pos = i >> 5, f = i & 31;
    double freq = exp(-((double)(2 * f) / 64.0) * LOG_THETA);
    double ang = (double)pos * freq;
    tc[i] = (float)cos(ang);
    ts[i] = (float)sin(ang);
}

__global__ void rope_apply_kernel(float* __restrict__ x, const int* __restrict__ positions,
                                  const float* __restrict__ tc, const float* __restrict__ ts,
                                  int Hh, int Dd, int ropeOff, int compPos, int nRows)
{
    int row = blockIdx.x * 8 + (threadIdx.x >> 5);
    if (row >= nRows) return;
    int lane = threadIdx.x & 31;
    int t = row / Hh;
    int pos = compPos ? (4 * (t + 1) - 1) : positions[t];
    float c = tc[pos * 32 + lane], s = ts[pos * 32 + lane];
    float* p = x + (size_t)row * Dd + ropeOff;
    float x0 = p[2 * lane], x1 = p[2 * lane + 1];
    p[2 * lane]     = x0 * c - x1 * s;
    p[2 * lane + 1] = x0 * s + x1 * c;
}

// ---------------- exact top-256 ----------------
__global__ void topk_kernel(const float* __restrict__ isc, int* __restrict__ selidx,
                            int* __restrict__ selcnt)
{
    int t = blockIdx.x;
    __shared__ float sv[SC_];
    __shared__ int   si[SC_];
    int tid = threadIdx.x;
    int visCount = (t >= 3) ? ((t - 3) / 4 + 1) : 0;
    for (int i = tid; i < SC_; i += 256) {
        sv[i] = (i < visCount) ? isc[t * SC_ + i] : NEGF;
        si[i] = i;
    }
    __syncthreads();
    for (int k = 2; k <= SC_; k <<= 1) {
        for (int j = k >> 1; j > 0; j >>= 1) {
            for (int base = tid; base < SC_; base += 256) {
                int partner = base ^ j;
                if (partner > base) {
                    bool up = ((base & k) == 0);
                    float va = sv[base], vb = sv[partner];
                    int ia = si[base], ib = si[partner];
                    bool aFirst = (va > vb) || (va == vb && ia < ib);
                    if (up ? !aFirst : aFirst) {
                        sv[base] = vb; sv[partner] = va;
                        si[base] = ib; si[partner] = ia;
                    }
                }
            }
            __syncthreads();
        }
    }
    int cnt = min(visCount, TOPK_);
    if (tid == 0) selcnt[t] = cnt;
    for (int r = tid; r < cnt; r += 256) selidx[t * TOPK_ + r] = si[r];
}

// ---------------- head-shared flash attention ----------------
__global__ void __launch_bounds__(512) attn2_kernel(
    const float* __restrict__ q, const float* __restrict__ kvc,
    const int* __restrict__ selidx, const int* __restrict__ selcnt,
    const float* __restrict__ sink, float* __restrict__ o)
{
    __shared__ float kt[32][DH_];
    __shared__ int   ss[TOPK_];
    int t = blockIdx.x;
    int tid = threadIdx.x, lane = tid & 31, w = tid >> 5;
    int cnt = selcnt[t];
    for (int i = tid; i < cnt; i += 512) ss[i] = selidx[t * TOPK_ + i];
    __syncthreads();

    float q8[8];
    const float* qp = q + ((size_t)t * H_ + w) * DH_;
    #pragma unroll
    for (int i = 0; i < 8; i++) q8[i] = qp[lane + 32 * i];

    float m = NEGF, se = 0.0f;
    float acc[8] = {};

    for (int j0 = 0; j0 < cnt; j0 += 32) {
        int rem = min(32, cnt - j0);
        __syncthreads();
        for (int f = tid; f < 32 * 64; f += 512) {
            int r = f >> 6, c4 = f & 63;
            float4 v = make_float4(0.f, 0.f, 0.f, 0.f);
            if (r < rem) v = *(const float4*)(kvc + (size_t)ss[j0 + r] * DH_ + 4 * c4);
            *(float4*)&kt[r][4 * c4] = v;
        }
        __syncthreads();
        for (int j = 0; j < rem; j++) {
            float dot = 0.0f;
            #pragma unroll
            for (int i = 0; i < 8; i++) dot += q8[i] * kt[j][lane + 32 * i];
            #pragma unroll
            for (int off = 16; off > 0; off >>= 1)
                dot += __shfl_xor_sync(0xffffffffu, dot, off);
            float lg = dot * SCALE_;
            float mn = fmaxf(m, lg);
            float sc = expf(m - mn);
            float p  = expf(lg - mn);
            se = se * sc + p;
            #pragma unroll
            for (int i = 0; i < 8; i++)
                acc[i] = acc[i] * sc + p * kt[j][lane + 32 * i];
            m = mn;
        }
    }

    float snk = sink[w];
    float mn = fmaxf(m, snk);
    float sc = expf(m - mn);
    se = se * sc + expf(snk - mn);
    float inv = 1.0f / se;
    float* op = o + ((size_t)t * H_ + w) * DH_;
    #pragma unroll
    for (int i = 0; i < 8; i++) op[lane + 32 * i] = acc[i] * sc * inv;
}

// ---------------- host ----------------
static inline dim3 ggrid(int M, int N) { return dim3((N + BN - 1) / BN, (M + BM - 1) / BM); }

extern "C" void kernel_launch(void* const* d_in, const int* in_sizes, int n_in,
                              void* d_out, int out_size)
{
    const float* hidden      = (const float*)d_in[0];
    const int*   positions   = (const int*)  d_in[1];
    const float* ln1_w       = (const float*)d_in[2];
    const float* ln2_w       = (const float*)d_in[3];
    const float* wq_a        = (const float*)d_in[4];
    const float* q_norm_w    = (const float*)d_in[5];
    const float* wq_b        = (const float*)d_in[6];
    const float* comp_wkv    = (const float*)d_in[7];
    const float* comp_wgate  = (const float*)d_in[8];
    const float* comp_ape    = (const float*)d_in[9];
    const float* comp_norm_w = (const float*)d_in[10];
    const float* idx_wq_b    = (const float*)d_in[11];
    const float* idx_wproj   = (const float*)d_in[12];
    const float* icomp_wkv   = (const float*)d_in[13];
    const float* icomp_wgate = (const float*)d_in[14];
    const float* icomp_ape   = (const float*)d_in[15];
    const float* icomp_norm_w= (const float*)d_in[16];
    const float* attn_sink   = (const float*)d_in[17];
    const float* wo_a        = (const float*)d_in[18];
    const float* wo_b        = (const float*)d_in[19];
    const float* gate_up_w   = (const float*)d_in[20];
    const float* down_w      = (const float*)d_in[21];
    float* out = (float*)d_out;

    float *px,*pqr,*pq,*pqi,*pwkv2,*pwik2,*pkv2,*pik2,*pkvF,*pkvc,*pikF,*pki,*pkiT,*pwoaT,*piw,*pisc;
    float *po,*poa,*ph,*px2,*pact,*pRC,*pRS;
    int *pselidx,*pselcnt;
    cudaGetSymbolAddress((void**)&px, g_x);       cudaGetSymbolAddress((void**)&pqr, g_qr);
    cudaGetSymbolAddress((void**)&pq, g_q);       cudaGetSymbolAddress((void**)&pqi, g_qi);
    cudaGetSymbolAddress((void**)&pwkv2, g_wkv2); cudaGetSymbolAddress((void**)&pwik2, g_wik2);
    cudaGetSymbolAddress((void**)&pkv2, g_kv2);   cudaGetSymbolAddress((void**)&pik2, g_ik2);
    cudaGetSymbolAddress((void**)&pkvF, g_kvF);   cudaGetSymbolAddress((void**)&pkvc, g_kvc);
    cudaGetSymbolAddress((void**)&pikF, g_ikF);   cudaGetSymbolAddress((void**)&pki, g_ki);
    cudaGetSymbolAddress((void**)&pkiT, g_kiT);   cudaGetSymbolAddress((void**)&pwoaT, g_woaT);
    cudaGetSymbolAddress((void**)&piw, g_iw);     cudaGetSymbolAddress((void**)&pisc, g_isc);
    cudaGetSymbolAddress((void**)&pselidx, g_selidx); cudaGetSymbolAddress((void**)&pselcnt, g_selcnt);
    cudaGetSymbolAddress((void**)&po, g_o);       cudaGetSymbolAddress((void**)&poa, g_oa);
    cudaGetSymbolAddress((void**)&ph, g_h);       cudaGetSymbolAddress((void**)&px2, g_x2);
    cudaGetSymbolAddress((void**)&pact, g_act);   cudaGetSymbolAddress((void**)&pRC, g_ropeC);
    cudaGetSymbolAddress((void**)&pRS, g_ropeS);

    cudaFuncSetAttribute(tgemm_kernel<EP_NONE>,  cudaFuncAttributeMaxDynamicSharedMemorySize, SMEM_PIPE_BYTES);
    cudaFuncSetAttribute(tgemm_kernel<EP_ADD>,   cudaFuncAttributeMaxDynamicSharedMemorySize, SMEM_PIPE_BYTES);
    cudaFuncSetAttribute(tgemm_kernel<EP_SILU>,  cudaFuncAttributeMaxDynamicSharedMemorySize, SMEM_PIPE_BYTES);
    cudaFuncSetAttribute(tgemm_kernel<EP_RFUSE>, cudaFuncAttributeMaxDynamicSharedMemorySize, SMEM_PIPE_BYTES);

    // 0) rope table + weight packs
    rope_table_kernel<<<(T_ * 32 + 255) / 256, 256>>>(pRC, pRS);
    pack2_kernel<<<(DIM_ * 2 * DH_ + 255) / 256, 256>>>(comp_wkv, comp_wgate, pwkv2, DIM_ * 2 * DH_);
    pack2_kernel<<<(DIM_ * 2 * DI_ + 255) / 256, 256>>>(icomp_wkv, icomp_wgate, pwik2, DIM_ * 2 * DI_);

    // 1) x = rms(hidden, ln1)
    rms_kernel<<<T_, 256>>>(hidden, ln1_w, px, DIM_);

    // 2) qr = rms(x @ wq_a, q_norm)
    tgemm_kernel<EP_NONE><<<ggrid(T_, QL_), 256, SMEM_PIPE_BYTES>>>(T_, QL_, DIM_, px, DIM_, 0, wq_a, QL_, 0, nullptr, pqr, QL_, 0);
    rms_kernel<<<T_, 256>>>(pqr, q_norm_w, pqr, QL_);

    // 3) q / qi projections + rope
    tgemm_kernel<EP_NONE><<<ggrid(T_, H_*DH_), 256, SMEM_PIPE_BYTES>>>(T_, H_*DH_, QL_, pqr, QL_, 0, wq_b, H_*DH_, 0, nullptr, pq, H_*DH_, 0);
    tgemm_kernel<EP_NONE><<<ggrid(T_, HI_*DI_), 256, SMEM_PIPE_BYTES>>>(T_, HI_*DI_, QL_, pqr, QL_, 0, idx_wq_b, HI_*DI_, 0, nullptr, pqi, HI_*DI_, 0);
    rope_apply_kernel<<<T_ * H_ / 8,  256>>>(pq,  positions, pRC, pRS, H_,  DH_, NOPE_,  0, T_ * H_);
    rope_apply_kernel<<<T_ * HI_ / 8, 256>>>(pqi, positions, pRC, pRS, HI_, DI_, INOPE_, 0, T_ * HI_);

    // 4) kvc: z=2 batched {wkv, wgate} GEMM, then elementwise gate+ape
    {
        dim3 g = ggrid(T_, 2*DH_); g.z = 2;
        tgemm_kernel<EP_NONE><<<g, 256, SMEM_PIPE_BYTES>>>(
            T_, 2*DH_, DIM_, px, DIM_, 0, pwkv2, 2*DH_, DIM_ * 2*DH_,
            nullptr, pkv2, 2*DH_, T_ * 2*DH_);
    }
    gate2_kernel<<<(T_ * 2*DH_ + 255) / 256, 256>>>(pkv2, comp_ape, pkvF, 2*DH_);
    compress_kernel<<<SC_, DH_>>>(pkvF, comp_norm_w, pkvc, DH_);
    rope_apply_kernel<<<SC_ / 8, 256>>>(pkvc, positions, pRC, pRS, 1, DH_, NOPE_, 1, SC_);

    // 5) ki: z=2 batched {iwkv, iwgate} GEMM + gate + compress + rope + transpose
    {
        dim3 g = ggrid(T_, 2*DI_); g.z = 2;
        tgemm_kernel<EP_NONE><<<g, 256, SMEM_PIPE_BYTES>>>(
            T_, 2*DI_, DIM_, px, DIM_, 0, pwik2, 2*DI_, DIM_ * 2*DI_,
            nullptr, pik2, 2*DI_, T_ * 2*DI_);
    }
    gate2_kernel<<<(T_ * 2*DI_ + 255) / 256, 256>>>(pik2, icomp_ape, pikF, 2*DI_);
    compress_kernel<<<SC_, DI_>>>(pikF, icomp_norm_w, pki, DI_);
    rope_apply_kernel<<<SC_ / 8, 256>>>(pki, positions, pRC, pRS, 1, DI_, INOPE_, 1, SC_);
    transpose_kernel<<<dim3(DI_/32, SC_/32, 1), dim3(32, 8)>>>(pki, pkiT, SC_, DI_);

    // 6) iw
    tgemm_kernel<EP_NONE><<<ggrid(T_, HI_), 256, SMEM_PIPE_BYTES>>>(T_, HI_, DIM_, px, DIM_, 0, idx_wproj, HI_, 0, nullptr, piw, HI_, 0);

    // 7) R GEMM with fused weighted-relu head reduction -> isc
    tgemm_kernel<EP_RFUSE><<<ggrid(T_*HI_, SC_), 256, SMEM_PIPE_BYTES>>>(T_*HI_, SC_, DI_, pqi, DI_, 0, pkiT, SC_, 0, piw, pisc, SC_, 0);

    // 8) top-256 + attention
    topk_kernel<<<T_, 256>>>(pisc, pselidx, pselcnt);
    attn2_kernel<<<T_, 512>>>(pq, pkvc, pselidx, pselcnt, attn_sink, po);

    // 9) output proj: transpose wo_a, z-batched GEMM, then wo_b (+residual)
    transpose_kernel<<<dim3(FG_/32, OLORA_/32, G_), dim3(32, 8)>>>(wo_a, pwoaT, OLORA_, FG_);
    {
        dim3 g = ggrid(T_, OLORA_); g.z = G_;
        tgemm_kernel<EP_NONE><<<g, 256, SMEM_PIPE_BYTES>>>(
            T_, OLORA_, FG_, po, H_*DH_, FG_, pwoaT, OLORA_, FG_*OLORA_,
            nullptr, poa, G_*OLORA_, OLORA_);
    }
    tgemm_kernel<EP_ADD><<<ggrid(T_, DIM_), 256, SMEM_PIPE_BYTES>>>(T_, DIM_, G_*OLORA_, poa, G_*OLORA_, 0, wo_b, DIM_, 0, hidden, ph, DIM_, 0);

    // 10) MLP: gate GEMM -> act; up GEMM fused silu-mul; down GEMM + residual
    rms_kernel<<<T_, 256>>>(ph, ln2_w, px2, DIM_);
    tgemm_kernel<EP_NONE><<<ggrid(T_, II_), 256, SMEM_PIPE_BYTES>>>(T_, II_, DIM_, px2, DIM_, 0, gate_up_w, 2*II_, 0, nullptr, pact, II_, 0);
    tgemm_kernel<EP_SILU><<<ggrid(T_, II_), 256, SMEM_PIPE_BYTES>>>(T_, II_, DIM_, px2, DIM_, 0, gate_up_w + II_, 2*II_, 0, pact, pact, II_, 0);
    tgemm_kernel<EP_ADD><<<ggrid(T_, DIM_), 256, SMEM_PIPE_BYTES>>>(T_, DIM_, II_, pact, II_, 0, down_w, DIM_, 0, ph, out, DIM_, 0);
}

// round 14
// speedup vs baseline: 1.6153x; 1.0309x over previous
#include <cuda_runtime.h>
#include <math.h>
#include <stdint.h>

#define T_    2048
#define DIM_  2048
#define QL_   1536
#define H_    16
#define DH_   256
#define NOPE_ 192
#define HI_   32
#define DI_   128
#define INOPE_ 64
#define SC_   512
#define TOPK_ 256
#define II_   8192
#define G_    4
#define OLORA_ 512
#define FG_   1024
#define NCAT_ 1568
#define EPSF  1e-6f
#define NEGF  (-1e30f)
#define SCALE_   0.0625f
#define ISCALE_  0.08838834764831845f
#define LOG_THETA 11.98292909421596506

// ---------------- scratch ----------------
__device__ float g_x   [T_ * DIM_];
__device__ float g_qr  [T_ * QL_];
__device__ float g_q   [T_ * H_ * DH_];
__device__ float g_qi  [T_ * HI_ * DI_];
__device__ float g_wcat[DIM_ * NCAT_];
__device__ float g_cat [T_ * NCAT_];
__device__ float g_kvF [T_ * 2 * DH_];
__device__ float g_kvc [SC_ * DH_];
__device__ float g_ikF [T_ * 2 * DI_];
__device__ float g_ki  [SC_ * DI_];
__device__ float g_kiT [DI_ * SC_];
__device__ float g_woaT[G_ * FG_ * OLORA_];
__device__ float g_iw  [T_ * HI_];
__device__ float g_isc [T_ * SC_];
__device__ int   g_selidx[T_ * TOPK_];
__device__ int   g_selcnt[T_];
__device__ float g_o   [T_ * H_ * DH_];
__device__ float g_oa  [T_ * G_ * OLORA_];
__device__ float g_h   [T_ * DIM_];
__device__ float g_x2  [T_ * DIM_];
__device__ float g_act [(size_t)T_ * II_];
__device__ float g_ropeC[T_ * 32];
__device__ float g_ropeS[T_ * 32];

// ---------------- reductions ----------------
__device__ __forceinline__ float blockReduceSum(float v) {
    __shared__ float sh[32];
    int lane = threadIdx.x & 31, wid = threadIdx.x >> 5;
    #pragma unroll
    for (int o = 16; o > 0; o >>= 1) v += __shfl_xor_sync(0xffffffffu, v, o);
    if (lane == 0) sh[wid] = v;
    __syncthreads();
    int nw = (blockDim.x + 31) >> 5;
    if (wid == 0) {
        float r = (lane < nw) ? sh[lane] : 0.0f;
        #pragma unroll
        for (int o = 16; o > 0; o >>= 1) r += __shfl_xor_sync(0xffffffffu, r, o);
        if (lane == 0) sh[0] = r;
    }
    __syncthreads();
    float res = sh[0];
    __syncthreads();
    return res;
}

// ---------------- tf32 / cp.async helpers ----------------
__device__ __forceinline__ uint32_t f2tf32(float x) {
    uint32_t r;
    asm("cvt.rna.tf32.f32 %0, %1;" : "=r"(r) : "f"(x));
    return r;
}

__device__ __forceinline__ void mma_tf32(float* d, const uint32_t* a, const uint32_t* b) {
    asm volatile(
        "mma.sync.aligned.m16n8k8.row.col.f32.tf32.tf32.f32 "
        "{%0,%1,%2,%3}, {%4,%5,%6,%7}, {%8,%9}, {%0,%1,%2,%3};"
        : "+f"(d[0]), "+f"(d[1]), "+f"(d[2]), "+f"(d[3])
        : "r"(a[0]), "r"(a[1]), "r"(a[2]), "r"(a[3]), "r"(b[0]), "r"(b[1]));
}

__device__ __forceinline__ void cp16(float* smem_dst, const float* gsrc, bool pred) {
    uint32_t s = (uint32_t)__cvta_generic_to_shared(smem_dst);
    int sz = pred ? 16 : 0;
    asm volatile("cp.async.cg.shared.global [%0], [%1], 16, %2;\n"
                 :: "r"(s), "l"(gsrc), "r"(sz));
}
#define CP_COMMIT() asm volatile("cp.async.commit_group;" ::: "memory")
#define CP_WAIT1()  asm volatile("cp.async.wait_group 1;" ::: "memory")
#define CP_WAIT0()  asm volatile("cp.async.wait_group 0;" ::: "memory")

// ---------------- epilogue modes ----------------
#define EP_NONE  0
#define EP_ADD   1
#define EP_SILU  3
#define EP_RFUSE 4

// ---------------- tensor-core TF32 GEMM, 128x128x32, 3-stage cp.async +
// register double-buffered fragments ----------------
#define BM 128
#define BN 128
#define BK 32
#define AS_S 36
#define BS_S 136
#define A_TILE (BM * AS_S)
#define B_TILE (BK * BS_S)
#define STAGE_F (A_TILE + B_TILE)
#define SMEM_PIPE_BYTES (STAGE_F * 3 * 4)   // 107520

template<int EP>
__global__ void __launch_bounds__(256, 2) tgemm_kernel(
    int M, int N, int K,
    const float* __restrict__ A, int lda, int aZ,
    const float* __restrict__ B, int ldb, int bZ,
    const float* __restrict__ Cadd,
    float* __restrict__ C, int ldc, int cZ)
{
    extern __shared__ float smem[];
    const int bm = blockIdx.y * BM;
    const int bn = blockIdx.x * BN;
    A += (size_t)blockIdx.z * aZ;
    B += (size_t)blockIdx.z * bZ;
    C += (size_t)blockIdx.z * cZ;
    const int tid = threadIdx.x;
    const int lane = tid & 31;
    const int wid = tid >> 5;
    const int wm = wid & 3;
    const int wn = wid >> 2;
    const int gid = lane >> 2;
    const int tig = lane & 3;

    float acc[2][8][4];
    #pragma unroll
    for (int mi = 0; mi < 2; mi++)
        #pragma unroll
        for (int ni = 0; ni < 8; ni++)
            #pragma unroll
            for (int r = 0; r < 4; r++) acc[mi][ni][r] = 0.0f;

    const int nIter = K / BK;

    auto issue = [&](int st, int k0) {
        float* sA = smem + st * STAGE_F;
        float* sB = sA + A_TILE;
        #pragma unroll
        for (int i = 0; i < 4; i++) {
            int f = tid + i * 256;
            int r = f >> 3, q = f & 7;
            int gr = bm + r;
            cp16(&sA[r * AS_S + 4 * q], A + (size_t)gr * lda + k0 + 4 * q, gr < M);
        }
        #pragma unroll
        for (int i = 0; i < 4; i++) {
            int f = tid + i * 256;
            int k = f >> 5, q = f & 31;
            int gc = bn + 4 * q;
            cp16(&sB[k * BS_S + 4 * q], B + (size_t)(k0 + k) * ldb + gc, gc < N);
        }
    };

    auto load_frags = [&](const float* sA, const float* sB, int kb,
                          uint32_t af[2][4], uint32_t bf[8][2]) {
        #pragma unroll
        for (int mi = 0; mi < 2; mi++) {
            int r = wm * 32 + mi * 16 + gid;
            af[mi][0] = f2tf32(sA[r * AS_S + kb + tig]);
            af[mi][1] = f2tf32(sA[(r + 8) * AS_S + kb + tig]);
            af[mi][2] = f2tf32(sA[r * AS_S + kb + tig + 4]);
            af[mi][3] = f2tf32(sA[(r + 8) * AS_S + kb + tig + 4]);
        }
        #pragma unroll
        for (int ni = 0; ni < 8; ni++) {
            int c = wn * 64 + ni * 8 + gid;
            bf[ni][0] = f2tf32(sB[(kb + tig) * BS_S + c]);
            bf[ni][1] = f2tf32(sB[(kb + tig + 4) * BS_S + c]);
        }
    };

    auto frag_compute = [&](int st) {
        const float* sA = smem + st * STAGE_F;
        const float* sB = sA + A_TILE;
        uint32_t af[2][2][4];
        uint32_t bf[2][8][2];
        load_frags(sA, sB, 0, af[0], bf[0]);
        #pragma unroll
        for (int kk = 0; kk < 4; kk++) {
            if (kk < 3)
                load_frags(sA, sB, (kk + 1) * 8, af[(kk + 1) & 1], bf[(kk + 1) & 1]);
            #pragma unroll
            for (int mi = 0; mi < 2; mi++)
                #pragma unroll
                for (int ni = 0; ni < 8; ni++)
                    mma_tf32(acc[mi][ni], af[kk & 1][mi], bf[kk & 1][ni]);
        }
    };

    issue(0, 0);
    CP_COMMIT();
    if (nIter > 1) { issue(1, BK); CP_COMMIT(); }

    int st = 0;
    for (int it = 0; it < nIter; ++it) {
        if (it + 1 < nIter) CP_WAIT1(); else CP_WAIT0();
        __syncthreads();
        if (it + 2 < nIter) {
            int st2 = st + 2; if (st2 >= 3) st2 -= 3;
            issue(st2, (it + 2) * BK);
            CP_COMMIT();
        }
        frag_compute(st);
        if (++st == 3) st = 0;
    }

    // ---------------- epilogues ----------------
    if (EP == EP_RFUSE) {
        int t = bm / HI_ + wm;
        float wA = Cadd[t * HI_ + gid];
        float wB = Cadd[t * HI_ + gid + 8];
        float wC = Cadd[t * HI_ + gid + 16];
        float wD = Cadd[t * HI_ + gid + 24];
        #pragma unroll
        for (int ni = 0; ni < 8; ni++) {
            float p0 = wA * fmaxf(acc[0][ni][0], 0.f) + wB * fmaxf(acc[0][ni][2], 0.f)
                     + wC * fmaxf(acc[1][ni][0], 0.f) + wD * fmaxf(acc[1][ni][2], 0.f);
            float p1 = wA * fmaxf(acc[0][ni][1], 0.f) + wB * fmaxf(acc[0][ni][3], 0.f)
                     + wC * fmaxf(acc[1][ni][1], 0.f) + wD * fmaxf(acc[1][ni][3], 0.f);
            #pragma unroll
            for (int off = 4; off < 32; off <<= 1) {
                p0 += __shfl_xor_sync(0xffffffffu, p0, off);
                p1 += __shfl_xor_sync(0xffffffffu, p1, off);
            }
            if (gid == 0) {
                int c = bn + wn * 64 + ni * 8 + tig * 2;
                C[(size_t)t * ldc + c]     = p0 * ISCALE_;
                C[(size_t)t * ldc + c + 1] = p1 * ISCALE_;
            }
        }
        return;
    }

    #pragma unroll
    for (int mi = 0; mi < 2; mi++) {
        int r0 = bm + wm * 32 + mi * 16 + gid;
        int r1 = r0 + 8;
        #pragma unroll
        for (int ni = 0; ni < 8; ni++) {
            int c = bn + wn * 64 + ni * 8 + tig * 2;
            float* ap = acc[mi][ni];
            if (c < N) {
                #pragma unroll
                for (int half = 0; half < 2; half++) {
                    int r = half ? r1 : r0;
                    if (r >= M) continue;
                    float a0 = ap[half * 2], a1 = ap[half * 2 + 1];
                    float v0, v1;
                    if (EP == EP_NONE) {
                        v0 = a0; v1 = a1;
                    } else if (EP == EP_ADD) {
                        float2 cc = *(const float2*)(Cadd + (size_t)r * ldc + c);
                        v0 = a0 + cc.x; v1 = a1 + cc.y;
                    } else { // EP_SILU
                        float2 gg = *(const float2*)(Cadd + (size_t)r * ldc + c);
                        v0 = gg.x / (1.0f + expf(-gg.x)) * a0;
                        v1 = gg.y / (1.0f + expf(-gg.y)) * a1;
                    }
                    *(float2*)(C + (size_t)r * ldc + c) = make_float2(v0, v1);
                }
            }
        }
    }
}

// ---------------- concat 5 projection weights column-wise ----------------
__global__ void concat_kernel(const float* __restrict__ wkv, const float* __restrict__ wg,
                              const float* __restrict__ iwkv, const float* __restrict__ iwg,
                              const float* __restrict__ iwp, float* __restrict__ out)
{
    int k = blockIdx.x;
    float* o = out + (size_t)k * NCAT_;
    for (int j = threadIdx.x; j < 512; j += 256) o[j]        = wkv [k * 512 + j];
    for (int j = threadIdx.x; j < 512; j += 256) o[512 + j]  = wg  [k * 512 + j];
    for (int j = threadIdx.x; j < 256; j += 256) o[1024 + j] = iwkv[k * 256 + j];
    for (int j = threadIdx.x; j < 256; j += 256) o[1280 + j] = iwg [k * 256 + j];
    if (threadIdx.x < 32) o[1536 + threadIdx.x] = iwp[k * 32 + threadIdx.x];
}

// ---------------- fused gate/split of the concat GEMM output ----------------
__global__ void fusedgate_kernel(const float* __restrict__ cat,
                                 const float* __restrict__ ape_kv, const float* __restrict__ ape_ik,
                                 float* __restrict__ kvF, float* __restrict__ ikF,
                                 float* __restrict__ iw)
{
    int t = blockIdx.x;
    const float* row = cat + (size_t)t * NCAT_;
    int a = t & 3;
    for (int e = threadIdx.x; e < 512; e += 256)
        kvF[t * 512 + e] = row[e] / (1.0f + expf(-row[512 + e])) + ape_kv[a * 512 + e];
    for (int e = threadIdx.x; e < 256; e += 256)
        ikF[t * 256 + e] = row[1024 + e] / (1.0f + expf(-row[1280 + e])) + ape_ik[a * 256 + e];
    if (threadIdx.x < 32) iw[t * 32 + threadIdx.x] = row[1536 + threadIdx.x];
}

// ---------------- tiled transpose ----------------
__global__ void transpose_kernel(const float* __restrict__ in, float* __restrict__ out,
                                 int R, int C)
{
    __shared__ float tile[32][33];
    const float* inz = in + (size_t)blockIdx.z * R * C;
    float* outz = out + (size_t)blockIdx.z * R * C;
    int bx = blockIdx.x * 32, by = blockIdx.y * 32;
    int x = bx + threadIdx.x;
    #pragma unroll
    for (int i = 0; i < 4; i++) {
        int y = by + threadIdx.y + 8 * i;
        if (y < R && x < C) tile[threadIdx.y + 8 * i][threadIdx.x] = inz[(size_t)y * C + x];
    }
    __syncthreads();
    int x2 = by + threadIdx.x;
    #pragma unroll
    for (int i = 0; i < 4; i++) {
        int y2 = bx + threadIdx.y + 8 * i;
        if (y2 < C && x2 < R) outz[(size_t)y2 * R + x2] = tile[threadIdx.x][threadIdx.y + 8 * i];
    }
}

// ---------------- rmsnorm ----------------
__global__ void rms_kernel(const float* __restrict__ in, const float* __restrict__ w,
                           float* __restrict__ out, int D)
{
    int t = blockIdx.x;
    const float* row = in + (size_t)t * D;
    float s = 0.0f;
    for (int d = threadIdx.x; d < D; d += blockDim.x) { float v = row[d]; s += v * v; }
    s = blockReduceSum(s);
    float inv = rsqrtf(s / (float)D + EPSF);
    for (int d = threadIdx.x; d < D; d += blockDim.x)
        out[(size_t)t * D + d] = row[d] * inv * w[d];
}

// ---------------- compress ----------------
__global__ void compress_kernel(const float* __restrict__ kvf, const float* __restrict__ w,
                                float* __restrict__ out, int d)
{
    int b = blockIdx.x;
    int e = threadIdx.x;
    int W = 2 * d;
    float m = 0.0f;
    if (b > 0) {
        #pragma unroll
        for (int r = 0; r < 4; r++) m += kvf[(size_t)((b - 1) * 4 + r) * W + e];
    }
    #pragma unroll
    for (int r = 0; r < 4; r++) m += kvf[(size_t)(b * 4 + r) * W + d + e];
    m *= 0.125f;
    float ssq = blockReduceSum(m * m);
    float inv = rsqrtf(ssq / (float)d + EPSF);
    out[(size_t)b * d + e] = m * inv * w[e];
}

// ---------------- RoPE table + apply ----------------
__global__ void rope_table_kernel(float* __restrict__ tc, float* __restrict__ ts)
{
    int i = blockIdx.x * blockDim.x + threadIdx.x;
    if (i >= T_ * 32) return;
    int pos = i >> 5, f = i & 31;
    double freq = exp(-((double)(2 * f) / 64.0) * LOG_THETA);
    double ang = (double)pos * freq;
    tc[i] = (float)cos(ang);
    ts[i] = (float)sin(ang);
}

__global__ void rope_apply_kernel(float* __restrict__ x, const int* __restrict__ positions,
                                  const float* __restrict__ tc, const float* __restrict__ ts,
                                  int Hh, int Dd, int ropeOff, int compPos, int nRows)
{
    int row = blockIdx.x * 8 + (threadIdx.x >> 5);
    if (row >= nRows) return;
    int lane = threadIdx.x & 31;
    int t = row / Hh;
    int pos = compPos ? (4 * (t + 1) - 1) : positions[t];
    float c = tc[pos * 32 + lane], s = ts[pos * 32 + lane];
    float* p = x + (size_t)row * Dd + ropeOff;
    float x0 = p[2 * lane], x1 = p[2 * lane + 1];
    p[2 * lane]     = x0 * c - x1 * s;
    p[2 * lane + 1] = x0 * s + x1 * c;
}

// ---------------- exact top-256 ----------------
__global__ void topk_kernel(const float* __restrict__ isc, int* __restrict__ selidx,
                            int* __restrict__ selcnt)
{
    int t = blockIdx.x;
    __shared__ float sv[SC_];
    __shared__ int   si[SC_];
    int tid = threadIdx.x;
    int visCount = (t >= 3) ? ((t - 3) / 4 + 1) : 0;
    for (int i = tid; i < SC_; i += 256) {
        sv[i] = (i < visCount) ? isc[t * SC_ + i] : NEGF;
        si[i] = i;
    }
    __syncthreads();
    for (int k = 2; k <= SC_; k <<= 1) {
        for (int j = k >> 1; j > 0; j >>= 1) {
            for (int base = tid; base < SC_; base += 256) {
                int partner = base ^ j;
                if (partner > base) {
                    bool up = ((base & k) == 0);
                    float va = sv[base], vb = sv[partner];
                    int ia = si[base], ib = si[partner];
                    bool aFirst = (va > vb) || (va == vb && ia < ib);
                    if (up ? !aFirst : aFirst) {
                        sv[base] = vb; sv[partner] = va;
                        si[base] = ib; si[partner] = ia;
                    }
                }
            }
            __syncthreads();
        }
    }
    int cnt = min(visCount, TOPK_);
    if (tid == 0) selcnt[t] = cnt;
    for (int r = tid; r < cnt; r += 256) selidx[t * TOPK_ + r] = si[r];
}

// ---------------- head-shared flash attention ----------------
__global__ void __launch_bounds__(512) attn2_kernel(
    const float* __restrict__ q, const float* __restrict__ kvc,
    const int* __restrict__ selidx, const int* __restrict__ selcnt,
    const float* __restrict__ sink, float* __restrict__ o)
{
    __shared__ float kt[32][DH_];
    __shared__ int   ss[TOPK_];
    int t = blockIdx.x;
    int tid = threadIdx.x, lane = tid & 31, w = tid >> 5;
    int cnt = selcnt[t];
    for (int i = tid; i < cnt; i += 512) ss[i] = selidx[t * TOPK_ + i];
    __syncthreads();

    float q8[8];
    const float* qp = q + ((size_t)t * H_ + w) * DH_;
    #pragma unroll
    for (int i = 0; i < 8; i++) q8[i] = qp[lane + 32 * i];

    float m = NEGF, se = 0.0f;
    float acc[8] = {};

    for (int j0 = 0; j0 < cnt; j0 += 32) {
        int rem = min(32, cnt - j0);
        __syncthreads();
        for (int f = tid; f < 32 * 64; f += 512) {
            int r = f >> 6, c4 = f & 63;
            float4 v = make_float4(0.f, 0.f, 0.f, 0.f);
            if (r < rem) v = *(const float4*)(kvc + (size_t)ss[j0 + r] * DH_ + 4 * c4);
            *(float4*)&kt[r][4 * c4] = v;
        }
        __syncthreads();
        for (int j = 0; j < rem; j++) {
            float dot = 0.0f;
            #pragma unroll
            for (int i = 0; i < 8; i++) dot += q8[i] * kt[j][lane + 32 * i];
            #pragma unroll
            for (int off = 16; off > 0; off >>= 1)
                dot += __shfl_xor_sync(0xffffffffu, dot, off);
            float lg = dot * SCALE_;
            float mn = fmaxf(m, lg);
            float sc = expf(m - mn);
            float p  = expf(lg - mn);
            se = se * sc + p;
            #pragma unroll
            for (int i = 0; i < 8; i++)
                acc[i] = acc[i] * sc + p * kt[j][lane + 32 * i];
            m = mn;
        }
    }

    float snk = sink[w];
    float mn = fmaxf(m, snk);
    float sc = expf(m - mn);
    se = se * sc + expf(snk - mn);
    float inv = 1.0f / se;
    float* op = o + ((size_t)t * H_ + w) * DH_;
    #pragma unroll
    for (int i = 0; i < 8; i++) op[lane + 32 * i] = acc[i] * sc * inv;
}

// ---------------- host ----------------
static inline dim3 ggrid(int M, int N) { return dim3((N + BN - 1) / BN, (M + BM - 1) / BM); }

extern "C" void kernel_launch(void* const* d_in, const int* in_sizes, int n_in,
                              void* d_out, int out_size)
{
    const float* hidden      = (const float*)d_in[0];
    const int*   positions   = (const int*)  d_in[1];
    const float* ln1_w       = (const float*)d_in[2];
    const float* ln2_w       = (const float*)d_in[3];
    const float* wq_a        = (const float*)d_in[4];
    const float* q_norm_w    = (const float*)d_in[5];
    const float* wq_b        = (const float*)d_in[6];
    const float* comp_wkv    = (const float*)d_in[7];
    const float* comp_wgate  = (const float*)d_in[8];
    const float* comp_ape    = (const float*)d_in[9];
    const float* comp_norm_w = (const float*)d_in[10];
    const float* idx_wq_b    = (const float*)d_in[11];
    const float* idx_wproj   = (const float*)d_in[12];
    const float* icomp_wkv   = (const float*)d_in[13];
    const float* icomp_wgate = (const float*)d_in[14];
    const float* icomp_ape   = (const float*)d_in[15];
    const float* icomp_norm_w= (const float*)d_in[16];
    const float* attn_sink   = (const float*)d_in[17];
    const float* wo_a        = (const float*)d_in[18];
    const float* wo_b        = (const float*)d_in[19];
    const float* gate_up_w   = (const float*)d_in[20];
    const float* down_w      = (const float*)d_in[21];
    float* out = (float*)d_out;

    float *px,*pqr,*pq,*pqi,*pwcat,*pcat,*pkvF,*pkvc,*pikF,*pki,*pkiT,*pwoaT,*piw,*pisc;
    float *po,*poa,*ph,*px2,*pact,*pRC,*pRS;
    int *pselidx,*pselcnt;
    cudaGetSymbolAddress((void**)&px, g_x);       cudaGetSymbolAddress((void**)&pqr, g_qr);
    cudaGetSymbolAddress((void**)&pq, g_q);       cudaGetSymbolAddress((void**)&pqi, g_qi);
    cudaGetSymbolAddress((void**)&pwcat, g_wcat); cudaGetSymbolAddress((void**)&pcat, g_cat);
    cudaGetSymbolAddress((void**)&pkvF, g_kvF);   cudaGetSymbolAddress((void**)&pkvc, g_kvc);
    cudaGetSymbolAddress((void**)&pikF, g_ikF);   cudaGetSymbolAddress((void**)&pki, g_ki);
    cudaGetSymbolAddress((void**)&pkiT, g_kiT);   cudaGetSymbolAddress((void**)&pwoaT, g_woaT);
    cudaGetSymbolAddress((void**)&piw, g_iw);     cudaGetSymbolAddress((void**)&pisc, g_isc);
    cudaGetSymbolAddress((void**)&pselidx, g_selidx); cudaGetSymbolAddress((void**)&pselcnt, g_selcnt);
    cudaGetSymbolAddress((void**)&po, g_o);       cudaGetSymbolAddress((void**)&poa, g_oa);
    cudaGetSymbolAddress((void**)&ph, g_h);       cudaGetSymbolAddress((void**)&px2, g_x2);
    cudaGetSymbolAddress((void**)&pact, g_act);   cudaGetSymbolAddress((void**)&pRC, g_ropeC);
    cudaGetSymbolAddress((void**)&pRS, g_ropeS);

    cudaFuncSetAttribute(tgemm_kernel<EP_NONE>,  cudaFuncAttributeMaxDynamicSharedMemorySize, SMEM_PIPE_BYTES);
    cudaFuncSetAttribute(tgemm_kernel<EP_ADD>,   cudaFuncAttributeMaxDynamicSharedMemorySize, SMEM_PIPE_BYTES);
    cudaFuncSetAttribute(tgemm_kernel<EP_SILU>,  cudaFuncAttributeMaxDynamicSharedMemorySize, SMEM_PIPE_BYTES);
    cudaFuncSetAttribute(tgemm_kernel<EP_RFUSE>, cudaFuncAttributeMaxDynamicSharedMemorySize, SMEM_PIPE_BYTES);

    // 0) rope table + weight concat
    rope_table_kernel<<<(T_ * 32 + 255) / 256, 256>>>(pRC, pRS);
    concat_kernel<<<DIM_, 256>>>(comp_wkv, comp_wgate, icomp_wkv, icomp_wgate, idx_wproj, pwcat);

    // 1) x = rms(hidden, ln1)
    rms_kernel<<<T_, 256>>>(hidden, ln1_w, px, DIM_);

    // 2) qr = rms(x @ wq_a, q_norm)
    tgemm_kernel<EP_NONE><<<ggrid(T_, QL_), 256, SMEM_PIPE_BYTES>>>(T_, QL_, DIM_, px, DIM_, 0, wq_a, QL_, 0, nullptr, pqr, QL_, 0);
    rms_kernel<<<T_, 256>>>(pqr, q_norm_w, pqr, QL_);

    // 3) q / qi projections + rope
    tgemm_kernel<EP_NONE><<<ggrid(T_, H_*DH_), 256, SMEM_PIPE_BYTES>>>(T_, H_*DH_, QL_, pqr, QL_, 0, wq_b, H_*DH_, 0, nullptr, pq, H_*DH_, 0);
    tgemm_kernel<EP_NONE><<<ggrid(T_, HI_*DI_), 256, SMEM_PIPE_BYTES>>>(T_, HI_*DI_, QL_, pqr, QL_, 0, idx_wq_b, HI_*DI_, 0, nullptr, pqi, HI_*DI_, 0);
    rope_apply_kernel<<<T_ * H_ / 8,  256>>>(pq,  positions, pRC, pRS, H_,  DH_, NOPE_,  0, T_ * H_);
    rope_apply_kernel<<<T_ * HI_ / 8, 256>>>(pqi, positions, pRC, pRS, HI_, DI_, INOPE_, 0, T_ * HI_);

    // 4) ONE fused projection GEMM (kv | kv-gate | ik | ik-gate | iw), then gate/split
    tgemm_kernel<EP_NONE><<<ggrid(T_, NCAT_), 256, SMEM_PIPE_BYTES>>>(T_, NCAT_, DIM_, px, DIM_, 0, pwcat, NCAT_, 0, nullptr, pcat, NCAT_, 0);
    fusedgate_kernel<<<T_, 256>>>(pcat, comp_ape, icomp_ape, pkvF, pikF, piw);

    // 5) compress + rope (kvc, ki) + ki transpose
    compress_kernel<<<SC_, DH_>>>(pkvF, comp_norm_w, pkvc, DH_);
    rope_apply_kernel<<<SC_ / 8, 256>>>(pkvc, positions, pRC, pRS, 1, DH_, NOPE_, 1, SC_);
    compress_kernel<<<SC_, DI_>>>(pikF, icomp_norm_w, pki, DI_);
    rope_apply_kernel<<<SC_ / 8, 256>>>(pki, positions, pRC, pRS, 1, DI_, INOPE_, 1, SC_);
    transpose_kernel<<<dim3(DI_/32, SC_/32, 1), dim3(32, 8)>>>(pki, pkiT, SC_, DI_);

    // 6) R GEMM with fused weighted-relu head reduction -> isc
    tgemm_kernel<EP_RFUSE><<<ggrid(T_*HI_, SC_), 256, SMEM_PIPE_BYTES>>>(T_*HI_, SC_, DI_, pqi, DI_, 0, pkiT, SC_, 0, piw, pisc, SC_, 0);

    // 7) top-256 + attention
    topk_kernel<<<T_, 256>>>(pisc, pselidx, pselcnt);
    attn2_kernel<<<T_, 512>>>(pq, pkvc, pselidx, pselcnt, attn_sink, po);

    // 8) output proj: transpose wo_a, z-batched GEMM, then wo_b (+residual)
    transpose_kernel<<<dim3(FG_/32, OLORA_/32, G_), dim3(32, 8)>>>(wo_a, pwoaT, OLORA_, FG_);
    {
        dim3 g = ggrid(T_, OLORA_); g.z = G_;
        tgemm_kernel<EP_NONE><<<g, 256, SMEM_PIPE_BYTES>>>(
            T_, OLORA_, FG_, po, H_*DH_, FG_, pwoaT, OLORA_, FG_*OLORA_,
            nullptr, poa, G_*OLORA_, OLORA_);
    }
    tgemm_kernel<EP_ADD><<<ggrid(T_, DIM_), 256, SMEM_PIPE_BYTES>>>(T_, DIM_, G_*OLORA_, poa, G_*OLORA_, 0, wo_b, DIM_, 0, hidden, ph, DIM_, 0);

    // 9) MLP: gate GEMM -> act; up GEMM fused silu-mul; down GEMM + residual
    rms_kernel<<<T_, 256>>>(ph, ln2_w, px2, DIM_);
    tgemm_kernel<EP_NONE><<<ggrid(T_, II_), 256, SMEM_PIPE_BYTES>>>(T_, II_, DIM_, px2, DIM_, 0, gate_up_w, 2*II_, 0, nullptr, pact, II_, 0);
    tgemm_kernel<EP_SILU><<<ggrid(T_, II_), 256, SMEM_PIPE_BYTES>>>(T_, II_, DIM_, px2, DIM_, 0, gate_up_w + II_, 2*II_, 0, pact, pact, II_, 0);
    tgemm_kernel<EP_ADD><<<ggrid(T_, DIM_), 256, SMEM_PIPE_BYTES>>>(T_, DIM_, II_, pact, II_, 0, down_w, DIM_, 0, ph, out, DIM_, 0);
}

// round 15
// speedup vs baseline: 1.6217x; 1.0040x over previous
#include <cuda_runtime.h>
#include <math.h>
#include <stdint.h>

#define T_    2048
#define DIM_  2048
#define QL_   1536
#define H_    16
#define DH_   256
#define NOPE_ 192
#define HI_   32
#define DI_   128
#define INOPE_ 64
#define SC_   512
#define TOPK_ 256
#define II_   8192
#define G_    4
#define OLORA_ 512
#define FG_   1024
#define NCAT_ 1568
#define EPSF  1e-6f
#define NEGF  (-1e30f)
#define SCALE_   0.0625f
#define ISCALE_  0.08838834764831845f
#define LOG_THETA 11.98292909421596506

// ---------------- scratch ----------------
__device__ float g_x   [T_ * DIM_];
__device__ float g_qr  [T_ * QL_];
__device__ float g_q   [T_ * H_ * DH_];
__device__ float g_qi  [T_ * HI_ * DI_];
__device__ float g_wcat[DIM_ * NCAT_];
__device__ float g_cat [T_ * NCAT_];
__device__ float g_kvF [T_ * 2 * DH_];
__device__ float g_kvc [SC_ * DH_];
__device__ float g_ikF [T_ * 2 * DI_];
__device__ float g_ki  [SC_ * DI_];
__device__ float g_kiT [DI_ * SC_];
__device__ float g_woaT[G_ * FG_ * OLORA_];
__device__ float g_iw  [T_ * HI_];
__device__ float g_isc [T_ * SC_];
__device__ int   g_selidx[T_ * TOPK_];
__device__ int   g_selcnt[T_];
__device__ float g_o   [T_ * H_ * DH_];
__device__ float g_oa  [T_ * G_ * OLORA_];
__device__ float g_h   [T_ * DIM_];
__device__ float g_x2  [T_ * DIM_];
__device__ float g_gu2 [(size_t)2 * T_ * II_];   // z-batched {gate, up} raw outputs
__device__ float g_act [(size_t)T_ * II_];
__device__ float g_ropeC[T_ * 32];
__device__ float g_ropeS[T_ * 32];

// ---------------- reductions ----------------
__device__ __forceinline__ float blockReduceSum(float v) {
    __shared__ float sh[32];
    int lane = threadIdx.x & 31, wid = threadIdx.x >> 5;
    #pragma unroll
    for (int o = 16; o > 0; o >>= 1) v += __shfl_xor_sync(0xffffffffu, v, o);
    if (lane == 0) sh[wid] = v;
    __syncthreads();
    int nw = (blockDim.x + 31) >> 5;
    if (wid == 0) {
        float r = (lane < nw) ? sh[lane] : 0.0f;
        #pragma unroll
        for (int o = 16; o > 0; o >>= 1) r += __shfl_xor_sync(0xffffffffu, r, o);
        if (lane == 0) sh[0] = r;
    }
    __syncthreads();
    float res = sh[0];
    __syncthreads();
    return res;
}

// ---------------- tf32 / cp.async helpers ----------------
__device__ __forceinline__ uint32_t f2tf32(float x) {
    uint32_t r;
    asm("cvt.rna.tf32.f32 %0, %1;" : "=r"(r) : "f"(x));
    return r;
}

__device__ __forceinline__ void mma_tf32(float* d, const uint32_t* a, const uint32_t* b) {
    asm volatile(
        "mma.sync.aligned.m16n8k8.row.col.f32.tf32.tf32.f32 "
        "{%0,%1,%2,%3}, {%4,%5,%6,%7}, {%8,%9}, {%0,%1,%2,%3};"
        : "+f"(d[0]), "+f"(d[1]), "+f"(d[2]), "+f"(d[3])
        : "r"(a[0]), "r"(a[1]), "r"(a[2]), "r"(a[3]), "r"(b[0]), "r"(b[1]));
}

__device__ __forceinline__ void cp16(float* smem_dst, const float* gsrc, bool pred) {
    uint32_t s = (uint32_t)__cvta_generic_to_shared(smem_dst);
    int sz = pred ? 16 : 0;
    asm volatile("cp.async.cg.shared.global [%0], [%1], 16, %2;\n"
                 :: "r"(s), "l"(gsrc), "r"(sz));
}
#define CP_COMMIT() asm volatile("cp.async.commit_group;" ::: "memory")
#define CP_WAIT1()  asm volatile("cp.async.wait_group 1;" ::: "memory")
#define CP_WAIT0()  asm volatile("cp.async.wait_group 0;" ::: "memory")

// ---------------- epilogue modes ----------------
#define EP_NONE  0
#define EP_ADD   1
#define EP_RFUSE 4

// ---------------- tensor-core TF32 GEMM, 128x128x32, 3-stage cp.async +
// register double-buffered fragments ----------------
#define BM 128
#define BN 128
#define BK 32
#define AS_S 36
#define BS_S 136
#define A_TILE (BM * AS_S)
#define B_TILE (BK * BS_S)
#define STAGE_F (A_TILE + B_TILE)
#define SMEM_PIPE_BYTES (STAGE_F * 3 * 4)   // 107520

template<int EP>
__global__ void __launch_bounds__(256, 2) tgemm_kernel(
    int M, int N, int K,
    const float* __restrict__ A, int lda, int aZ,
    const float* __restrict__ B, int ldb, int bZ,
    const float* __restrict__ Cadd,
    float* __restrict__ C, int ldc, int cZ)
{
    extern __shared__ float smem[];
    const int bm = blockIdx.y * BM;
    const int bn = blockIdx.x * BN;
    A += (size_t)blockIdx.z * aZ;
    B += (size_t)blockIdx.z * bZ;
    C += (size_t)blockIdx.z * cZ;
    const int tid = threadIdx.x;
    const int lane = tid & 31;
    const int wid = tid >> 5;
    const int wm = wid & 3;
    const int wn = wid >> 2;
    const int gid = lane >> 2;
    const int tig = lane & 3;

    float acc[2][8][4];
    #pragma unroll
    for (int mi = 0; mi < 2; mi++)
        #pragma unroll
        for (int ni = 0; ni < 8; ni++)
            #pragma unroll
            for (int r = 0; r < 4; r++) acc[mi][ni][r] = 0.0f;

    const int nIter = K / BK;

    auto issue = [&](int st, int k0) {
        float* sA = smem + st * STAGE_F;
        float* sB = sA + A_TILE;
        #pragma unroll
        for (int i = 0; i < 4; i++) {
            int f = tid + i * 256;
            int r = f >> 3, q = f & 7;
            int gr = bm + r;
            cp16(&sA[r * AS_S + 4 * q], A + (size_t)gr * lda + k0 + 4 * q, gr < M);
        }
        #pragma unroll
        for (int i = 0; i < 4; i++) {
            int f = tid + i * 256;
            int k = f >> 5, q = f & 31;
            int gc = bn + 4 * q;
            cp16(&sB[k * BS_S + 4 * q], B + (size_t)(k0 + k) * ldb + gc, gc < N);
        }
    };

    auto load_frags = [&](const float* sA, const float* sB, int kb,
                          uint32_t af[2][4], uint32_t bf[8][2]) {
        #pragma unroll
        for (int mi = 0; mi < 2; mi++) {
            int r = wm * 32 + mi * 16 + gid;
            af[mi][0] = f2tf32(sA[r * AS_S + kb + tig]);
            af[mi][1] = f2tf32(sA[(r + 8) * AS_S + kb + tig]);
            af[mi][2] = f2tf32(sA[r * AS_S + kb + tig + 4]);
            af[mi][3] = f2tf32(sA[(r + 8) * AS_S + kb + tig + 4]);
        }
        #pragma unroll
        for (int ni = 0; ni < 8; ni++) {
            int c = wn * 64 + ni * 8 + gid;
            bf[ni][0] = f2tf32(sB[(kb + tig) * BS_S + c]);
            bf[ni][1] = f2tf32(sB[(kb + tig + 4) * BS_S + c]);
        }
    };

    auto frag_compute = [&](int st) {
        const float* sA = smem + st * STAGE_F;
        const float* sB = sA + A_TILE;
        uint32_t af[2][2][4];
        uint32_t bf[2][8][2];
        load_frags(sA, sB, 0, af[0], bf[0]);
        #pragma unroll
        for (int kk = 0; kk < 4; kk++) {
            if (kk < 3)
                load_frags(sA, sB, (kk + 1) * 8, af[(kk + 1) & 1], bf[(kk + 1) & 1]);
            #pragma unroll
            for (int mi = 0; mi < 2; mi++)
                #pragma unroll
                for (int ni = 0; ni < 8; ni++)
                    mma_tf32(acc[mi][ni], af[kk & 1][mi], bf[kk & 1][ni]);
        }
    };

    issue(0, 0);
    CP_COMMIT();
    if (nIter > 1) { issue(1, BK); CP_COMMIT(); }

    int st = 0;
    for (int it = 0; it < nIter; ++it) {
        if (it + 1 < nIter) CP_WAIT1(); else CP_WAIT0();
        __syncthreads();
        if (it + 2 < nIter) {
            int st2 = st + 2; if (st2 >= 3) st2 -= 3;
            issue(st2, (it + 2) * BK);
            CP_COMMIT();
        }
        frag_compute(st);
        if (++st == 3) st = 0;
    }

    // ---------------- epilogues ----------------
    if (EP == EP_RFUSE) {
        int t = bm / HI_ + wm;
        float wA = Cadd[t * HI_ + gid];
        float wB = Cadd[t * HI_ + gid + 8];
        float wC = Cadd[t * HI_ + gid + 16];
        float wD = Cadd[t * HI_ + gid + 24];
        #pragma unroll
        for (int ni = 0; ni < 8; ni++) {
            float p0 = wA * fmaxf(acc[0][ni][0], 0.f) + wB * fmaxf(acc[0][ni][2], 0.f)
                     + wC * fmaxf(acc[1][ni][0], 0.f) + wD * fmaxf(acc[1][ni][2], 0.f);
            float p1 = wA * fmaxf(acc[0][ni][1], 0.f) + wB * fmaxf(acc[0][ni][3], 0.f)
                     + wC * fmaxf(acc[1][ni][1], 0.f) + wD * fmaxf(acc[1][ni][3], 0.f);
            #pragma unroll
            for (int off = 4; off < 32; off <<= 1) {
                p0 += __shfl_xor_sync(0xffffffffu, p0, off);
                p1 += __shfl_xor_sync(0xffffffffu, p1, off);
            }
            if (gid == 0) {
                int c = bn + wn * 64 + ni * 8 + tig * 2;
                C[(size_t)t * ldc + c]     = p0 * ISCALE_;
                C[(size_t)t * ldc + c + 1] = p1 * ISCALE_;
            }
        }
        return;
    }

    #pragma unroll
    for (int mi = 0; mi < 2; mi++) {
        int r0 = bm + wm * 32 + mi * 16 + gid;
        int r1 = r0 + 8;
        #pragma unroll
        for (int ni = 0; ni < 8; ni++) {
            int c = bn + wn * 64 + ni * 8 + tig * 2;
            float* ap = acc[mi][ni];
            if (c < N) {
                #pragma unroll
                for (int half = 0; half < 2; half++) {
                    int r = half ? r1 : r0;
                    if (r >= M) continue;
                    float a0 = ap[half * 2], a1 = ap[half * 2 + 1];
                    float v0, v1;
                    if (EP == EP_NONE) {
                        v0 = a0; v1 = a1;
                    } else { // EP_ADD
                        float2 cc = *(const float2*)(Cadd + (size_t)r * ldc + c);
                        v0 = a0 + cc.x; v1 = a1 + cc.y;
                    }
                    *(float2*)(C + (size_t)r * ldc + c) = make_float2(v0, v1);
                }
            }
        }
    }
}

// ---------------- concat 5 projection weights column-wise ----------------
__global__ void concat_kernel(const float* __restrict__ wkv, const float* __restrict__ wg,
                              const float* __restrict__ iwkv, const float* __restrict__ iwg,
                              const float* __restrict__ iwp, float* __restrict__ out)
{
    int k = blockIdx.x;
    float* o = out + (size_t)k * NCAT_;
    for (int j = threadIdx.x; j < 512; j += 256) o[j]        = wkv [k * 512 + j];
    for (int j = threadIdx.x; j < 512; j += 256) o[512 + j]  = wg  [k * 512 + j];
    for (int j = threadIdx.x; j < 256; j += 256) o[1024 + j] = iwkv[k * 256 + j];
    for (int j = threadIdx.x; j < 256; j += 256) o[1280 + j] = iwg [k * 256 + j];
    if (threadIdx.x < 32) o[1536 + threadIdx.x] = iwp[k * 32 + threadIdx.x];
}

// ---------------- fused gate/split of the concat GEMM output ----------------
__global__ void fusedgate_kernel(const float* __restrict__ cat,
                                 const float* __restrict__ ape_kv, const float* __restrict__ ape_ik,
                                 float* __restrict__ kvF, float* __restrict__ ikF,
                                 float* __restrict__ iw)
{
    int t = blockIdx.x;
    const float* row = cat + (size_t)t * NCAT_;
    int a = t & 3;
    for (int e = threadIdx.x; e < 512; e += 256)
        kvF[t * 512 + e] = row[e] / (1.0f + expf(-row[512 + e])) + ape_kv[a * 512 + e];
    for (int e = threadIdx.x; e < 256; e += 256)
        ikF[t * 256 + e] = row[1024 + e] / (1.0f + expf(-row[1280 + e])) + ape_ik[a * 256 + e];
    if (threadIdx.x < 32) iw[t * 32 + threadIdx.x] = row[1536 + threadIdx.x];
}

// ---------------- silu-mul on z-batched MLP output ----------------
__global__ void silu2_kernel(const float* __restrict__ gu2, float* __restrict__ act)
{
    size_t i = (size_t)blockIdx.x * blockDim.x + threadIdx.x;
    if (i >= (size_t)T_ * II_) return;
    float g = gu2[i];
    float u = gu2[(size_t)T_ * II_ + i];
    act[i] = g / (1.0f + expf(-g)) * u;
}

// ---------------- tiled transpose ----------------
__global__ void transpose_kernel(const float* __restrict__ in, float* __restrict__ out,
                                 int R, int C)
{
    __shared__ float tile[32][33];
    const float* inz = in + (size_t)blockIdx.z * R * C;
    float* outz = out + (size_t)blockIdx.z * R * C;
    int bx = blockIdx.x * 32, by = blockIdx.y * 32;
    int x = bx + threadIdx.x;
    #pragma unroll
    for (int i = 0; i < 4; i++) {
        int y = by + threadIdx.y + 8 * i;
        if (y < R && x < C) tile[threadIdx.y + 8 * i][threadIdx.x] = inz[(size_t)y * C + x];
    }
    __syncthreads();
    int x2 = by + threadIdx.x;
    #pragma unroll
    for (int i = 0; i < 4; i++) {
        int y2 = bx + threadIdx.y + 8 * i;
        if (y2 < C && x2 < R) outz[(size_t)y2 * R + x2] = tile[threadIdx.x][threadIdx.y + 8 * i];
    }
}

// ---------------- rmsnorm ----------------
__global__ void rms_kernel(const float* __restrict__ in, const float* __restrict__ w,
                           float* __restrict__ out, int D)
{
    int t = blockIdx.x;
    const float* row = in + (size_t)t * D;
    float s = 0.0f;
    for (int d = threadIdx.x; d < D; d += blockDim.x) { float v = row[d]; s += v * v; }
    s = blockReduceSum(s);
    float inv = rsqrtf(s / (float)D + EPSF);
    for (int d = threadIdx.x; d < D; d += blockDim.x)
        out[(size_t)t * D + d] = row[d] * inv * w[d];
}

// ---------------- compress ----------------
__global__ void compress_kernel(const float* __restrict__ kvf, const float* __restrict__ w,
                                float* __restrict__ out, int d)
{
    int b = blockIdx.x;
    int e = threadIdx.x;
    int W = 2 * d;
    float m = 0.0f;
    if (b > 0) {
        #pragma unroll
        for (int r = 0; r < 4; r++) m += kvf[(size_t)((b - 1) * 4 + r) * W + e];
    }
    #pragma unroll
    for (int r = 0; r < 4; r++) m += kvf[(size_t)(b * 4 + r) * W + d + e];
    m *= 0.125f;
    float ssq = blockReduceSum(m * m);
    float inv = rsqrtf(ssq / (float)d + EPSF);
    out[(size_t)b * d + e] = m * inv * w[e];
}

// ---------------- RoPE table + apply ----------------
__global__ void rope_table_kernel(float* __restrict__ tc, float* __restrict__ ts)
{
    int i = blockIdx.x * blockDim.x + threadIdx.x;
    if (i >= T_ * 32) return;
    int pos = i >> 5, f = i & 31;
    double freq = exp(-((double)(2 * f) / 64.0) * LOG_THETA);
    double ang = (double)pos * freq;
    tc[i] = (float)cos(ang);
    ts[i] = (float)sin(ang);
}

__global__ void rope_apply_kernel(float* __restrict__ x, const int* __restrict__ positions,
                                  const float* __restrict__ tc, const float* __restrict__ ts,
                                  int Hh, int Dd, int ropeOff, int compPos, int nRows)
{
    int row = blockIdx.x * 8 + (threadIdx.x >> 5);
    if (row >= nRows) return;
    int lane = threadIdx.x & 31;
    int t = row / Hh;
    int pos = compPos ? (4 * (t + 1) - 1) : positions[t];
    float c = tc[pos * 32 + lane], s = ts[pos * 32 + lane];
    float* p = x + (size_t)row * Dd + ropeOff;
    float x0 = p[2 * lane], x1 = p[2 * lane + 1];
    p[2 * lane]     = x0 * c - x1 * s;
    p[2 * lane + 1] = x0 * s + x1 * c;
}

// ---------------- exact top-256 ----------------
__global__ void topk_kernel(const float* __restrict__ isc, int* __restrict__ selidx,
                            int* __restrict__ selcnt)
{
    int t = blockIdx.x;
    __shared__ float sv[SC_];
    __shared__ int   si[SC_];
    int tid = threadIdx.x;
    int visCount = (t >= 3) ? ((t - 3) / 4 + 1) : 0;
    for (int i = tid; i < SC_; i += 256) {
        sv[i] = (i < visCount) ? isc[t * SC_ + i] : NEGF;
        si[i] = i;
    }
    __syncthreads();
    for (int k = 2; k <= SC_; k <<= 1) {
        for (int j = k >> 1; j > 0; j >>= 1) {
            for (int base = tid; base < SC_; base += 256) {
                int partner = base ^ j;
                if (partner > base) {
                    bool up = ((base & k) == 0);
                    float va = sv[base], vb = sv[partner];
                    int ia = si[base], ib = si[partner];
                    bool aFirst = (va > vb) || (va == vb && ia < ib);
                    if (up ? !aFirst : aFirst) {
                        sv[base] = vb; sv[partner] = va;
                        si[base] = ib; si[partner] = ia;
                    }
                }
            }
            __syncthreads();
        }
    }
    int cnt = min(visCount, TOPK_);
    if (tid == 0) selcnt[t] = cnt;
    for (int r = tid; r < cnt; r += 256) selidx[t * TOPK_ + r] = si[r];
}

// ---------------- head-shared flash attention ----------------
__global__ void __launch_bounds__(512) attn2_kernel(
    const float* __restrict__ q, const float* __restrict__ kvc,
    const int* __restrict__ selidx, const int* __restrict__ selcnt,
    const float* __restrict__ sink, float* __restrict__ o)
{
    __shared__ float kt[32][DH_];
    __shared__ int   ss[TOPK_];
    int t = blockIdx.x;
    int tid = threadIdx.x, lane = tid & 31, w = tid >> 5;
    int cnt = selcnt[t];
    for (int i = tid; i < cnt; i += 512) ss[i] = selidx[t * TOPK_ + i];
    __syncthreads();

    float q8[8];
    const float* qp = q + ((size_t)t * H_ + w) * DH_;
    #pragma unroll
    for (int i = 0; i < 8; i++) q8[i] = qp[lane + 32 * i];

    float m = NEGF, se = 0.0f;
    float acc[8] = {};

    for (int j0 = 0; j0 < cnt; j0 += 32) {
        int rem = min(32, cnt - j0);
        __syncthreads();
        for (int f = tid; f < 32 * 64; f += 512) {
            int r = f >> 6, c4 = f & 63;
            float4 v = make_float4(0.f, 0.f, 0.f, 0.f);
            if (r < rem) v = *(const float4*)(kvc + (size_t)ss[j0 + r] * DH_ + 4 * c4);
            *(float4*)&kt[r][4 * c4] = v;
        }
        __syncthreads();
        for (int j = 0; j < rem; j++) {
            float dot = 0.0f;
            #pragma unroll
            for (int i = 0; i < 8; i++) dot += q8[i] * kt[j][lane + 32 * i];
            #pragma unroll
            for (int off = 16; off > 0; off >>= 1)
                dot += __shfl_xor_sync(0xffffffffu, dot, off);
            float lg = dot * SCALE_;
            float mn = fmaxf(m, lg);
            float sc = expf(m - mn);
            float p  = expf(lg - mn);
            se = se * sc + p;
            #pragma unroll
            for (int i = 0; i < 8; i++)
                acc[i] = acc[i] * sc + p * kt[j][lane + 32 * i];
            m = mn;
        }
    }

    float snk = sink[w];
    float mn = fmaxf(m, snk);
    float sc = expf(m - mn);
    se = se * sc + expf(snk - mn);
    float inv = 1.0f / se;
    float* op = o + ((size_t)t * H_ + w) * DH_;
    #pragma unroll
    for (int i = 0; i < 8; i++) op[lane + 32 * i] = acc[i] * sc * inv;
}

// ---------------- host ----------------
static inline dim3 ggrid(int M, int N) { return dim3((N + BN - 1) / BN, (M + BM - 1) / BM); }

extern "C" void kernel_launch(void* const* d_in, const int* in_sizes, int n_in,
                              void* d_out, int out_size)
{
    const float* hidden      = (const float*)d_in[0];
    const int*   positions   = (const int*)  d_in[1];
    const float* ln1_w       = (const float*)d_in[2];
    const float* ln2_w       = (const float*)d_in[3];
    const float* wq_a        = (const float*)d_in[4];
    const float* q_norm_w    = (const float*)d_in[5];
    const float* wq_b        = (const float*)d_in[6];
    const float* comp_wkv    = (const float*)d_in[7];
    const float* comp_wgate  = (const float*)d_in[8];
    const float* comp_ape    = (const float*)d_in[9];
    const float* comp_norm_w = (const float*)d_in[10];
    const float* idx_wq_b    = (const float*)d_in[11];
    const float* idx_wproj   = (const float*)d_in[12];
    const float* icomp_wkv   = (const float*)d_in[13];
    const float* icomp_wgate = (const float*)d_in[14];
    const float* icomp_ape   = (const float*)d_in[15];
    const float* icomp_norm_w= (const float*)d_in[16];
    const float* attn_sink   = (const float*)d_in[17];
    const float* wo_a        = (const float*)d_in[18];
    const float* wo_b        = (const float*)d_in[19];
    const float* gate_up_w   = (const float*)d_in[20];
    const float* down_w      = (const float*)d_in[21];
    float* out = (float*)d_out;

    float *px,*pqr,*pq,*pqi,*pwcat,*pcat,*pkvF,*pkvc,*pikF,*pki,*pkiT,*pwoaT,*piw,*pisc;
    float *po,*poa,*ph,*px2,*pgu2,*pact,*pRC,*pRS;
    int *pselidx,*pselcnt;
    cudaGetSymbolAddress((void**)&px, g_x);       cudaGetSymbolAddress((void**)&pqr, g_qr);
    cudaGetSymbolAddress((void**)&pq, g_q);       cudaGetSymbolAddress((void**)&pqi, g_qi);
    cudaGetSymbolAddress((void**)&pwcat, g_wcat); cudaGetSymbolAddress((void**)&pcat, g_cat);
    cudaGetSymbolAddress((void**)&pkvF, g_kvF);   cudaGetSymbolAddress((void**)&pkvc, g_kvc);
    cudaGetSymbolAddress((void**)&pikF, g_ikF);   cudaGetSymbolAddress((void**)&pki, g_ki);
    cudaGetSymbolAddress((void**)&pkiT, g_kiT);   cudaGetSymbolAddress((void**)&pwoaT, g_woaT);
    cudaGetSymbolAddress((void**)&piw, g_iw);     cudaGetSymbolAddress((void**)&pisc, g_isc);
    cudaGetSymbolAddress((void**)&pselidx, g_selidx); cudaGetSymbolAddress((void**)&pselcnt, g_selcnt);
    cudaGetSymbolAddress((void**)&po, g_o);       cudaGetSymbolAddress((void**)&poa, g_oa);
    cudaGetSymbolAddress((void**)&ph, g_h);       cudaGetSymbolAddress((void**)&px2, g_x2);
    cudaGetSymbolAddress((void**)&pgu2, g_gu2);   cudaGetSymbolAddress((void**)&pact, g_act);
    cudaGetSymbolAddress((void**)&pRC, g_ropeC);  cudaGetSymbolAddress((void**)&pRS, g_ropeS);

    cudaFuncSetAttribute(tgemm_kernel<EP_NONE>,  cudaFuncAttributeMaxDynamicSharedMemorySize, SMEM_PIPE_BYTES);
    cudaFuncSetAttribute(tgemm_kernel<EP_ADD>,   cudaFuncAttributeMaxDynamicSharedMemorySize, SMEM_PIPE_BYTES);
    cudaFuncSetAttribute(tgemm_kernel<EP_RFUSE>, cudaFuncAttributeMaxDynamicSharedMemorySize, SMEM_PIPE_BYTES);

    // 0) rope table + weight concat
    rope_table_kernel<<<(T_ * 32 + 255) / 256, 256>>>(pRC, pRS);
    concat_kernel<<<DIM_, 256>>>(comp_wkv, comp_wgate, icomp_wkv, icomp_wgate, idx_wproj, pwcat);

    // 1) x = rms(hidden, ln1)
    rms_kernel<<<T_, 256>>>(hidden, ln1_w, px, DIM_);

    // 2) qr = rms(x @ wq_a, q_norm)
    tgemm_kernel<EP_NONE><<<ggrid(T_, QL_), 256, SMEM_PIPE_BYTES>>>(T_, QL_, DIM_, px, DIM_, 0, wq_a, QL_, 0, nullptr, pqr, QL_, 0);
    rms_kernel<<<T_, 256>>>(pqr, q_norm_w, pqr, QL_);

    // 3) q / qi projections + rope
    tgemm_kernel<EP_NONE><<<ggrid(T_, H_*DH_), 256, SMEM_PIPE_BYTES>>>(T_, H_*DH_, QL_, pqr, QL_, 0, wq_b, H_*DH_, 0, nullptr, pq, H_*DH_, 0);
    tgemm_kernel<EP_NONE><<<ggrid(T_, HI_*DI_), 256, SMEM_PIPE_BYTES>>>(T_, HI_*DI_, QL_, pqr, QL_, 0, idx_wq_b, HI_*DI_, 0, nullptr, pqi, HI_*DI_, 0);
    rope_apply_kernel<<<T_ * H_ / 8,  256>>>(pq,  positions, pRC, pRS, H_,  DH_, NOPE_,  0, T_ * H_);
    rope_apply_kernel<<<T_ * HI_ / 8, 256>>>(pqi, positions, pRC, pRS, HI_, DI_, INOPE_, 0, T_ * HI_);

    // 4) ONE fused projection GEMM (kv | kv-gate | ik | ik-gate | iw), then gate/split
    tgemm_kernel<EP_NONE><<<ggrid(T_, NCAT_), 256, SMEM_PIPE_BYTES>>>(T_, NCAT_, DIM_, px, DIM_, 0, pwcat, NCAT_, 0, nullptr, pcat, NCAT_, 0);
    fusedgate_kernel<<<T_, 256>>>(pcat, comp_ape, icomp_ape, pkvF, pikF, piw);

    // 5) compress + rope (kvc, ki) + ki transpose
    compress_kernel<<<SC_, DH_>>>(pkvF, comp_norm_w, pkvc, DH_);
    rope_apply_kernel<<<SC_ / 8, 256>>>(pkvc, positions, pRC, pRS, 1, DH_, NOPE_, 1, SC_);
    compress_kernel<<<SC_, DI_>>>(pikF, icomp_norm_w, pki, DI_);
    rope_apply_kernel<<<SC_ / 8, 256>>>(pki, positions, pRC, pRS, 1, DI_, INOPE_, 1, SC_);
    transpose_kernel<<<dim3(DI_/32, SC_/32, 1), dim3(32, 8)>>>(pki, pkiT, SC_, DI_);

    // 6) R GEMM with fused weighted-relu head reduction -> isc
    tgemm_kernel<EP_RFUSE><<<ggrid(T_*HI_, SC_), 256, SMEM_PIPE_BYTES>>>(T_*HI_, SC_, DI_, pqi, DI_, 0, pkiT, SC_, 0, piw, pisc, SC_, 0);

    // 7) top-256 + attention
    topk_kernel<<<T_, 256>>>(pisc, pselidx, pselcnt);
    attn2_kernel<<<T_, 512>>>(pq, pkvc, pselidx, pselcnt, attn_sink, po);

    // 8) output proj: transpose wo_a, z-batched GEMM, then wo_b (+residual)
    transpose_kernel<<<dim3(FG_/32, OLORA_/32, G_), dim3(32, 8)>>>(wo_a, pwoaT, OLORA_, FG_);
    {
        dim3 g = ggrid(T_, OLORA_); g.z = G_;
        tgemm_kernel<EP_NONE><<<g, 256, SMEM_PIPE_BYTES>>>(
            T_, OLORA_, FG_, po, H_*DH_, FG_, pwoaT, OLORA_, FG_*OLORA_,
            nullptr, poa, G_*OLORA_, OLORA_);
    }
    tgemm_kernel<EP_ADD><<<ggrid(T_, DIM_), 256, SMEM_PIPE_BYTES>>>(T_, DIM_, G_*OLORA_, poa, G_*OLORA_, 0, wo_b, DIM_, 0, hidden, ph, DIM_, 0);

    // 9) MLP: z=2 batched {gate, up} GEMM (B halves of gate_up_w via bZ=II), silu-mul, down (+residual)
    rms_kernel<<<T_, 256>>>(ph, ln2_w, px2, DIM_);
    {
        dim3 g = ggrid(T_, II_); g.z = 2;
        tgemm_kernel<EP_NONE><<<g, 256, SMEM_PIPE_BYTES>>>(
            T_, II_, DIM_, px2, DIM_, 0, gate_up_w, 2*II_, II_,
            nullptr, pgu2, II_, T_ * II_);
    }
    silu2_kernel<<<(int)(((size_t)T_ * II_ + 255) / 256), 256>>>(pgu2, pact);
    tgemm_kernel<EP_ADD><<<ggrid(T_, DIM_), 256, SMEM_PIPE_BYTES>>>(T_, DIM_, II_, pact, II_, 0, down_w, DIM_, 0, ph, out, DIM_, 0);
}

// round 16
// speedup vs baseline: 1.6306x; 1.0054x over previous
#include <cuda_runtime.h>
#include <math.h>
#include <stdint.h>

#define T_    2048
#define DIM_  2048
#define QL_   1536
#define H_    16
#define DH_   256
#define NOPE_ 192
#define HI_   32
#define DI_   128
#define INOPE_ 64
#define SC_   512
#define TOPK_ 256
#define II_   8192
#define G_    4
#define OLORA_ 512
#define FG_   1024
#define NCAT_ 1568
#define EPSF  1e-6f
#define NEGF  (-1e30f)
#define SCALE_   0.0625f
#define ISCALE_  0.08838834764831845f
#define LOG_THETA 11.98292909421596506

// ---------------- scratch ----------------
__device__ float g_x   [T_ * DIM_];
__device__ float g_qr  [T_ * QL_];
__device__ float g_q   [T_ * H_ * DH_];
__device__ float g_qi  [T_ * HI_ * DI_];
__device__ float g_wcat[DIM_ * NCAT_];
__device__ float g_cat [2 * T_ * NCAT_];        // split-K partials
__device__ float g_kvF [T_ * 2 * DH_];
__device__ float g_kvc [SC_ * DH_];
__device__ float g_ikF [T_ * 2 * DI_];
__device__ float g_ki  [SC_ * DI_];
__device__ float g_kiT [DI_ * SC_];
__device__ float g_woaT[G_ * FG_ * OLORA_];
__device__ float g_iw  [T_ * HI_];
__device__ float g_isc [T_ * SC_];
__device__ int   g_selidx[T_ * TOPK_];
__device__ int   g_selcnt[T_];
__device__ float g_o   [T_ * H_ * DH_];
__device__ float g_oa  [T_ * G_ * OLORA_];
__device__ float g_hp  [2 * T_ * DIM_];         // split-K partials (wo_b / down)
__device__ float g_h   [T_ * DIM_];
__device__ float g_x2  [T_ * DIM_];
__device__ float g_gu2 [(size_t)2 * T_ * II_];
__device__ float g_act [(size_t)T_ * II_];
__device__ float g_ropeC[T_ * 32];
__device__ float g_ropeS[T_ * 32];

// ---------------- reductions ----------------
__device__ __forceinline__ float blockReduceSum(float v) {
    __shared__ float sh[32];
    int lane = threadIdx.x & 31, wid = threadIdx.x >> 5;
    #pragma unroll
    for (int o = 16; o > 0; o >>= 1) v += __shfl_xor_sync(0xffffffffu, v, o);
    if (lane == 0) sh[wid] = v;
    __syncthreads();
    int nw = (blockDim.x + 31) >> 5;
    if (wid == 0) {
        float r = (lane < nw) ? sh[lane] : 0.0f;
        #pragma unroll
        for (int o = 16; o > 0; o >>= 1) r += __shfl_xor_sync(0xffffffffu, r, o);
        if (lane == 0) sh[0] = r;
    }
    __syncthreads();
    float res = sh[0];
    __syncthreads();
    return res;
}

// ---------------- tf32 / cp.async helpers ----------------
__device__ __forceinline__ uint32_t f2tf32(float x) {
    uint32_t r;
    asm("cvt.rna.tf32.f32 %0, %1;" : "=r"(r) : "f"(x));
    return r;
}

__device__ __forceinline__ void mma_tf32(float* d, const uint32_t* a, const uint32_t* b) {
    asm volatile(
        "mma.sync.aligned.m16n8k8.row.col.f32.tf32.tf32.f32 "
        "{%0,%1,%2,%3}, {%4,%5,%6,%7}, {%8,%9}, {%0,%1,%2,%3};"
        : "+f"(d[0]), "+f"(d[1]), "+f"(d[2]), "+f"(d[3])
        : "r"(a[0]), "r"(a[1]), "r"(a[2]), "r"(a[3]), "r"(b[0]), "r"(b[1]));
}

__device__ __forceinline__ void cp16(float* smem_dst, const float* gsrc, bool pred) {
    uint32_t s = (uint32_t)__cvta_generic_to_shared(smem_dst);
    int sz = pred ? 16 : 0;
    asm volatile("cp.async.cg.shared.global [%0], [%1], 16, %2;\n"
                 :: "r"(s), "l"(gsrc), "r"(sz));
}
#define CP_COMMIT() asm volatile("cp.async.commit_group;" ::: "memory")
#define CP_WAIT1()  asm volatile("cp.async.wait_group 1;" ::: "memory")
#define CP_WAIT0()  asm volatile("cp.async.wait_group 0;" ::: "memory")

// ---------------- epilogue modes ----------------
#define EP_NONE  0
#define EP_ADD   1
#define EP_RFUSE 4

// ---------------- tensor-core TF32 GEMM ----------------
#define BM 128
#define BN 128
#define BK 32
#define AS_S 36
#define BS_S 136
#define A_TILE (BM * AS_S)
#define B_TILE (BK * BS_S)
#define STAGE_F (A_TILE + B_TILE)
#define SMEM_PIPE_BYTES (STAGE_F * 3 * 4)   // 107520

template<int EP>
__global__ void __launch_bounds__(256, 2) tgemm_kernel(
    int M, int N, int K,
    const float* __restrict__ A, int lda, int aZ,
    const float* __restrict__ B, int ldb, int bZ,
    const float* __restrict__ Cadd,
    float* __restrict__ C, int ldc, int cZ)
{
    extern __shared__ float smem[];
    const int bm = blockIdx.y * BM;
    const int bn = blockIdx.x * BN;
    A += (size_t)blockIdx.z * aZ;
    B += (size_t)blockIdx.z * bZ;
    C += (size_t)blockIdx.z * cZ;
    const int tid = threadIdx.x;
    const int lane = tid & 31;
    const int wid = tid >> 5;
    const int wm = wid & 3;
    const int wn = wid >> 2;
    const int gid = lane >> 2;
    const int tig = lane & 3;

    float acc[2][8][4];
    #pragma unroll
    for (int mi = 0; mi < 2; mi++)
        #pragma unroll
        for (int ni = 0; ni < 8; ni++)
            #pragma unroll
            for (int r = 0; r < 4; r++) acc[mi][ni][r] = 0.0f;

    const int nIter = K / BK;

    auto issue = [&](int st, int k0) {
        float* sA = smem + st * STAGE_F;
        float* sB = sA + A_TILE;
        #pragma unroll
        for (int i = 0; i < 4; i++) {
            int f = tid + i * 256;
            int r = f >> 3, q = f & 7;
            int gr = bm + r;
            cp16(&sA[r * AS_S + 4 * q], A + (size_t)gr * lda + k0 + 4 * q, gr < M);
        }
        #pragma unroll
        for (int i = 0; i < 4; i++) {
            int f = tid + i * 256;
            int k = f >> 5, q = f & 31;
            int gc = bn + 4 * q;
            cp16(&sB[k * BS_S + 4 * q], B + (size_t)(k0 + k) * ldb + gc, gc < N);
        }
    };

    auto load_frags = [&](const float* sA, const float* sB, int kb,
                          uint32_t af[2][4], uint32_t bf[8][2]) {
        #pragma unroll
        for (int mi = 0; mi < 2; mi++) {
            int r = wm * 32 + mi * 16 + gid;
            af[mi][0] = f2tf32(sA[r * AS_S + kb + tig]);
            af[mi][1] = f2tf32(sA[(r + 8) * AS_S + kb + tig]);
            af[mi][2] = f2tf32(sA[r * AS_S + kb + tig + 4]);
            af[mi][3] = f2tf32(sA[(r + 8) * AS_S + kb + tig + 4]);
        }
        #pragma unroll
        for (int ni = 0; ni < 8; ni++) {
            int c = wn * 64 + ni * 8 + gid;
            bf[ni][0] = f2tf32(sB[(kb + tig) * BS_S + c]);
            bf[ni][1] = f2tf32(sB[(kb + tig + 4) * BS_S + c]);
        }
    };

    auto frag_compute = [&](int st) {
        const float* sA = smem + st * STAGE_F;
        const float* sB = sA + A_TILE;
        uint32_t af[2][2][4];
        uint32_t bf[2][8][2];
        load_frags(sA, sB, 0, af[0], bf[0]);
        #pragma unroll
        for (int kk = 0; kk < 4; kk++) {
            if (kk < 3)
                load_frags(sA, sB, (kk + 1) * 8, af[(kk + 1) & 1], bf[(kk + 1) & 1]);
            #pragma unroll
            for (int mi = 0; mi < 2; mi++)
                #pragma unroll
                for (int ni = 0; ni < 8; ni++)
                    mma_tf32(acc[mi][ni], af[kk & 1][mi], bf[kk & 1][ni]);
        }
    };

    issue(0, 0);
    CP_COMMIT();
    if (nIter > 1) { issue(1, BK); CP_COMMIT(); }

    int st = 0;
    for (int it = 0; it < nIter; ++it) {
        if (it + 1 < nIter) CP_WAIT1(); else CP_WAIT0();
        __syncthreads();
        if (it + 2 < nIter) {
            int st2 = st + 2; if (st2 >= 3) st2 -= 3;
            issue(st2, (it + 2) * BK);
            CP_COMMIT();
        }
        frag_compute(st);
        if (++st == 3) st = 0;
    }

    // ---------------- epilogues ----------------
    if (EP == EP_RFUSE) {
        int t = bm / HI_ + wm;
        float wA = Cadd[t * HI_ + gid];
        float wB = Cadd[t * HI_ + gid + 8];
        float wC = Cadd[t * HI_ + gid + 16];
        float wD = Cadd[t * HI_ + gid + 24];
        #pragma unroll
        for (int ni = 0; ni < 8; ni++) {
            float p0 = wA * fmaxf(acc[0][ni][0], 0.f) + wB * fmaxf(acc[0][ni][2], 0.f)
                     + wC * fmaxf(acc[1][ni][0], 0.f) + wD * fmaxf(acc[1][ni][2], 0.f);
            float p1 = wA * fmaxf(acc[0][ni][1], 0.f) + wB * fmaxf(acc[0][ni][3], 0.f)
                     + wC * fmaxf(acc[1][ni][1], 0.f) + wD * fmaxf(acc[1][ni][3], 0.f);
            #pragma unroll
            for (int off = 4; off < 32; off <<= 1) {
                p0 += __shfl_xor_sync(0xffffffffu, p0, off);
                p1 += __shfl_xor_sync(0xffffffffu, p1, off);
            }
            if (gid == 0) {
                int c = bn + wn * 64 + ni * 8 + tig * 2;
                C[(size_t)t * ldc + c]     = p0 * ISCALE_;
                C[(size_t)t * ldc + c + 1] = p1 * ISCALE_;
            }
        }
        return;
    }

    #pragma unroll
    for (int mi = 0; mi < 2; mi++) {
        int r0 = bm + wm * 32 + mi * 16 + gid;
        int r1 = r0 + 8;
        #pragma unroll
        for (int ni = 0; ni < 8; ni++) {
            int c = bn + wn * 64 + ni * 8 + tig * 2;
            float* ap = acc[mi][ni];
            if (c < N) {
                #pragma unroll
                for (int half = 0; half < 2; half++) {
                    int r = half ? r1 : r0;
                    if (r >= M) continue;
                    float a0 = ap[half * 2], a1 = ap[half * 2 + 1];
                    float v0, v1;
                    if (EP == EP_NONE) {
                        v0 = a0; v1 = a1;
                    } else { // EP_ADD
                        float2 cc = *(const float2*)(Cadd + (size_t)r * ldc + c);
                        v0 = a0 + cc.x; v1 = a1 + cc.y;
                    }
                    *(float2*)(C + (size_t)r * ldc + c) = make_float2(v0, v1);
                }
            }
        }
    }
}

// ---------------- split-K combine: out = p0 + p1 (+ residual) ----------------
__global__ void combine2_kernel(const float* __restrict__ parts, const float* __restrict__ res,
                                float* __restrict__ out, size_t n)
{
    size_t i = (size_t)blockIdx.x * blockDim.x + threadIdx.x;
    if (i >= n) return;
    float v = parts[i] + parts[n + i];
    if (res) v += res[i];
    out[i] = v;
}

// ---------------- concat 5 projection weights column-wise ----------------
__global__ void concat_kernel(const float* __restrict__ wkv, const float* __restrict__ wg,
                              const float* __restrict__ iwkv, const float* __restrict__ iwg,
                              const float* __restrict__ iwp, float* __restrict__ out)
{
    int k = blockIdx.x;
    float* o = out + (size_t)k * NCAT_;
    for (int j = threadIdx.x; j < 512; j += 256) o[j]        = wkv [k * 512 + j];
    for (int j = threadIdx.x; j < 512; j += 256) o[512 + j]  = wg  [k * 512 + j];
    for (int j = threadIdx.x; j < 256; j += 256) o[1024 + j] = iwkv[k * 256 + j];
    for (int j = threadIdx.x; j < 256; j += 256) o[1280 + j] = iwg [k * 256 + j];
    if (threadIdx.x < 32) o[1536 + threadIdx.x] = iwp[k * 32 + threadIdx.x];
}

// ---------------- gate/split of split-K concat GEMM output (sums partials) ----------------
__global__ void fusedgate_kernel(const float* __restrict__ cat,
                                 const float* __restrict__ ape_kv, const float* __restrict__ ape_ik,
                                 float* __restrict__ kvF, float* __restrict__ ikF,
                                 float* __restrict__ iw)
{
    int t = blockIdx.x;
    const float* r0 = cat + (size_t)t * NCAT_;
    const float* r1 = r0 + (size_t)T_ * NCAT_;
    int a = t & 3;
    for (int e = threadIdx.x; e < 512; e += 256) {
        float kv = r0[e] + r1[e];
        float gt = r0[512 + e] + r1[512 + e];
        kvF[t * 512 + e] = kv / (1.0f + expf(-gt)) + ape_kv[a * 512 + e];
    }
    for (int e = threadIdx.x; e < 256; e += 256) {
        float kv = r0[1024 + e] + r1[1024 + e];
        float gt = r0[1280 + e] + r1[1280 + e];
        ikF[t * 256 + e] = kv / (1.0f + expf(-gt)) + ape_ik[a * 256 + e];
    }
    if (threadIdx.x < 32)
        iw[t * 32 + threadIdx.x] = r0[1536 + threadIdx.x] + r1[1536 + threadIdx.x];
}

// ---------------- silu-mul on z-batched MLP output ----------------
__global__ void silu2_kernel(const float* __restrict__ gu2, float* __restrict__ act)
{
    size_t i = (size_t)blockIdx.x * blockDim.x + threadIdx.x;
    if (i >= (size_t)T_ * II_) return;
    float g = gu2[i];
    float u = gu2[(size_t)T_ * II_ + i];
    act[i] = g / (1.0f + expf(-g)) * u;
}

// ---------------- tiled transpose ----------------
__global__ void transpose_kernel(const float* __restrict__ in, float* __restrict__ out,
                                 int R, int C)
{
    __shared__ float tile[32][33];
    const float* inz = in + (size_t)blockIdx.z * R * C;
    float* outz = out + (size_t)blockIdx.z * R * C;
    int bx = blockIdx.x * 32, by = blockIdx.y * 32;
    int x = bx + threadIdx.x;
    #pragma unroll
    for (int i = 0; i < 4; i++) {
        int y = by + threadIdx.y + 8 * i;
        if (y < R && x < C) tile[threadIdx.y + 8 * i][threadIdx.x] = inz[(size_t)y * C + x];
    }
    __syncthreads();
    int x2 = by + threadIdx.x;
    #pragma unroll
    for (int i = 0; i < 4; i++) {
        int y2 = bx + threadIdx.y + 8 * i;
        if (y2 < C && x2 < R) outz[(size_t)y2 * R + x2] = tile[threadIdx.x][threadIdx.y + 8 * i];
    }
}

// ---------------- rmsnorm ----------------
__global__ void rms_kernel(const float* __restrict__ in, const float* __restrict__ w,
                           float* __restrict__ out, int D)
{
    int t = blockIdx.x;
    const float* row = in + (size_t)t * D;
    float s = 0.0f;
    for (int d = threadIdx.x; d < D; d += blockDim.x) { float v = row[d]; s += v * v; }
    s = blockReduceSum(s);
    float inv = rsqrtf(s / (float)D + EPSF);
    for (int d = threadIdx.x; d < D; d += blockDim.x)
        out[(size_t)t * D + d] = row[d] * inv * w[d];
}

// ---------------- compress ----------------
__global__ void compress_kernel(const float* __restrict__ kvf, const float* __restrict__ w,
                                float* __restrict__ out, int d)
{
    int b = blockIdx.x;
    int e = threadIdx.x;
    int W = 2 * d;
    float m = 0.0f;
    if (b > 0) {
        #pragma unroll
        for (int r = 0; r < 4; r++) m += kvf[(size_t)((b - 1) * 4 + r) * W + e];
    }
    #pragma unroll
    for (int r = 0; r < 4; r++) m += kvf[(size_t)(b * 4 + r) * W + d + e];
    m *= 0.125f;
    float ssq = blockReduceSum(m * m);
    float inv = rsqrtf(ssq / (float)d + EPSF);
    out[(size_t)b * d + e] = m * inv * w[e];
}

// ---------------- RoPE table + apply ----------------
__global__ void rope_table_kernel(float* __restrict__ tc, float* __restrict__ ts)
{
    int i = blockIdx.x * blockDim.x + threadIdx.x;
    if (i >= T_ * 32) return;
    int pos = i >> 5, f = i & 31;
    double freq = exp(-((double)(2 * f) / 64.0) * LOG_THETA);
    double ang = (double)pos * freq;
    tc[i] = (float)cos(ang);
    ts[i] = (float)sin(ang);
}

__global__ void rope_apply_kernel(float* __restrict__ x, const int* __restrict__ positions,
                                  const float* __restrict__ tc, const float* __restrict__ ts,
                                  int Hh, int Dd, int ropeOff, int compPos, int nRows)
{
    int row = blockIdx.x * 8 + (threadIdx.x >> 5);
    if (row >= nRows) return;
    int lane = threadIdx.x & 31;
    int t = row / Hh;
    int pos = compPos ? (4 * (t + 1) - 1) : positions[t];
    float c = tc[pos * 32 + lane], s = ts[pos * 32 + lane];
    float* p = x + (size_t)row * Dd + ropeOff;
    float x0 = p[2 * lane], x1 = p[2 * lane + 1];
    p[2 * lane]     = x0 * c - x1 * s;
    p[2 * lane + 1] = x0 * s + x1 * c;
}

// ---------------- exact top-256 ----------------
__global__ void topk_kernel(const float* __restrict__ isc, int* __restrict__ selidx,
                            int* __restrict__ selcnt)
{
    int t = blockIdx.x;
    __shared__ float sv[SC_];
    __shared__ int   si[SC_];
    int tid = threadIdx.x;
    int visCount = (t >= 3) ? ((t - 3) / 4 + 1) : 0;
    for (int i = tid; i < SC_; i += 256) {
        sv[i] = (i < visCount) ? isc[t * SC_ + i] : NEGF;
        si[i] = i;
    }
    __syncthreads();
    for (int k = 2; k <= SC_; k <<= 1) {
        for (int j = k >> 1; j > 0; j >>= 1) {
            for (int base = tid; base < SC_; base += 256) {
                int partner = base ^ j;
                if (partner > base) {
                    bool up = ((base & k) == 0);
                    float va = sv[base], vb = sv[partner];
                    int ia = si[base], ib = si[partner];
                    bool aFirst = (va > vb) || (va == vb && ia < ib);
                    if (up ? !aFirst : aFirst) {
                        sv[base] = vb; sv[partner] = va;
                        si[base] = ib; si[partner] = ia;
                    }
                }
            }
            __syncthreads();
        }
    }
    int cnt = min(visCount, TOPK_);
    if (tid == 0) selcnt[t] = cnt;
    for (int r = tid; r < cnt; r += 256) selidx[t * TOPK_ + r] = si[r];
}

// ---------------- head-shared flash attention ----------------
__global__ void __launch_bounds__(512) attn2_kernel(
    const float* __restrict__ q, const float* __restrict__ kvc,
    const int* __restrict__ selidx, const int* __restrict__ selcnt,
    const float* __restrict__ sink, float* __restrict__ o)
{
    __shared__ float kt[32][DH_];
    __shared__ int   ss[TOPK_];
    int t = blockIdx.x;
    int tid = threadIdx.x, lane = tid & 31, w = tid >> 5;
    int cnt = selcnt[t];
    for (int i = tid; i < cnt; i += 512) ss[i] = selidx[t * TOPK_ + i];
    __syncthreads();

    float q8[8];
    const float* qp = q + ((size_t)t * H_ + w) * DH_;
    #pragma unroll
    for (int i = 0; i < 8; i++) q8[i] = qp[lane + 32 * i];

    float m = NEGF, se = 0.0f;
    float acc[8] = {};

    for (int j0 = 0; j0 < cnt; j0 += 32) {
        int rem = min(32, cnt - j0);
        __syncthreads();
        for (int f = tid; f < 32 * 64; f += 512) {
            int r = f >> 6, c4 = f & 63;
            float4 v = make_float4(0.f, 0.f, 0.f, 0.f);
            if (r < rem) v = *(const float4*)(kvc + (size_t)ss[j0 + r] * DH_ + 4 * c4);
            *(float4*)&kt[r][4 * c4] = v;
        }
        __syncthreads();
        for (int j = 0; j < rem; j++) {
            float dot = 0.0f;
            #pragma unroll
            for (int i = 0; i < 8; i++) dot += q8[i] * kt[j][lane + 32 * i];
            #pragma unroll
            for (int off = 16; off > 0; off >>= 1)
                dot += __shfl_xor_sync(0xffffffffu, dot, off);
            float lg = dot * SCALE_;
            float mn = fmaxf(m, lg);
            float sc = expf(m - mn);
            float p  = expf(lg - mn);
            se = se * sc + p;
            #pragma unroll
            for (int i = 0; i < 8; i++)
                acc[i] = acc[i] * sc + p * kt[j][lane + 32 * i];
            m = mn;
        }
    }

    float snk = sink[w];
    float mn = fmaxf(m, snk);
    float sc = expf(m - mn);
    se = se * sc + expf(snk - mn);
    float inv = 1.0f / se;
    float* op = o + ((size_t)t * H_ + w) * DH_;
    #pragma unroll
    for (int i = 0; i < 8; i++) op[lane + 32 * i] = acc[i] * sc * inv;
}

// ---------------- host ----------------
static inline dim3 ggrid(int M, int N) { return dim3((N + BN - 1) / BN, (M + BM - 1) / BM); }

extern "C" void kernel_launch(void* const* d_in, const int* in_sizes, int n_in,
                              void* d_out, int out_size)
{
    const float* hidden      = (const float*)d_in[0];
    const int*   positions   = (const int*)  d_in[1];
    const float* ln1_w       = (const float*)d_in[2];
    const float* ln2_w       = (const float*)d_in[3];
    const float* wq_a        = (const float*)d_in[4];
    const float* q_norm_w    = (const float*)d_in[5];
    const float* wq_b        = (const float*)d_in[6];
    const float* comp_wkv    = (const float*)d_in[7];
    const float* comp_wgate  = (const float*)d_in[8];
    const float* comp_ape    = (const float*)d_in[9];
    const float* comp_norm_w = (const float*)d_in[10];
    const float* idx_wq_b    = (const float*)d_in[11];
    const float* idx_wproj   = (const float*)d_in[12];
    const float* icomp_wkv   = (const float*)d_in[13];
    const float* icomp_wgate = (const float*)d_in[14];
    const float* icomp_ape   = (const float*)d_in[15];
    const float* icomp_norm_w= (const float*)d_in[16];
    const float* attn_sink   = (const float*)d_in[17];
    const float* wo_a        = (const float*)d_in[18];
    const float* wo_b        = (const float*)d_in[19];
    const float* gate_up_w   = (const float*)d_in[20];
    const float* down_w      = (const float*)d_in[21];
    float* out = (float*)d_out;

    float *px,*pqr,*pq,*pqi,*pwcat,*pcat,*pkvF,*pkvc,*pikF,*pki,*pkiT,*pwoaT,*piw,*pisc;
    float *po,*poa,*php,*ph,*px2,*pgu2,*pact,*pRC,*pRS;
    int *pselidx,*pselcnt;
    cudaGetSymbolAddress((void**)&px, g_x);       cudaGetSymbolAddress((void**)&pqr, g_qr);
    cudaGetSymbolAddress((void**)&pq, g_q);       cudaGetSymbolAddress((void**)&pqi, g_qi);
    cudaGetSymbolAddress((void**)&pwcat, g_wcat); cudaGetSymbolAddress((void**)&pcat, g_cat);
    cudaGetSymbolAddress((void**)&pkvF, g_kvF);   cudaGetSymbolAddress((void**)&pkvc, g_kvc);
    cudaGetSymbolAddress((void**)&pikF, g_ikF);   cudaGetSymbolAddress((void**)&pki, g_ki);
    cudaGetSymbolAddress((void**)&pkiT, g_kiT);   cudaGetSymbolAddress((void**)&pwoaT, g_woaT);
    cudaGetSymbolAddress((void**)&piw, g_iw);     cudaGetSymbolAddress((void**)&pisc, g_isc);
    cudaGetSymbolAddress((void**)&pselidx, g_selidx); cudaGetSymbolAddress((void**)&pselcnt, g_selcnt);
    cudaGetSymbolAddress((void**)&po, g_o);       cudaGetSymbolAddress((void**)&poa, g_oa);
    cudaGetSymbolAddress((void**)&php, g_hp);     cudaGetSymbolAddress((void**)&ph, g_h);
    cudaGetSymbolAddress((void**)&px2, g_x2);     cudaGetSymbolAddress((void**)&pgu2, g_gu2);
    cudaGetSymbolAddress((void**)&pact, g_act);
    cudaGetSymbolAddress((void**)&pRC, g_ropeC);  cudaGetSymbolAddress((void**)&pRS, g_ropeS);

    cudaFuncSetAttribute(tgemm_kernel<EP_NONE>,  cudaFuncAttributeMaxDynamicSharedMemorySize, SMEM_PIPE_BYTES);
    cudaFuncSetAttribute(tgemm_kernel<EP_ADD>,   cudaFuncAttributeMaxDynamicSharedMemorySize, SMEM_PIPE_BYTES);
    cudaFuncSetAttribute(tgemm_kernel<EP_RFUSE>, cudaFuncAttributeMaxDynamicSharedMemorySize, SMEM_PIPE_BYTES);

    // 0) rope table + weight concat
    rope_table_kernel<<<(T_ * 32 + 255) / 256, 256>>>(pRC, pRS);
    concat_kernel<<<DIM_, 256>>>(comp_wkv, comp_wgate, icomp_wkv, icomp_wgate, idx_wproj, pwcat);

    // 1) x = rms(hidden, ln1)
    rms_kernel<<<T_, 256>>>(hidden, ln1_w, px, DIM_);

    // 2) qr = rms(x @ wq_a, q_norm)
    tgemm_kernel<EP_NONE><<<ggrid(T_, QL_), 256, SMEM_PIPE_BYTES>>>(T_, QL_, DIM_, px, DIM_, 0, wq_a, QL_, 0, nullptr, pqr, QL_, 0);
    rms_kernel<<<T_, 256>>>(pqr, q_norm_w, pqr, QL_);

    // 3) q / qi projections + rope
    tgemm_kernel<EP_NONE><<<ggrid(T_, H_*DH_), 256, SMEM_PIPE_BYTES>>>(T_, H_*DH_, QL_, pqr, QL_, 0, wq_b, H_*DH_, 0, nullptr, pq, H_*DH_, 0);
    tgemm_kernel<EP_NONE><<<ggrid(T_, HI_*DI_), 256, SMEM_PIPE_BYTES>>>(T_, HI_*DI_, QL_, pqr, QL_, 0, idx_wq_b, HI_*DI_, 0, nullptr, pqi, HI_*DI_, 0);
    rope_apply_kernel<<<T_ * H_ / 8,  256>>>(pq,  positions, pRC, pRS, H_,  DH_, NOPE_,  0, T_ * H_);
    rope_apply_kernel<<<T_ * HI_ / 8, 256>>>(pqi, positions, pRC, pRS, HI_, DI_, INOPE_, 0, T_ * HI_);

    // 4) Fused projection GEMM, split-K=2 (z over K halves), then gate/split summing partials
    {
        dim3 g = ggrid(T_, NCAT_); g.z = 2;
        tgemm_kernel<EP_NONE><<<g, 256, SMEM_PIPE_BYTES>>>(
            T_, NCAT_, DIM_/2, px, DIM_, DIM_/2, pwcat, NCAT_, (DIM_/2)*NCAT_,
            nullptr, pcat, NCAT_, T_*NCAT_);
    }
    fusedgate_kernel<<<T_, 256>>>(pcat, comp_ape, icomp_ape, pkvF, pikF, piw);

    // 5) compress + rope (kvc, ki) + ki transpose
    compress_kernel<<<SC_, DH_>>>(pkvF, comp_norm_w, pkvc, DH_);
    rope_apply_kernel<<<SC_ / 8, 256>>>(pkvc, positions, pRC, pRS, 1, DH_, NOPE_, 1, SC_);
    compress_kernel<<<SC_, DI_>>>(pikF, icomp_norm_w, pki, DI_);
    rope_apply_kernel<<<SC_ / 8, 256>>>(pki, positions, pRC, pRS, 1, DI_, INOPE_, 1, SC_);
    transpose_kernel<<<dim3(DI_/32, SC_/32, 1), dim3(32, 8)>>>(pki, pkiT, SC_, DI_);

    // 6) R GEMM with fused weighted-relu head reduction -> isc
    tgemm_kernel<EP_RFUSE><<<ggrid(T_*HI_, SC_), 256, SMEM_PIPE_BYTES>>>(T_*HI_, SC_, DI_, pqi, DI_, 0, pkiT, SC_, 0, piw, pisc, SC_, 0);

    // 7) top-256 + attention
    topk_kernel<<<T_, 256>>>(pisc, pselidx, pselcnt);
    attn2_kernel<<<T_, 512>>>(pq, pkvc, pselidx, pselcnt, attn_sink, po);

    // 8) output proj: transpose wo_a, z-batched wo_a GEMM, split-K=2 wo_b + combine(+residual)
    transpose_kernel<<<dim3(FG_/32, OLORA_/32, G_), dim3(32, 8)>>>(wo_a, pwoaT, OLORA_, FG_);
    {
        dim3 g = ggrid(T_, OLORA_); g.z = G_;
        tgemm_kernel<EP_NONE><<<g, 256, SMEM_PIPE_BYTES>>>(
            T_, OLORA_, FG_, po, H_*DH_, FG_, pwoaT, OLORA_, FG_*OLORA_,
            nullptr, poa, G_*OLORA_, OLORA_);
    }
    {
        dim3 g = ggrid(T_, DIM_); g.z = 2;
        tgemm_kernel<EP_NONE><<<g, 256, SMEM_PIPE_BYTES>>>(
            T_, DIM_, (G_*OLORA_)/2, poa, G_*OLORA_, (G_*OLORA_)/2,
            wo_b, DIM_, ((G_*OLORA_)/2)*DIM_,
            nullptr, php, DIM_, T_*DIM_);
    }
    combine2_kernel<<<(T_*DIM_ + 255)/256, 256>>>(php, hidden, ph, (size_t)T_*DIM_);

    // 9) MLP: z=2 {gate,up} GEMM, silu-mul, split-K=2 down + combine(+residual) -> out
    rms_kernel<<<T_, 256>>>(ph, ln2_w, px2, DIM_);
    {
        dim3 g = ggrid(T_, II_); g.z = 2;
        tgemm_kernel<EP_NONE><<<g, 256, SMEM_PIPE_BYTES>>>(
            T_, II_, DIM_, px2, DIM_, 0, gate_up_w, 2*II_, II_,
            nullptr, pgu2, II_, T_ * II_);
    }
    silu2_kernel<<<(int)(((size_t)T_ * II_ + 255) / 256), 256>>>(pgu2, pact);
    {
        dim3 g = ggrid(T_, DIM_); g.z = 2;
        tgemm_kernel<EP_NONE><<<g, 256, SMEM_PIPE_BYTES>>>(
            T_, DIM_, II_/2, pact, II_, II_/2, down_w, DIM_, (II_/2)*DIM_,
            nullptr, php, DIM_, T_*DIM_);
    }
    combine2_kernel<<<(T_*DIM_ + 255)/256, 256>>>(php, ph, out, (size_t)T_*DIM_);
}

// round 17
// speedup vs baseline: 2.4278x; 1.4889x over previous
#include <cuda_runtime.h>
#include <cuda_fp16.h>
#include <math.h>
#include <stdint.h>

#define T_    2048
#define DIM_  2048
#define QL_   1536
#define H_    16
#define DH_   256
#define NOPE_ 192
#define HI_   32
#define DI_   128
#define INOPE_ 64
#define SC_   512
#define TOPK_ 256
#define II_   8192
#define G_    4
#define OLORA_ 512
#define FG_   1024
#define NCAT_ 1568
#define EPSF  1e-6f
#define NEGF  (-1e30f)
#define SCALE_   0.0625f
#define ISCALE_  0.08838834764831845f
#define LOG_THETA 11.98292909421596506

// ---------------- fp32 scratch ----------------
__device__ float g_qr  [T_ * QL_];
__device__ float g_q   [T_ * H_ * DH_];
__device__ float g_qi  [T_ * HI_ * DI_];
__device__ float g_cat [2 * T_ * NCAT_];
__device__ float g_kvF [T_ * 2 * DH_];
__device__ float g_kvc [SC_ * DH_];
__device__ float g_ikF [T_ * 2 * DI_];
__device__ float g_ki  [SC_ * DI_];
__device__ float g_iw  [T_ * HI_];
__device__ float g_isc [T_ * SC_];
__device__ int   g_selidx[T_ * TOPK_];
__device__ int   g_selcnt[T_];
__device__ float g_oa  [T_ * G_ * OLORA_];
__device__ float g_hp  [2 * T_ * DIM_];
__device__ float g_h   [T_ * DIM_];
__device__ float g_gu2 [(size_t)2 * T_ * II_];
__device__ float g_ropeC[T_ * 32];
__device__ float g_ropeS[T_ * 32];
// ---------------- fp16 operands ----------------
__device__ __half h_wqaT [QL_ * DIM_];
__device__ __half h_wqbT [(H_*DH_) * QL_];
__device__ __half h_idxbT[(HI_*DI_) * QL_];
__device__ __half h_wcatT[NCAT_ * DIM_];
__device__ __half h_wobT [DIM_ * (G_*OLORA_)];
__device__ __half h_guT  [(size_t)(2*II_) * DIM_];
__device__ __half h_dwT  [(size_t)DIM_ * II_];
__device__ __half h_woa  [G_ * OLORA_ * FG_];
__device__ __half h_x    [T_ * DIM_];
__device__ __half h_qr   [T_ * QL_];
__device__ __half h_qi   [T_ * HI_ * DI_];
__device__ __half h_ki   [SC_ * DI_];
__device__ __half h_o    [T_ * H_ * DH_];
__device__ __half h_oa   [T_ * G_ * OLORA_];
__device__ __half h_x2   [T_ * DIM_];
__device__ __half h_act  [(size_t)T_ * II_];

// ---------------- reductions ----------------
__device__ __forceinline__ float blockReduceSum(float v) {
    __shared__ float sh[32];
    int lane = threadIdx.x & 31, wid = threadIdx.x >> 5;
    #pragma unroll
    for (int o = 16; o > 0; o >>= 1) v += __shfl_xor_sync(0xffffffffu, v, o);
    if (lane == 0) sh[wid] = v;
    __syncthreads();
    int nw = (blockDim.x + 31) >> 5;
    if (wid == 0) {
        float r = (lane < nw) ? sh[lane] : 0.0f;
        #pragma unroll
        for (int o = 16; o > 0; o >>= 1) r += __shfl_xor_sync(0xffffffffu, r, o);
        if (lane == 0) sh[0] = r;
    }
    __syncthreads();
    float res = sh[0];
    __syncthreads();
    return res;
}

// ---------------- helpers ----------------
__device__ __forceinline__ void mma_f16(float* d, const uint32_t* a, const uint32_t* b) {
    asm volatile(
        "mma.sync.aligned.m16n8k16.row.col.f32.f16.f16.f32 "
        "{%0,%1,%2,%3}, {%4,%5,%6,%7}, {%8,%9}, {%0,%1,%2,%3};"
        : "+f"(d[0]), "+f"(d[1]), "+f"(d[2]), "+f"(d[3])
        : "r"(a[0]), "r"(a[1]), "r"(a[2]), "r"(a[3]), "r"(b[0]), "r"(b[1]));
}

__device__ __forceinline__ void cp16(void* smem_dst, const void* gsrc, bool pred) {
    uint32_t s = (uint32_t)__cvta_generic_to_shared(smem_dst);
    int sz = pred ? 16 : 0;
    asm volatile("cp.async.cg.shared.global [%0], [%1], 16, %2;\n"
                 :: "r"(s), "l"(gsrc), "r"(sz));
}
#define CP_COMMIT() asm volatile("cp.async.commit_group;" ::: "memory")
#define CP_WAIT1()  asm volatile("cp.async.wait_group 1;" ::: "memory")
#define CP_WAIT0()  asm volatile("cp.async.wait_group 0;" ::: "memory")

#define EP_NONE  0
#define EP_RFUSE 4

// ---------------- fp16 tensor-core GEMM, 128x128x32(half), 3-stage ----------------
// A [M][K] half row-major; BT [N][K] half row-major (B col-major). Acc fp32.
#define RS_H 40                       // padded row stride in halves (20 words)
#define TILE_H (128 * RS_H)           // 5120 halves per operand tile
#define STAGE_H (2 * TILE_H)          // 10240 halves
#define SMEM_H_BYTES (3 * STAGE_H * 2)   // 61440

template<int EP>
__global__ void __launch_bounds__(256, 2) hgemm_kernel(
    int M, int N, int K,
    const __half* __restrict__ A, int lda, int aZ,
    const __half* __restrict__ BT, int ldb, int bZ,
    const float* __restrict__ Cadd,
    float* __restrict__ C, int ldc, int cZ)
{
    extern __shared__ __half smh[];
    const int bm = blockIdx.y * 128;
    const int bn = blockIdx.x * 128;
    A  += (size_t)blockIdx.z * aZ;
    BT += (size_t)blockIdx.z * bZ;
    C  += (size_t)blockIdx.z * cZ;
    const int tid = threadIdx.x;
    const int lane = tid & 31;
    const int wid = tid >> 5;
    const int wm = wid & 3;
    const int wn = wid >> 2;
    const int gid = lane >> 2;
    const int tig = lane & 3;

    float acc[2][8][4];
    #pragma unroll
    for (int mi = 0; mi < 2; mi++)
        #pragma unroll
        for (int ni = 0; ni < 8; ni++)
            #pragma unroll
            for (int r = 0; r < 4; r++) acc[mi][ni][r] = 0.0f;

    const int nIter = K / 32;

    auto issue = [&](int st, int k0) {
        __half* sA = smh + st * STAGE_H;
        __half* sB = sA + TILE_H;
        #pragma unroll
        for (int i = 0; i < 2; i++) {
            int f = tid + i * 256;
            int r = f >> 2, q = f & 3;
            cp16(&sA[r * RS_H + 8 * q], A + (size_t)(bm + r) * lda + k0 + 8 * q, bm + r < M);
        }
        #pragma unroll
        for (int i = 0; i < 2; i++) {
            int f = tid + i * 256;
            int r = f >> 2, q = f & 3;
            cp16(&sB[r * RS_H + 8 * q], BT + (size_t)(bn + r) * ldb + k0 + 8 * q, bn + r < N);
        }
    };

    auto load_frags = [&](const __half* sA, const __half* sB, int kb,
                          uint32_t af[2][4], uint32_t bf[8][2]) {
        const uint32_t* wA = (const uint32_t*)sA;
        const uint32_t* wB = (const uint32_t*)sB;
        int kw = (kb >> 1) + tig;
        #pragma unroll
        for (int mi = 0; mi < 2; mi++) {
            int r = wm * 32 + mi * 16 + gid;
            af[mi][0] = wA[r * 20 + kw];
            af[mi][1] = wA[(r + 8) * 20 + kw];
            af[mi][2] = wA[r * 20 + kw + 4];
            af[mi][3] = wA[(r + 8) * 20 + kw + 4];
        }
        #pragma unroll
        for (int ni = 0; ni < 8; ni++) {
            int c = wn * 64 + ni * 8 + gid;
            bf[ni][0] = wB[c * 20 + kw];
            bf[ni][1] = wB[c * 20 + kw + 4];
        }
    };

    auto frag_compute = [&](int st) {
        const __half* sA = smh + st * STAGE_H;
        const __half* sB = sA + TILE_H;
        uint32_t af[2][2][4];
        uint32_t bf[2][8][2];
        load_frags(sA, sB, 0, af[0], bf[0]);
        #pragma unroll
        for (int kk = 0; kk < 2; kk++) {
            if (kk < 1)
                load_frags(sA, sB, 16, af[1], bf[1]);
            #pragma unroll
            for (int mi = 0; mi < 2; mi++)
                #pragma unroll
                for (int ni = 0; ni < 8; ni++)
                    mma_f16(acc[mi][ni], af[kk][mi], bf[kk][ni]);
        }
    };

    issue(0, 0);
    CP_COMMIT();
    if (nIter > 1) { issue(1, 32); CP_COMMIT(); }

    int st = 0;
    for (int it = 0; it < nIter; ++it) {
        if (it + 1 < nIter) CP_WAIT1(); else CP_WAIT0();
        __syncthreads();
        if (it + 2 < nIter) {
            int st2 = st + 2; if (st2 >= 3) st2 -= 3;
            issue(st2, (it + 2) * 32);
            CP_COMMIT();
        }
        frag_compute(st);
        if (++st == 3) st = 0;
    }

    if (EP == EP_RFUSE) {
        int t = bm / HI_ + wm;
        float wA = Cadd[t * HI_ + gid];
        float wB = Cadd[t * HI_ + gid + 8];
        float wC = Cadd[t * HI_ + gid + 16];
        float wD = Cadd[t * HI_ + gid + 24];
        #pragma unroll
        for (int ni = 0; ni < 8; ni++) {
            float p0 = wA * fmaxf(acc[0][ni][0], 0.f) + wB * fmaxf(acc[0][ni][2], 0.f)
                     + wC * fmaxf(acc[1][ni][0], 0.f) + wD * fmaxf(acc[1][ni][2], 0.f);
            float p1 = wA * fmaxf(acc[0][ni][1], 0.f) + wB * fmaxf(acc[0][ni][3], 0.f)
                     + wC * fmaxf(acc[1][ni][1], 0.f) + wD * fmaxf(acc[1][ni][3], 0.f);
            #pragma unroll
            for (int off = 4; off < 32; off <<= 1) {
                p0 += __shfl_xor_sync(0xffffffffu, p0, off);
                p1 += __shfl_xor_sync(0xffffffffu, p1, off);
            }
            if (gid == 0) {
                int c = bn + wn * 64 + ni * 8 + tig * 2;
                C[(size_t)t * ldc + c]     = p0 * ISCALE_;
                C[(size_t)t * ldc + c + 1] = p1 * ISCALE_;
            }
        }
        return;
    }

    #pragma unroll
    for (int mi = 0; mi < 2; mi++) {
        int r0 = bm + wm * 32 + mi * 16 + gid;
        int r1 = r0 + 8;
        #pragma unroll
        for (int ni = 0; ni < 8; ni++) {
            int c = bn + wn * 64 + ni * 8 + tig * 2;
            float* ap = acc[mi][ni];
            if (c < N) {
                if (r0 < M) *(float2*)(C + (size_t)r0 * ldc + c) = make_float2(ap[0], ap[1]);
                if (r1 < M) *(float2*)(C + (size_t)r1 * ldc + c) = make_float2(ap[2], ap[3]);
            }
        }
    }
}

// ---------------- transpose + cvt: in fp32 [R][C] -> out half [C][R] ----------------
__global__ void transpose_cvt_kernel(const float* __restrict__ in, __half* __restrict__ out,
                                     int R, int C)
{
    __shared__ float tile[32][33];
    int bx = blockIdx.x * 32, by = blockIdx.y * 32;
    int x = bx + threadIdx.x;
    #pragma unroll
    for (int i = 0; i < 4; i++) {
        int y = by + threadIdx.y + 8 * i;
        if (y < R && x < C) tile[threadIdx.y + 8 * i][threadIdx.x] = in[(size_t)y * C + x];
    }
    __syncthreads();
    int x2 = by + threadIdx.x;
    #pragma unroll
    for (int i = 0; i < 4; i++) {
        int y2 = bx + threadIdx.y + 8 * i;
        if (y2 < C && x2 < R) out[(size_t)y2 * R + x2] = __float2half(tile[threadIdx.x][threadIdx.y + 8 * i]);
    }
}

__global__ void cvt1d_kernel(const float* __restrict__ in, __half* __restrict__ out, size_t n)
{
    size_t i = (size_t)blockIdx.x * blockDim.x + threadIdx.x;
    if (i < n) out[i] = __float2half(in[i]);
}

__global__ void combine2_kernel(const float* __restrict__ parts, const float* __restrict__ res,
                                float* __restrict__ out, size_t n)
{
    size_t i = (size_t)blockIdx.x * blockDim.x + threadIdx.x;
    if (i >= n) return;
    float v = parts[i] + parts[n + i];
    if (res) v += res[i];
    out[i] = v;
}

// ---------------- gate/split of split-K concat GEMM output ----------------
__global__ void fusedgate_kernel(const float* __restrict__ cat,
                                 const float* __restrict__ ape_kv, const float* __restrict__ ape_ik,
                                 float* __restrict__ kvF, float* __restrict__ ikF,
                                 float* __restrict__ iw)
{
    int t = blockIdx.x;
    const float* r0 = cat + (size_t)t * NCAT_;
    const float* r1 = r0 + (size_t)T_ * NCAT_;
    int a = t & 3;
    for (int e = threadIdx.x; e < 512; e += 256) {
        float kv = r0[e] + r1[e];
        float gt = r0[512 + e] + r1[512 + e];
        kvF[t * 512 + e] = kv / (1.0f + expf(-gt)) + ape_kv[a * 512 + e];
    }
    for (int e = threadIdx.x; e < 256; e += 256) {
        float kv = r0[1024 + e] + r1[1024 + e];
        float gt = r0[1280 + e] + r1[1280 + e];
        ikF[t * 256 + e] = kv / (1.0f + expf(-gt)) + ape_ik[a * 256 + e];
    }
    if (threadIdx.x < 32)
        iw[t * 32 + threadIdx.x] = r0[1536 + threadIdx.x] + r1[1536 + threadIdx.x];
}

__global__ void silu2_kernel(const float* __restrict__ gu2, __half* __restrict__ act)
{
    size_t i = (size_t)blockIdx.x * blockDim.x + threadIdx.x;
    if (i >= (size_t)T_ * II_) return;
    float g = gu2[i];
    float u = gu2[(size_t)T_ * II_ + i];
    act[i] = __float2half(g / (1.0f + expf(-g)) * u);
}

// ---------------- rmsnorm (optionally half output) ----------------
template<bool HO>
__global__ void rms_kernel(const float* __restrict__ in, const float* __restrict__ w,
                           float* __restrict__ outf, __half* __restrict__ outh, int D)
{
    int t = blockIdx.x;
    const float* row = in + (size_t)t * D;
    float s = 0.0f;
    for (int d = threadIdx.x; d < D; d += blockDim.x) { float v = row[d]; s += v * v; }
    s = blockReduceSum(s);
    float inv = rsqrtf(s / (float)D + EPSF);
    for (int d = threadIdx.x; d < D; d += blockDim.x) {
        float v = row[d] * inv * w[d];
        if (HO) outh[(size_t)t * D + d] = __float2half(v);
        else    outf[(size_t)t * D + d] = v;
    }
}

__global__ void compress_kernel(const float* __restrict__ kvf, const float* __restrict__ w,
                                float* __restrict__ out, int d)
{
    int b = blockIdx.x;
    int e = threadIdx.x;
    int W = 2 * d;
    float m = 0.0f;
    if (b > 0) {
        #pragma unroll
        for (int r = 0; r < 4; r++) m += kvf[(size_t)((b - 1) * 4 + r) * W + e];
    }
    #pragma unroll
    for (int r = 0; r < 4; r++) m += kvf[(size_t)(b * 4 + r) * W + d + e];
    m *= 0.125f;
    float ssq = blockReduceSum(m * m);
    float inv = rsqrtf(ssq / (float)d + EPSF);
    out[(size_t)b * d + e] = m * inv * w[e];
}

__global__ void rope_table_kernel(float* __restrict__ tc, float* __restrict__ ts)
{
    int i = blockIdx.x * blockDim.x + threadIdx.x;
    if (i >= T_ * 32) return;
    int pos = i >> 5, f = i & 31;
    double freq = exp(-((double)(2 * f) / 64.0) * LOG_THETA);
    double ang = (double)pos * freq;
    tc[i] = (float)cos(ang);
    ts[i] = (float)sin(ang);
}

__global__ void rope_apply_kernel(float* __restrict__ x, const int* __restrict__ positions,
                                  const float* __restrict__ tc, const float* __restrict__ ts,
                                  int Hh, int Dd, int ropeOff, int compPos, int nRows)
{
    int row = blockIdx.x * 8 + (threadIdx.x >> 5);
    if (row >= nRows) return;
    int lane = threadIdx.x & 31;
    int t = row / Hh;
    int pos = compPos ? (4 * (t + 1) - 1) : positions[t];
    float c = tc[pos * 32 + lane], s = ts[pos * 32 + lane];
    float* p = x + (size_t)row * Dd + ropeOff;
    float x0 = p[2 * lane], x1 = p[2 * lane + 1];
    p[2 * lane]     = x0 * c - x1 * s;
    p[2 * lane + 1] = x0 * s + x1 * c;
}

__global__ void topk_kernel(const float* __restrict__ isc, int* __restrict__ selidx,
                            int* __restrict__ selcnt)
{
    int t = blockIdx.x;
    __shared__ float sv[SC_];
    __shared__ int   si[SC_];
    int tid = threadIdx.x;
    int visCount = (t >= 3) ? ((t - 3) / 4 + 1) : 0;
    for (int i = tid; i < SC_; i += 256) {
        sv[i] = (i < visCount) ? isc[t * SC_ + i] : NEGF;
        si[i] = i;
    }
    __syncthreads();
    for (int k = 2; k <= SC_; k <<= 1) {
        for (int j = k >> 1; j > 0; j >>= 1) {
            for (int base = tid; base < SC_; base += 256) {
                int partner = base ^ j;
                if (partner > base) {
                    bool up = ((base & k) == 0);
                    float va = sv[base], vb = sv[partner];
                    int ia = si[base], ib = si[partner];
                    bool aFirst = (va > vb) || (va == vb && ia < ib);
                    if (up ? !aFirst : aFirst) {
                        sv[base] = vb; sv[partner] = va;
                        si[base] = ib; si[partner] = ia;
                    }
                }
            }
            __syncthreads();
        }
    }
    int cnt = min(visCount, TOPK_);
    if (tid == 0) selcnt[t] = cnt;
    for (int r = tid; r < cnt; r += 256) selidx[t * TOPK_ + r] = si[r];
}

__global__ void __launch_bounds__(512) attn2_kernel(
    const float* __restrict__ q, const float* __restrict__ kvc,
    const int* __restrict__ selidx, const int* __restrict__ selcnt,
    const float* __restrict__ sink, __half* __restrict__ o)
{
    __shared__ float kt[32][DH_];
    __shared__ int   ss[TOPK_];
    int t = blockIdx.x;
    int tid = threadIdx.x, lane = tid & 31, w = tid >> 5;
    int cnt = selcnt[t];
    for (int i = tid; i < cnt; i += 512) ss[i] = selidx[t * TOPK_ + i];
    __syncthreads();

    float q8[8];
    const float* qp = q + ((size_t)t * H_ + w) * DH_;
    #pragma unroll
    for (int i = 0; i < 8; i++) q8[i] = qp[lane + 32 * i];

    float m = NEGF, se = 0.0f;
    float acc[8] = {};

    for (int j0 = 0; j0 < cnt; j0 += 32) {
        int rem = min(32, cnt - j0);
        __syncthreads();
        for (int f = tid; f < 32 * 64; f += 512) {
            int r = f >> 6, c4 = f & 63;
            float4 v = make_float4(0.f, 0.f, 0.f, 0.f);
            if (r < rem) v = *(const float4*)(kvc + (size_t)ss[j0 + r] * DH_ + 4 * c4);
            *(float4*)&kt[r][4 * c4] = v;
        }
        __syncthreads();
        for (int j = 0; j < rem; j++) {
            float dot = 0.0f;
            #pragma unroll
            for (int i = 0; i < 8; i++) dot += q8[i] * kt[j][lane + 32 * i];
            #pragma unroll
            for (int off = 16; off > 0; off >>= 1)
                dot += __shfl_xor_sync(0xffffffffu, dot, off);
            float lg = dot * SCALE_;
            float mn = fmaxf(m, lg);
            float sc = expf(m - mn);
            float p  = expf(lg - mn);
            se = se * sc + p;
            #pragma unroll
            for (int i = 0; i < 8; i++)
                acc[i] = acc[i] * sc + p * kt[j][lane + 32 * i];
            m = mn;
        }
    }

    float snk = sink[w];
    float mn = fmaxf(m, snk);
    float sc = expf(m - mn);
    se = se * sc + expf(snk - mn);
    float inv = 1.0f / se;
    __half* op = o + ((size_t)t * H_ + w) * DH_;
    #pragma unroll
    for (int i = 0; i < 8; i++) op[lane + 32 * i] = __float2half(acc[i] * sc * inv);
}

// ---------------- host ----------------
static inline dim3 ggrid(int M, int N) { return dim3((N + 127) / 128, (M + 127) / 128); }
static inline dim3 tgrid(int R, int C) { return dim3((C + 31) / 32, (R + 31) / 32); }

extern "C" void kernel_launch(void* const* d_in, const int* in_sizes, int n_in,
                              void* d_out, int out_size)
{
    const float* hidden      = (const float*)d_in[0];
    const int*   positions   = (const int*)  d_in[1];
    const float* ln1_w       = (const float*)d_in[2];
    const float* ln2_w       = (const float*)d_in[3];
    const float* wq_a        = (const float*)d_in[4];
    const float* q_norm_w    = (const float*)d_in[5];
    const float* wq_b        = (const float*)d_in[6];
    const float* comp_wkv    = (const float*)d_in[7];
    const float* comp_wgate  = (const float*)d_in[8];
    const float* comp_ape    = (const float*)d_in[9];
    const float* comp_norm_w = (const float*)d_in[10];
    const float* idx_wq_b    = (const float*)d_in[11];
    const float* idx_wproj   = (const float*)d_in[12];
    const float* icomp_wkv   = (const float*)d_in[13];
    const float* icomp_wgate = (const float*)d_in[14];
    const float* icomp_ape   = (const float*)d_in[15];
    const float* icomp_norm_w= (const float*)d_in[16];
    const float* attn_sink   = (const float*)d_in[17];
    const float* wo_a        = (const float*)d_in[18];
    const float* wo_b        = (const float*)d_in[19];
    const float* gate_up_w   = (const float*)d_in[20];
    const float* down_w      = (const float*)d_in[21];
    float* out = (float*)d_out;

    float *pqr,*pq,*pqi,*pcat,*pkvF,*pkvc,*pikF,*pki,*piw,*pisc,*poa,*php,*ph,*pgu2,*pRC,*pRS;
    int *pselidx,*pselcnt;
    __half *hwqaT,*hwqbT,*hidxbT,*hwcatT,*hwobT,*hguT,*hdwT,*hwoa;
    __half *hx,*hqr,*hqi,*hki,*ho,*hoa,*hx2,*hact;
    cudaGetSymbolAddress((void**)&pqr, g_qr);     cudaGetSymbolAddress((void**)&pq, g_q);
    cudaGetSymbolAddress((void**)&pqi, g_qi);     cudaGetSymbolAddress((void**)&pcat, g_cat);
    cudaGetSymbolAddress((void**)&pkvF, g_kvF);   cudaGetSymbolAddress((void**)&pkvc, g_kvc);
    cudaGetSymbolAddress((void**)&pikF, g_ikF);   cudaGetSymbolAddress((void**)&pki, g_ki);
    cudaGetSymbolAddress((void**)&piw, g_iw);     cudaGetSymbolAddress((void**)&pisc, g_isc);
    cudaGetSymbolAddress((void**)&pselidx, g_selidx); cudaGetSymbolAddress((void**)&pselcnt, g_selcnt);
    cudaGetSymbolAddress((void**)&poa, g_oa);     cudaGetSymbolAddress((void**)&php, g_hp);
    cudaGetSymbolAddress((void**)&ph, g_h);       cudaGetSymbolAddress((void**)&pgu2, g_gu2);
    cudaGetSymbolAddress((void**)&pRC, g_ropeC);  cudaGetSymbolAddress((void**)&pRS, g_ropeS);
    cudaGetSymbolAddress((void**)&hwqaT, h_wqaT); cudaGetSymbolAddress((void**)&hwqbT, h_wqbT);
    cudaGetSymbolAddress((void**)&hidxbT, h_idxbT); cudaGetSymbolAddress((void**)&hwcatT, h_wcatT);
    cudaGetSymbolAddress((void**)&hwobT, h_wobT); cudaGetSymbolAddress((void**)&hguT, h_guT);
    cudaGetSymbolAddress((void**)&hdwT, h_dwT);   cudaGetSymbolAddress((void**)&hwoa, h_woa);
    cudaGetSymbolAddress((void**)&hx, h_x);       cudaGetSymbolAddress((void**)&hqr, h_qr);
    cudaGetSymbolAddress((void**)&hqi, h_qi);     cudaGetSymbolAddress((void**)&hki, h_ki);
    cudaGetSymbolAddress((void**)&ho, h_o);       cudaGetSymbolAddress((void**)&hoa, h_oa);
    cudaGetSymbolAddress((void**)&hx2, h_x2);     cudaGetSymbolAddress((void**)&hact, h_act);

    cudaFuncSetAttribute(hgemm_kernel<EP_NONE>,  cudaFuncAttributeMaxDynamicSharedMemorySize, SMEM_H_BYTES);
    cudaFuncSetAttribute(hgemm_kernel<EP_RFUSE>, cudaFuncAttributeMaxDynamicSharedMemorySize, SMEM_H_BYTES);

    dim3 tb(32, 8);
    // 0) weight preps (transpose+cvt to [N][K] fp16), rope table
    transpose_cvt_kernel<<<tgrid(DIM_, QL_), tb>>>(wq_a, hwqaT, DIM_, QL_);
    transpose_cvt_kernel<<<tgrid(QL_, H_*DH_), tb>>>(wq_b, hwqbT, QL_, H_*DH_);
    transpose_cvt_kernel<<<tgrid(QL_, HI_*DI_), tb>>>(idx_wq_b, hidxbT, QL_, HI_*DI_);
    transpose_cvt_kernel<<<tgrid(DIM_, 512), tb>>>(comp_wkv,   hwcatT,                 DIM_, 512);
    transpose_cvt_kernel<<<tgrid(DIM_, 512), tb>>>(comp_wgate, hwcatT + 512*DIM_,      DIM_, 512);
    transpose_cvt_kernel<<<tgrid(DIM_, 256), tb>>>(icomp_wkv,  hwcatT + 1024*DIM_,     DIM_, 256);
    transpose_cvt_kernel<<<tgrid(DIM_, 256), tb>>>(icomp_wgate,hwcatT + 1280*DIM_,     DIM_, 256);
    transpose_cvt_kernel<<<tgrid(DIM_, 32), tb>>>(idx_wproj,   hwcatT + 1536*DIM_,     DIM_, 32);
    transpose_cvt_kernel<<<tgrid(G_*OLORA_, DIM_), tb>>>(wo_b, hwobT, G_*OLORA_, DIM_);
    transpose_cvt_kernel<<<tgrid(DIM_, 2*II_), tb>>>(gate_up_w, hguT, DIM_, 2*II_);
    transpose_cvt_kernel<<<tgrid(II_, DIM_), tb>>>(down_w, hdwT, II_, DIM_);
    cvt1d_kernel<<<(G_*OLORA_*FG_ + 255)/256, 256>>>(wo_a, hwoa, (size_t)G_*OLORA_*FG_);
    rope_table_kernel<<<(T_*32 + 255)/256, 256>>>(pRC, pRS);

    // 1) x = rms(hidden) -> fp16
    rms_kernel<true><<<T_, 256>>>(hidden, ln1_w, nullptr, hx, DIM_);

    // 2) qr = rms(x @ wq_a) -> fp16
    hgemm_kernel<EP_NONE><<<ggrid(T_, QL_), 256, SMEM_H_BYTES>>>(
        T_, QL_, DIM_, hx, DIM_, 0, hwqaT, DIM_, 0, nullptr, pqr, QL_, 0);
    rms_kernel<true><<<T_, 256>>>(pqr, q_norm_w, nullptr, hqr, QL_);

    // 3) q / qi projections + rope; qi -> fp16
    hgemm_kernel<EP_NONE><<<ggrid(T_, H_*DH_), 256, SMEM_H_BYTES>>>(
        T_, H_*DH_, QL_, hqr, QL_, 0, hwqbT, QL_, 0, nullptr, pq, H_*DH_, 0);
    hgemm_kernel<EP_NONE><<<ggrid(T_, HI_*DI_), 256, SMEM_H_BYTES>>>(
        T_, HI_*DI_, QL_, hqr, QL_, 0, hidxbT, QL_, 0, nullptr, pqi, HI_*DI_, 0);
    rope_apply_kernel<<<T_*H_/8,  256>>>(pq,  positions, pRC, pRS, H_,  DH_, NOPE_,  0, T_*H_);
    rope_apply_kernel<<<T_*HI_/8, 256>>>(pqi, positions, pRC, pRS, HI_, DI_, INOPE_, 0, T_*HI_);
    cvt1d_kernel<<<(T_*HI_*DI_ + 255)/256, 256>>>(pqi, hqi, (size_t)T_*HI_*DI_);

    // 4) fused projection GEMM, split-K=2, then gate/split
    {
        dim3 g = ggrid(T_, NCAT_); g.z = 2;
        hgemm_kernel<EP_NONE><<<g, 256, SMEM_H_BYTES>>>(
            T_, NCAT_, DIM_/2, hx, DIM_, DIM_/2, hwcatT, DIM_, DIM_/2,
            nullptr, pcat, NCAT_, T_*NCAT_);
    }
    fusedgate_kernel<<<T_, 256>>>(pcat, comp_ape, icomp_ape, pkvF, pikF, piw);

    // 5) compress + rope; ki -> fp16
    compress_kernel<<<SC_, DH_>>>(pkvF, comp_norm_w, pkvc, DH_);
    rope_apply_kernel<<<SC_/8, 256>>>(pkvc, positions, pRC, pRS, 1, DH_, NOPE_, 1, SC_);
    compress_kernel<<<SC_, DI_>>>(pikF, icomp_norm_w, pki, DI_);
    rope_apply_kernel<<<SC_/8, 256>>>(pki, positions, pRC, pRS, 1, DI_, INOPE_, 1, SC_);
    cvt1d_kernel<<<(SC_*DI_ + 255)/256, 256>>>(pki, hki, (size_t)SC_*DI_);

    // 6) R GEMM + fused weighted-relu head reduction -> isc (B = ki as [N][K], no transpose)
    hgemm_kernel<EP_RFUSE><<<ggrid(T_*HI_, SC_), 256, SMEM_H_BYTES>>>(
        T_*HI_, SC_, DI_, hqi, DI_, 0, hki, DI_, 0, piw, pisc, SC_, 0);

    // 7) top-256 + attention (o -> fp16)
    topk_kernel<<<T_, 256>>>(pisc, pselidx, pselcnt);
    attn2_kernel<<<T_, 512>>>(pq, pkvc, pselidx, pselcnt, attn_sink, ho);

    // 8) output proj: z-batched wo_a (weights already [N][K]), cvt, split-K wo_b + combine
    {
        dim3 g = ggrid(T_, OLORA_); g.z = G_;
        hgemm_kernel<EP_NONE><<<g, 256, SMEM_H_BYTES>>>(
            T_, OLORA_, FG_, ho, H_*DH_, FG_, hwoa, FG_, OLORA_*FG_,
            nullptr, poa, G_*OLORA_, OLORA_);
    }
    cvt1d_kernel<<<(T_*G_*OLORA_ + 255)/256, 256>>>(poa, hoa, (size_t)T_*G_*OLORA_);
    {
        dim3 g = ggrid(T_, DIM_); g.z = 2;
        hgemm_kernel<EP_NONE><<<g, 256, SMEM_H_BYTES>>>(
            T_, DIM_, (G_*OLORA_)/2, hoa, G_*OLORA_, (G_*OLORA_)/2,
            hwobT, G_*OLORA_, (G_*OLORA_)/2,
            nullptr, php, DIM_, T_*DIM_);
    }
    combine2_kernel<<<(T_*DIM_ + 255)/256, 256>>>(php, hidden, ph, (size_t)T_*DIM_);

    // 9) MLP: rms -> fp16; z=2 {gate,up}; silu -> fp16; split-K down + combine -> out
    rms_kernel<true><<<T_, 256>>>(ph, ln2_w, nullptr, hx2, DIM_);
    {
        dim3 g = ggrid(T_, II_); g.z = 2;
        hgemm_kernel<EP_NONE><<<g, 256, SMEM_H_BYTES>>>(
            T_, II_, DIM_, hx2, DIM_, 0, hguT, DIM_, II_*DIM_,
            nullptr, pgu2, II_, T_ * II_);
    }
    silu2_kernel<<<(int)(((size_t)T_*II_ + 255)/256), 256>>>(pgu2, hact);
    {
        dim3 g = ggrid(T_, DIM_); g.z = 2;
        hgemm_kernel<EP_NONE><<<g, 256, SMEM_H_BYTES>>>(
            T_, DIM_, II_/2, hact, II_, II_/2, hdwT, II_, II_/2,
            nullptr, php, DIM_, T_*DIM_);
    }
    combine2_kernel<<<(T_*DIM_ + 255)/256, 256>>>(php, ph, out, (size_t)T_*DIM_);
}